// round 2
// baseline (speedup 1.0000x reference)
#include <cuda_runtime.h>
#include <math.h>

#define T_SEQ 2048
#define DMODEL 2048
#define NH 32
#define NKV 8
#define HD 64
#define KVW (NKV*HD)   // 512

// ---- scratch (small; no 512MB probs buffer — probs only ever go to d_out) ----
__device__ float g_Q[(size_t)T_SEQ * DMODEL];   // 16 MB
__device__ float g_K[(size_t)T_SEQ * KVW];      // 4 MB
__device__ float g_V[(size_t)T_SEQ * KVW];      // 4 MB
__device__ float g_A[(size_t)T_SEQ * DMODEL];   // 16 MB (attn out pre-Wo)

// ============================================================================
// Generic tiled SGEMM: C[M,N] = A[M,K] @ B[K,N], row-major, dims divide tiles.
// ============================================================================
template<int BM,int BN,int BK,int TM,int TN>
__device__ __forceinline__ void gemm_body(
    const float* __restrict__ A, int lda,
    const float* __restrict__ B, int ldb,
    float* __restrict__ C, int ldc,
    int K, int m0, int n0)
{
    __shared__ float As[BK][BM];
    __shared__ float Bs[BK][BN];
    const int tid = threadIdx.x;
    const int tx = tid % (BN/TN);
    const int ty = tid / (BN/TN);
    float acc[TM][TN];
    #pragma unroll
    for (int i=0;i<TM;i++)
        #pragma unroll
        for (int j=0;j<TN;j++) acc[i][j]=0.f;

    for (int k0 = 0; k0 < K; k0 += BK) {
        constexpr int AV = BM*BK/4/256;
        #pragma unroll
        for (int i = 0; i < AV; i++) {
            int v = tid + i*256;
            int r = v / (BK/4);
            int c4 = v % (BK/4);
            float4 a = *(const float4*)&A[(size_t)(m0+r)*lda + k0 + c4*4];
            As[c4*4+0][r]=a.x; As[c4*4+1][r]=a.y; As[c4*4+2][r]=a.z; As[c4*4+3][r]=a.w;
        }
        constexpr int BV = BK*BN/4/256;
        #pragma unroll
        for (int i = 0; i < BV; i++) {
            int v = tid + i*256;
            int r = v / (BN/4);
            int c4 = v % (BN/4);
            *(float4*)&Bs[r][c4*4] = *(const float4*)&B[(size_t)(k0+r)*ldb + n0 + c4*4];
        }
        __syncthreads();
        #pragma unroll
        for (int kk = 0; kk < BK; kk++) {
            float a[TM], b[TN];
            #pragma unroll
            for (int i=0;i<TM;i+=4) *(float4*)&a[i] = *(const float4*)&As[kk][ty*TM+i];
            #pragma unroll
            for (int j=0;j<TN;j+=4) *(float4*)&b[j] = *(const float4*)&Bs[kk][tx*TN+j];
            #pragma unroll
            for (int i=0;i<TM;i++)
                #pragma unroll
                for (int j=0;j<TN;j++)
                    acc[i][j] = fmaf(a[i], b[j], acc[i][j]);
        }
        __syncthreads();
    }
    #pragma unroll
    for (int i=0;i<TM;i++) {
        #pragma unroll
        for (int j=0;j<TN;j+=4) {
            float4 v = make_float4(acc[i][j],acc[i][j+1],acc[i][j+2],acc[i][j+3]);
            *(float4*)&C[(size_t)(m0+ty*TM+i)*ldc + n0 + tx*TN + j] = v;
        }
    }
}

__global__ void __launch_bounds__(256) sgemm128(
    const float* __restrict__ A, int lda, const float* __restrict__ B, int ldb,
    float* __restrict__ C, int ldc, int K)
{
    gemm_body<128,128,16,8,8>(A,lda,B,ldb,C,ldc,K, blockIdx.y*128, blockIdx.x*128);
}

// PV: per head z: A=probs[h], B = V col-slice, C = attn-out col-slice
__global__ void __launch_bounds__(256) pv_gemm(
    const float* __restrict__ P, const float* __restrict__ V, float* __restrict__ O)
{
    int h = blockIdx.z;
    const float* A = P + (size_t)h * T_SEQ * T_SEQ;
    const float* B = V + (h>>2)*HD;
    float* C = O + h*HD;
    gemm_body<128,64,16,8,4>(A, T_SEQ, B, KVW, C, DMODEL, T_SEQ, blockIdx.y*128, 0);
}

// ============================================================================
// RoPE (interleaved pairs, matches reference tables)
// ============================================================================
__global__ void rope_kernel(float* __restrict__ buf, int rowW, int nPairs)
{
    int idx = blockIdx.x*blockDim.x + threadIdx.x;
    if (idx >= nPairs) return;
    int pairsPerRow = rowW >> 1;
    int t = idx / pairsPerRow;
    int p = idx % pairsPerRow;
    int c = 2*p;
    int j = (c & 63) >> 1;                        // pair index within head
    float theta = powf(10000.0f, -(float)(2*j) / 64.0f);
    float f = (float)t * theta;
    float sn, cs;
    sincosf(f, &sn, &cs);
    size_t base = (size_t)t*rowW + c;
    float x1 = buf[base], x2 = buf[base+1];
    buf[base]   = x1*cs - x2*sn;
    buf[base+1] = x1*sn + x2*cs;
}

// ============================================================================
// Logits kernel (materialized-probs path): 128x128 tile of Q@K^T per block,
// applies scale + the "faithful bug" mask transform, writes logits.
// ============================================================================
__global__ void __launch_bounds__(256) logits_kernel(
    const float* __restrict__ Q, const float* __restrict__ Kb,
    const int* __restrict__ mask, float* __restrict__ logits)
{
    __shared__ float Qs[32][128];
    __shared__ float Ks[32][128];
    const int h = blockIdx.z, kv = h >> 2;
    const int q0 = blockIdx.y * 128, k0 = blockIdx.x * 128;
    const int tid = threadIdx.x, tx = tid % 16, ty = tid / 16;
    float acc[8][8];
    #pragma unroll
    for (int i=0;i<8;i++)
        #pragma unroll
        for (int j=0;j<8;j++) acc[i][j]=0.f;

    for (int d0 = 0; d0 < HD; d0 += 32) {
        #pragma unroll
        for (int i = 0; i < 4; i++) {
            int v = tid + i*256;
            int r = v >> 3, c4 = v & 7;
            float4 a = *(const float4*)&Q[(size_t)(q0+r)*DMODEL + h*HD + d0 + c4*4];
            Qs[c4*4+0][r]=a.x; Qs[c4*4+1][r]=a.y; Qs[c4*4+2][r]=a.z; Qs[c4*4+3][r]=a.w;
        }
        #pragma unroll
        for (int i = 0; i < 4; i++) {
            int v = tid + i*256;
            int r = v >> 3, c4 = v & 7;
            float4 a = *(const float4*)&Kb[(size_t)(k0+r)*KVW + kv*HD + d0 + c4*4];
            Ks[c4*4+0][r]=a.x; Ks[c4*4+1][r]=a.y; Ks[c4*4+2][r]=a.z; Ks[c4*4+3][r]=a.w;
        }
        __syncthreads();
        #pragma unroll
        for (int d = 0; d < 32; d++) {
            float a[8], b[8];
            *(float4*)&a[0] = *(const float4*)&Qs[d][ty*8];
            *(float4*)&a[4] = *(const float4*)&Qs[d][ty*8+4];
            *(float4*)&b[0] = *(const float4*)&Ks[d][tx*8];
            *(float4*)&b[4] = *(const float4*)&Ks[d][tx*8+4];
            #pragma unroll
            for (int i=0;i<8;i++)
                #pragma unroll
                for (int j=0;j<8;j++)
                    acc[i][j] = fmaf(a[i], b[j], acc[i][j]);
        }
        __syncthreads();
    }
    #pragma unroll
    for (int i=0;i<8;i++) {
        int q = q0 + ty*8 + i;
        const int* mr = mask + (size_t)q*T_SEQ + k0 + tx*8;
        float* lr = logits + ((size_t)h*T_SEQ + q)*T_SEQ + k0 + tx*8;
        #pragma unroll
        for (int j=0;j<8;j++) {
            float s = acc[i][j]*0.125f;
            lr[j] = mr[j] ? (s+s) : (s - 1e9f);
        }
    }
}

// In-place row softmax over T_SEQ=2048 (8 elems/thread)
__global__ void __launch_bounds__(256) softmax_kernel(float* __restrict__ p)
{
    size_t row = blockIdx.x;
    float* ptr = p + row*(size_t)T_SEQ;
    int tid = threadIdx.x;
    int lane = tid & 31, warp = tid >> 5;
    __shared__ float sm[8];
    float v[8];
    float mx = -3.0e38f;
    #pragma unroll
    for (int i=0;i<8;i++){ v[i]=ptr[tid+i*256]; mx=fmaxf(mx,v[i]); }
    #pragma unroll
    for (int o=16;o>0;o>>=1) mx = fmaxf(mx, __shfl_xor_sync(0xffffffffu, mx, o));
    if (lane==0) sm[warp]=mx;
    __syncthreads();
    if (tid==0){ float m=sm[0]; for(int i=1;i<8;i++) m=fmaxf(m,sm[i]); sm[0]=m; }
    __syncthreads();
    mx = sm[0];
    __syncthreads();
    float s=0.f;
    #pragma unroll
    for (int i=0;i<8;i++){ v[i]=expf(v[i]-mx); s+=v[i]; }
    #pragma unroll
    for (int o=16;o>0;o>>=1) s += __shfl_xor_sync(0xffffffffu, s, o);
    if (lane==0) sm[warp]=s;
    __syncthreads();
    if (tid==0){ float t=0; for(int i=1;i<8;i++) t+=sm[i]; sm[0]+=t; }
    __syncthreads();
    float inv = 1.0f/sm[0];
    #pragma unroll
    for (int i=0;i<8;i++) ptr[tid+i*256] = v[i]*inv;
}

// ============================================================================
// Flash attention (out-only path, no probs materialization).
// Block = (head, 64-query tile). 32-key iterations, online softmax.
// ============================================================================
__global__ void __launch_bounds__(256) flash_kernel(
    const float* __restrict__ Q, const float* __restrict__ Kb,
    const float* __restrict__ Vb, const int* __restrict__ mask,
    float* __restrict__ Oout)
{
    __shared__ float Qs[64][64];  // [d][q]
    __shared__ float Kt[64][32];  // [d][k]
    __shared__ float Vs[32][64];  // [k][d]
    __shared__ float Ps[32][64];  // [k][q]
    const int h = blockIdx.y, kv = h >> 2;
    const int q0 = blockIdx.x * 64;
    const int tid = threadIdx.x, tx = tid % 16, ty = tid / 16;
    const float NEG_INF = __int_as_float(0xff800000);

    #pragma unroll
    for (int i = 0; i < 4; i++) {
        int v = tid + i*256;
        int r = v >> 4, c4 = v & 15;
        float4 a = *(const float4*)&Q[(size_t)(q0+r)*DMODEL + h*HD + c4*4];
        Qs[c4*4+0][r]=a.x; Qs[c4*4+1][r]=a.y; Qs[c4*4+2][r]=a.z; Qs[c4*4+3][r]=a.w;
    }
    float accO[4][4];
    float mrow[4], lrow[4];
    #pragma unroll
    for (int i=0;i<4;i++){
        mrow[i]=NEG_INF; lrow[i]=0.f;
        #pragma unroll
        for (int j=0;j<4;j++) accO[i][j]=0.f;
    }
    __syncthreads();

    for (int k0 = 0; k0 < T_SEQ; k0 += 32) {
        #pragma unroll
        for (int i = 0; i < 2; i++) {
            int v = tid + i*256;
            int r = v >> 4, c4 = v & 15;
            float4 a = *(const float4*)&Kb[(size_t)(k0+r)*KVW + kv*HD + c4*4];
            Kt[c4*4+0][r]=a.x; Kt[c4*4+1][r]=a.y; Kt[c4*4+2][r]=a.z; Kt[c4*4+3][r]=a.w;
            float4 b = *(const float4*)&Vb[(size_t)(k0+r)*KVW + kv*HD + c4*4];
            *(float4*)&Vs[r][c4*4] = b;
        }
        __syncthreads();

        // S = Q @ K^T tile (4 q-rows x 2 k-cols per thread)
        float s[4][2] = {{0,0},{0,0},{0,0},{0,0}};
        #pragma unroll
        for (int d = 0; d < 64; d++) {
            float4 qv = *(const float4*)&Qs[d][ty*4];
            float ka = Kt[d][tx*2], kb = Kt[d][tx*2+1];
            s[0][0]=fmaf(qv.x,ka,s[0][0]); s[0][1]=fmaf(qv.x,kb,s[0][1]);
            s[1][0]=fmaf(qv.y,ka,s[1][0]); s[1][1]=fmaf(qv.y,kb,s[1][1]);
            s[2][0]=fmaf(qv.z,ka,s[2][0]); s[2][1]=fmaf(qv.z,kb,s[2][1]);
            s[3][0]=fmaf(qv.w,ka,s[3][0]); s[3][1]=fmaf(qv.w,kb,s[3][1]);
        }
        float alpha[4];
        #pragma unroll
        for (int i = 0; i < 4; i++) {
            int qg = q0 + ty*4 + i;
            const int* mr = mask + (size_t)qg*T_SEQ + k0 + tx*2;
            float s0 = s[i][0]*0.125f, s1 = s[i][1]*0.125f;
            s0 = mr[0] ? (s0+s0) : (s0 - 1e9f);
            s1 = mr[1] ? (s1+s1) : (s1 - 1e9f);
            float m = fmaxf(s0, s1);
            #pragma unroll
            for (int o=8;o>0;o>>=1) m = fmaxf(m, __shfl_xor_sync(0xffffffffu, m, o));
            float mnew = fmaxf(mrow[i], m);
            alpha[i] = expf(mrow[i] - mnew);
            mrow[i] = mnew;
            float p0 = expf(s0 - mnew), p1 = expf(s1 - mnew);
            s[i][0]=p0; s[i][1]=p1;
            float ps = p0 + p1;
            #pragma unroll
            for (int o=8;o>0;o>>=1) ps += __shfl_xor_sync(0xffffffffu, ps, o);
            lrow[i] = lrow[i]*alpha[i] + ps;
        }
        // stage P to smem
        #pragma unroll
        for (int i=0;i<4;i++){
            Ps[tx*2+0][ty*4+i] = s[i][0];
            Ps[tx*2+1][ty*4+i] = s[i][1];
        }
        __syncthreads();
        // O = alpha*O + P @ V
        #pragma unroll
        for (int i=0;i<4;i++)
            #pragma unroll
            for (int j=0;j<4;j++) accO[i][j] *= alpha[i];
        #pragma unroll
        for (int k = 0; k < 32; k++) {
            float4 pv = *(const float4*)&Ps[k][ty*4];
            float4 vv = *(const float4*)&Vs[k][tx*4];
            accO[0][0]=fmaf(pv.x,vv.x,accO[0][0]); accO[0][1]=fmaf(pv.x,vv.y,accO[0][1]);
            accO[0][2]=fmaf(pv.x,vv.z,accO[0][2]); accO[0][3]=fmaf(pv.x,vv.w,accO[0][3]);
            accO[1][0]=fmaf(pv.y,vv.x,accO[1][0]); accO[1][1]=fmaf(pv.y,vv.y,accO[1][1]);
            accO[1][2]=fmaf(pv.y,vv.z,accO[1][2]); accO[1][3]=fmaf(pv.y,vv.w,accO[1][3]);
            accO[2][0]=fmaf(pv.z,vv.x,accO[2][0]); accO[2][1]=fmaf(pv.z,vv.y,accO[2][1]);
            accO[2][2]=fmaf(pv.z,vv.z,accO[2][2]); accO[2][3]=fmaf(pv.z,vv.w,accO[2][3]);
            accO[3][0]=fmaf(pv.w,vv.x,accO[3][0]); accO[3][1]=fmaf(pv.w,vv.y,accO[3][1]);
            accO[3][2]=fmaf(pv.w,vv.z,accO[3][2]); accO[3][3]=fmaf(pv.w,vv.w,accO[3][3]);
        }
        __syncthreads();
    }
    #pragma unroll
    for (int i = 0; i < 4; i++) {
        float inv = 1.0f / lrow[i];
        int qg = q0 + ty*4 + i;
        float4 o = make_float4(accO[i][0]*inv, accO[i][1]*inv, accO[i][2]*inv, accO[i][3]*inv);
        *(float4*)&Oout[(size_t)qg*DMODEL + h*HD + tx*4] = o;
    }
}

// ============================================================================
extern "C" void kernel_launch(void* const* d_in, const int* in_sizes, int n_in,
                              void* d_out, int out_size)
{
    (void)in_sizes; (void)n_in;
    const float* x  = (const float*)d_in[0];
    const float* Wq = (const float*)d_in[1];
    const float* Wk = (const float*)d_in[2];
    const float* Wv = (const float*)d_in[3];
    const float* Wo = (const float*)d_in[4];
    const int* mask = (const int*)d_in[5];
    float* out = (float*)d_out;

    float *gQ, *gK, *gV, *gA;
    cudaGetSymbolAddress((void**)&gQ, g_Q);
    cudaGetSymbolAddress((void**)&gK, g_K);
    cudaGetSymbolAddress((void**)&gV, g_V);
    cudaGetSymbolAddress((void**)&gA, g_A);

    // QKV projections
    sgemm128<<<dim3(DMODEL/128, T_SEQ/128), 256>>>(x, DMODEL, Wq, DMODEL, gQ, DMODEL, DMODEL);
    sgemm128<<<dim3(KVW/128,   T_SEQ/128), 256>>>(x, DMODEL, Wk, KVW,   gK, KVW,   DMODEL);
    sgemm128<<<dim3(KVW/128,   T_SEQ/128), 256>>>(x, DMODEL, Wv, KVW,   gV, KVW,   DMODEL);

    // RoPE on Q and K
    {
        int np_q = T_SEQ * (DMODEL/2);
        int np_k = T_SEQ * (KVW/2);
        rope_kernel<<<(np_q+255)/256, 256>>>(gQ, DMODEL, np_q);
        rope_kernel<<<(np_k+255)/256, 256>>>(gK, KVW,   np_k);
    }

    const long long OUT_N = (long long)T_SEQ * DMODEL;          // 4194304
    const long long ATT_N = (long long)NH * T_SEQ * T_SEQ;      // 134217728
    long long osz = (long long)out_size;

    if (osz >= OUT_N + ATT_N) {
        // out followed by attn: materialize probs directly into d_out
        float* probs = out + OUT_N;
        logits_kernel<<<dim3(T_SEQ/128, T_SEQ/128, NH), 256>>>(gQ, gK, mask, probs);
        softmax_kernel<<<NH*T_SEQ, 256>>>(probs);
        pv_gemm<<<dim3(1, T_SEQ/128, NH), 256>>>(probs, gV, gA);
        sgemm128<<<dim3(DMODEL/128, T_SEQ/128), 256>>>(gA, DMODEL, Wo, DMODEL, out, DMODEL, DMODEL);
    } else if (osz == ATT_N) {
        // attn only
        logits_kernel<<<dim3(T_SEQ/128, T_SEQ/128, NH), 256>>>(gQ, gK, mask, out);
        softmax_kernel<<<NH*T_SEQ, 256>>>(out);
    } else {
        // out only: flash attention, no probs materialization
        flash_kernel<<<dim3(T_SEQ/64, NH), 256>>>(gQ, gK, gV, mask, gA);
        sgemm128<<<dim3(DMODEL/128, T_SEQ/128), 256>>>(gA, DMODEL, Wo, DMODEL, out, DMODEL, DMODEL);
    }
}

// round 4
// speedup vs baseline: 1.6456x; 1.6456x over previous
#include <cuda_runtime.h>
#include <cuda_bf16.h>
#include <math.h>

#define T_SEQ 2048
#define DMODEL 2048
#define NH 32
#define NKV 8
#define HD 64
#define KVW (NKV*HD)   // 512

// ---- scratch ----
__device__ float g_Q[(size_t)T_SEQ * DMODEL];   // 16 MB
__device__ float g_K[(size_t)T_SEQ * KVW];      // 4 MB
__device__ float g_V[(size_t)T_SEQ * KVW];      // 4 MB
__device__ float g_A[(size_t)T_SEQ * DMODEL];   // 16 MB
__device__ float g_P[(size_t)NH * T_SEQ * T_SEQ]; // 512 MB probs scratch (out-only path)

// ============================================================================
// bf16 split helpers
// ============================================================================
__device__ __forceinline__ void split1(float x, unsigned short &h, unsigned short &l) {
    __nv_bfloat16 hb = __float2bfloat16(x);
    __nv_bfloat16 lb = __float2bfloat16(x - __bfloat162float(hb));
    h = *(unsigned short*)&hb;
    l = *(unsigned short*)&lb;
}
__device__ __forceinline__ void split2(float x, float y, unsigned &hi, unsigned &lo) {
    unsigned short hx, lx, hy, ly;
    split1(x, hx, lx); split1(y, hy, ly);
    hi = ((unsigned)hy << 16) | hx;
    lo = ((unsigned)ly << 16) | lx;
}

__device__ __forceinline__ void mma16816(float c[4], const unsigned a[4], const unsigned b[2]) {
    asm volatile(
        "mma.sync.aligned.m16n8k16.row.col.f32.bf16.bf16.f32 "
        "{%0,%1,%2,%3},{%4,%5,%6,%7},{%8,%9},{%0,%1,%2,%3};\n"
        : "+f"(c[0]), "+f"(c[1]), "+f"(c[2]), "+f"(c[3])
        : "r"(a[0]), "r"(a[1]), "r"(a[2]), "r"(a[3]), "r"(b[0]), "r"(b[1]));
}

// ============================================================================
// Tensor-core GEMM body, fp32 in/out, bf16-split (hh + hl + lh) accumulation.
//   C[M,N] = A[M,K] @ B[...]
//   B_NMAJOR=0: B is [K,N] row-major (transposed into smem)
//   B_NMAJOR=1: B is [N,K] row-major (loaded directly; e.g. K for Q@K^T)
//   EPI=0: plain store.  EPI=1: logits epilogue (scale + faithful-bug mask).
// ============================================================================
template<int BM,int BN,int BK,int WM,int WN,int B_NMAJOR,int EPI>
__device__ __forceinline__ void mma_gemm(
    const float* __restrict__ A, int lda,
    const float* __restrict__ B, int ldb,
    float* __restrict__ C, int ldc,
    int K, int m0, int n0,
    const int* __restrict__ mask)
{
    constexpr int PAD = 2;
    __shared__ unsigned short As[2][BM][BK+PAD];
    __shared__ unsigned short Bs[2][BN][BK+PAD];

    const int tid  = threadIdx.x;
    const int w    = tid >> 5;
    const int lane = tid & 31;
    constexpr int WROWS = BM / WM;
    const int wm = (w % WROWS) * WM;
    const int wn = (w / WROWS) * WN;
    constexpr int MT = WM / 16;
    constexpr int NT = WN / 8;
    const int g  = lane >> 2;
    const int t4 = lane & 3;

    float acc[MT][NT][4];
    #pragma unroll
    for (int mt=0;mt<MT;mt++)
        #pragma unroll
        for (int nt=0;nt<NT;nt++)
            #pragma unroll
            for (int i=0;i<4;i++) acc[mt][nt][i]=0.f;

    for (int k0 = 0; k0 < K; k0 += BK) {
        // ---- stage A tile (hi/lo) ----
        #pragma unroll
        for (int i = 0; i < BM*BK/4/256; i++) {
            int v = tid + i*256;
            int r = v / (BK/4);
            int c = (v % (BK/4)) * 4;
            float4 a = *(const float4*)&A[(size_t)(m0+r)*lda + k0 + c];
            unsigned h0,l0,h1,l1;
            split2(a.x, a.y, h0, l0);
            split2(a.z, a.w, h1, l1);
            *(unsigned*)&As[0][r][c]   = h0; *(unsigned*)&As[0][r][c+2] = h1;
            *(unsigned*)&As[1][r][c]   = l0; *(unsigned*)&As[1][r][c+2] = l1;
        }
        // ---- stage B tile (hi/lo) ----
        if (B_NMAJOR) {
            #pragma unroll
            for (int i = 0; i < BN*BK/4/256; i++) {
                int v = tid + i*256;
                int r = v / (BK/4);
                int c = (v % (BK/4)) * 4;
                float4 b = *(const float4*)&B[(size_t)(n0+r)*ldb + k0 + c];
                unsigned h0,l0,h1,l1;
                split2(b.x, b.y, h0, l0);
                split2(b.z, b.w, h1, l1);
                *(unsigned*)&Bs[0][r][c]   = h0; *(unsigned*)&Bs[0][r][c+2] = h1;
                *(unsigned*)&Bs[1][r][c]   = l0; *(unsigned*)&Bs[1][r][c+2] = l1;
            }
        } else {
            #pragma unroll
            for (int i = 0; i < BK*BN/4/256; i++) {
                int v = tid + i*256;
                int r = v / (BN/4);          // k row
                int c = (v % (BN/4)) * 4;    // n col
                float4 b = *(const float4*)&B[(size_t)(k0+r)*ldb + n0 + c];
                float bv[4] = {b.x, b.y, b.z, b.w};
                #pragma unroll
                for (int j = 0; j < 4; j++) {
                    unsigned short hb, lb;
                    split1(bv[j], hb, lb);
                    Bs[0][c+j][r] = hb;
                    Bs[1][c+j][r] = lb;
                }
            }
        }
        __syncthreads();

        // ---- mma over BK ----
        #pragma unroll
        for (int ks = 0; ks < BK; ks += 16) {
            unsigned ah[MT][4], al[MT][4], bh[NT][2], bl[NT][2];
            #pragma unroll
            for (int mt = 0; mt < MT; mt++) {
                int row = wm + mt*16 + g;
                int kc  = ks + t4*2;
                ah[mt][0] = *(unsigned*)&As[0][row  ][kc];
                ah[mt][1] = *(unsigned*)&As[0][row+8][kc];
                ah[mt][2] = *(unsigned*)&As[0][row  ][kc+8];
                ah[mt][3] = *(unsigned*)&As[0][row+8][kc+8];
                al[mt][0] = *(unsigned*)&As[1][row  ][kc];
                al[mt][1] = *(unsigned*)&As[1][row+8][kc];
                al[mt][2] = *(unsigned*)&As[1][row  ][kc+8];
                al[mt][3] = *(unsigned*)&As[1][row+8][kc+8];
            }
            #pragma unroll
            for (int nt = 0; nt < NT; nt++) {
                int col = wn + nt*8 + g;
                int kc  = ks + t4*2;
                bh[nt][0] = *(unsigned*)&Bs[0][col][kc];
                bh[nt][1] = *(unsigned*)&Bs[0][col][kc+8];
                bl[nt][0] = *(unsigned*)&Bs[1][col][kc];
                bl[nt][1] = *(unsigned*)&Bs[1][col][kc+8];
            }
            #pragma unroll
            for (int mt = 0; mt < MT; mt++)
                #pragma unroll
                for (int nt = 0; nt < NT; nt++) {
                    mma16816(acc[mt][nt], ah[mt], bh[nt]);
                    mma16816(acc[mt][nt], ah[mt], bl[nt]);
                    mma16816(acc[mt][nt], al[mt], bh[nt]);
                }
        }
        __syncthreads();
    }

    // ---- epilogue ----
    #pragma unroll
    for (int mt = 0; mt < MT; mt++) {
        #pragma unroll
        for (int nt = 0; nt < NT; nt++) {
            int row = m0 + wm + mt*16 + g;
            int col = n0 + wn + nt*8 + t4*2;
            float* c0 = &C[(size_t)row    *ldc + col];
            float* c1 = &C[(size_t)(row+8)*ldc + col];
            if (EPI == 0) {
                c0[0] = acc[mt][nt][0]; c0[1] = acc[mt][nt][1];
                c1[0] = acc[mt][nt][2]; c1[1] = acc[mt][nt][3];
            } else {
                const int* mp0 = &mask[(size_t)row    *T_SEQ + col];
                const int* mp1 = &mask[(size_t)(row+8)*T_SEQ + col];
                float s;
                s = acc[mt][nt][0]*0.125f; c0[0] = mp0[0] ? (s+s) : (s - 1e9f);
                s = acc[mt][nt][1]*0.125f; c0[1] = mp0[1] ? (s+s) : (s - 1e9f);
                s = acc[mt][nt][2]*0.125f; c1[0] = mp1[0] ? (s+s) : (s - 1e9f);
                s = acc[mt][nt][3]*0.125f; c1[1] = mp1[1] ? (s+s) : (s - 1e9f);
            }
        }
    }
}

// ============================================================================
// Kernel wrappers
// ============================================================================
__global__ void __launch_bounds__(256) gemm_tc(
    const float* __restrict__ A, int lda, const float* __restrict__ B, int ldb,
    float* __restrict__ C, int ldc, int K)
{
    mma_gemm<128,128,32,32,64,0,0>(A,lda,B,ldb,C,ldc,K, blockIdx.y*128, blockIdx.x*128, nullptr);
}

__global__ void __launch_bounds__(256) logits_tc(
    const float* __restrict__ Q, const float* __restrict__ Kb,
    const int* __restrict__ mask, float* __restrict__ logits)
{
    int h = blockIdx.z;
    mma_gemm<128,128,32,32,64,1,1>(
        Q + h*HD, DMODEL,
        Kb + (h>>2)*HD, KVW,
        logits + (size_t)h*T_SEQ*T_SEQ, T_SEQ,
        HD, blockIdx.y*128, blockIdx.x*128, mask);
}

__global__ void __launch_bounds__(256) pv_tc(
    const float* __restrict__ P, const float* __restrict__ V, float* __restrict__ O)
{
    int h = blockIdx.z;
    mma_gemm<128,64,32,32,32,0,0>(
        P + (size_t)h*T_SEQ*T_SEQ, T_SEQ,
        V + (h>>2)*HD, KVW,
        O + h*HD, DMODEL,
        T_SEQ, blockIdx.y*128, 0, nullptr);
}

// ============================================================================
// RoPE (interleaved pairs)
// ============================================================================
__global__ void rope_kernel(float* __restrict__ buf, int rowW, int nPairs)
{
    int idx = blockIdx.x*blockDim.x + threadIdx.x;
    if (idx >= nPairs) return;
    int pairsPerRow = rowW >> 1;
    int t = idx / pairsPerRow;
    int p = idx % pairsPerRow;
    int c = 2*p;
    int j = (c & 63) >> 1;
    float theta = powf(10000.0f, -(float)(2*j) / 64.0f);
    float f = (float)t * theta;
    float sn, cs;
    sincosf(f, &sn, &cs);
    size_t base = (size_t)t*rowW + c;
    float x1 = buf[base], x2 = buf[base+1];
    buf[base]   = x1*cs - x2*sn;
    buf[base+1] = x1*sn + x2*cs;
}

// ============================================================================
// In-place row softmax over T_SEQ=2048
// ============================================================================
__global__ void __launch_bounds__(256) softmax_kernel(float* __restrict__ p)
{
    size_t row = blockIdx.x;
    float* ptr = p + row*(size_t)T_SEQ;
    int tid = threadIdx.x;
    int lane = tid & 31, warp = tid >> 5;
    __shared__ float sm[8];
    float v[8];
    float mx = -3.0e38f;
    #pragma unroll
    for (int i=0;i<8;i++){ v[i]=ptr[tid+i*256]; mx=fmaxf(mx,v[i]); }
    #pragma unroll
    for (int o=16;o>0;o>>=1) mx = fmaxf(mx, __shfl_xor_sync(0xffffffffu, mx, o));
    if (lane==0) sm[warp]=mx;
    __syncthreads();
    if (tid==0){ float m=sm[0]; for(int i=1;i<8;i++) m=fmaxf(m,sm[i]); sm[0]=m; }
    __syncthreads();
    mx = sm[0];
    __syncthreads();
    float s=0.f;
    #pragma unroll
    for (int i=0;i<8;i++){ v[i]=expf(v[i]-mx); s+=v[i]; }
    #pragma unroll
    for (int o=16;o>0;o>>=1) s += __shfl_xor_sync(0xffffffffu, s, o);
    if (lane==0) sm[warp]=s;
    __syncthreads();
    if (tid==0){ float t=0; for(int i=1;i<8;i++) t+=sm[i]; sm[0]+=t; }
    __syncthreads();
    float inv = 1.0f/sm[0];
    #pragma unroll
    for (int i=0;i<8;i++) ptr[tid+i*256] = v[i]*inv;
}

// ============================================================================
extern "C" void kernel_launch(void* const* d_in, const int* in_sizes, int n_in,
                              void* d_out, int out_size)
{
    (void)in_sizes; (void)n_in;
    const float* x  = (const float*)d_in[0];
    const float* Wq = (const float*)d_in[1];
    const float* Wk = (const float*)d_in[2];
    const float* Wv = (const float*)d_in[3];
    const float* Wo = (const float*)d_in[4];
    const int* mask = (const int*)d_in[5];
    float* out = (float*)d_out;

    float *gQ, *gK, *gV, *gA, *gP;
    cudaGetSymbolAddress((void**)&gQ, g_Q);
    cudaGetSymbolAddress((void**)&gK, g_K);
    cudaGetSymbolAddress((void**)&gV, g_V);
    cudaGetSymbolAddress((void**)&gA, g_A);
    cudaGetSymbolAddress((void**)&gP, g_P);

    // QKV projections (tensor cores)
    gemm_tc<<<dim3(DMODEL/128, T_SEQ/128), 256>>>(x, DMODEL, Wq, DMODEL, gQ, DMODEL, DMODEL);
    gemm_tc<<<dim3(KVW/128,   T_SEQ/128), 256>>>(x, DMODEL, Wk, KVW,   gK, KVW,   DMODEL);
    gemm_tc<<<dim3(KVW/128,   T_SEQ/128), 256>>>(x, DMODEL, Wv, KVW,   gV, KVW,   DMODEL);

    // RoPE on Q and K
    {
        int np_q = T_SEQ * (DMODEL/2);
        int np_k = T_SEQ * (KVW/2);
        rope_kernel<<<(np_q+255)/256, 256>>>(gQ, DMODEL, np_q);
        rope_kernel<<<(np_k+255)/256, 256>>>(gK, KVW,   np_k);
    }

    const long long OUT_N = (long long)T_SEQ * DMODEL;          // 4194304
    const long long ATT_N = (long long)NH * T_SEQ * T_SEQ;      // 134217728
    long long osz = (long long)out_size;

    float* probs;
    bool need_out;
    if (osz >= OUT_N + ATT_N)      { probs = out + OUT_N; need_out = true;  }
    else if (osz == ATT_N)         { probs = out;         need_out = false; }
    else                           { probs = gP;          need_out = true;  }

    logits_tc<<<dim3(T_SEQ/128, T_SEQ/128, NH), 256>>>(gQ, gK, mask, probs);
    softmax_kernel<<<NH*T_SEQ, 256>>>(probs);
    if (need_out) {
        pv_tc<<<dim3(1, T_SEQ/128, NH), 256>>>(probs, gV, gA);
        gemm_tc<<<dim3(DMODEL/128, T_SEQ/128), 256>>>(gA, DMODEL, Wo, DMODEL, out, DMODEL, DMODEL);
    }
}

// round 6
// speedup vs baseline: 1.8728x; 1.1380x over previous
#include <cuda_runtime.h>
#include <cuda_bf16.h>
#include <math.h>

#define T_SEQ 2048
#define DMODEL 2048
#define NH 32
#define NKV 8
#define HD 64
#define KVW (NKV*HD)   // 512
typedef unsigned short ushort_t;

// ---------------- scratch (device globals; no allocs) ----------------
__device__ float g_Q[(size_t)T_SEQ * DMODEL];
__device__ float g_K[(size_t)T_SEQ * KVW];
__device__ float g_V[(size_t)T_SEQ * KVW];
__device__ float g_P[(size_t)NH * T_SEQ * T_SEQ];          // 512 MB (out-only path)

__device__ __align__(16) ushort_t g_xh[(size_t)T_SEQ*DMODEL],  g_xl[(size_t)T_SEQ*DMODEL];
__device__ __align__(16) ushort_t g_Wqh[(size_t)DMODEL*DMODEL],g_Wql[(size_t)DMODEL*DMODEL];
__device__ __align__(16) ushort_t g_Wkh[(size_t)KVW*DMODEL],   g_Wkl[(size_t)KVW*DMODEL];
__device__ __align__(16) ushort_t g_Wvh[(size_t)KVW*DMODEL],   g_Wvl[(size_t)KVW*DMODEL];
__device__ __align__(16) ushort_t g_Woh[(size_t)DMODEL*DMODEL],g_Wol[(size_t)DMODEL*DMODEL];
__device__ __align__(16) ushort_t g_Qh[(size_t)T_SEQ*DMODEL],  g_Ql[(size_t)T_SEQ*DMODEL];
__device__ __align__(16) ushort_t g_Kh[(size_t)T_SEQ*KVW],     g_Kl[(size_t)T_SEQ*KVW];
__device__ __align__(16) ushort_t g_VTh[(size_t)KVW*T_SEQ],    g_VTl[(size_t)KVW*T_SEQ];
__device__ __align__(16) ushort_t g_Ph[(size_t)NH*T_SEQ*T_SEQ],g_Pl[(size_t)NH*T_SEQ*T_SEQ]; // 256MB each
__device__ __align__(16) ushort_t g_Ah[(size_t)T_SEQ*DMODEL],  g_Al[(size_t)T_SEQ*DMODEL];

// ---------------- helpers ----------------
__device__ __forceinline__ void split1(float x, ushort_t &h, ushort_t &l) {
    __nv_bfloat16 hb = __float2bfloat16(x);
    __nv_bfloat16 lb = __float2bfloat16(x - __bfloat162float(hb));
    h = *(ushort_t*)&hb;
    l = *(ushort_t*)&lb;
}

__device__ __forceinline__ void mma16816(float c[4], const unsigned a[4], const unsigned b[2]) {
    asm volatile(
        "mma.sync.aligned.m16n8k16.row.col.f32.bf16.bf16.f32 "
        "{%0,%1,%2,%3},{%4,%5,%6,%7},{%8,%9},{%0,%1,%2,%3};\n"
        : "+f"(c[0]), "+f"(c[1]), "+f"(c[2]), "+f"(c[3])
        : "r"(a[0]), "r"(a[1]), "r"(a[2]), "r"(a[3]), "r"(b[0]), "r"(b[1]));
}

__device__ __forceinline__ void cp16(void* dst, const void* src) {
    unsigned d = (unsigned)__cvta_generic_to_shared(dst);
    asm volatile("cp.async.cg.shared.global [%0], [%1], 16;\n" :: "r"(d), "l"(src));
}
__device__ __forceinline__ void cp_commit() { asm volatile("cp.async.commit_group;\n"); }
__device__ __forceinline__ void cp_wait1()  { asm volatile("cp.async.wait_group 1;\n"); }
__device__ __forceinline__ void cp_wait0()  { asm volatile("cp.async.wait_group 0;\n"); }

__device__ __forceinline__ void ldm4(unsigned r[4], const void* p) {
    unsigned a = (unsigned)__cvta_generic_to_shared(p);
    asm volatile("ldmatrix.sync.aligned.m8n8.x4.shared.b16 {%0,%1,%2,%3},[%4];\n"
        : "=r"(r[0]), "=r"(r[1]), "=r"(r[2]), "=r"(r[3]) : "r"(a));
}

// ============================================================================
// Pipelined bf16-split tensor-core GEMM.
//   A: hi/lo [M][K] (lda), B: hi/lo [N][K] (ldb, k-contiguous), BK=16.
//   EPI 0: fp32 C.   EPI 1: logits (scale + faithful-bug mask).
//   EPI 2: split store to Ch/Cl bf16.
// ============================================================================
#define BKK 16
#define PADK 24

template<int BM,int BN,int WM,int WN,int EPI>
__device__ __forceinline__ void mma_core(
    const ushort_t* __restrict__ Ah, const ushort_t* __restrict__ Al, int lda,
    const ushort_t* __restrict__ Bh, const ushort_t* __restrict__ Bl, int ldb,
    float* __restrict__ C, ushort_t* __restrict__ Ch, ushort_t* __restrict__ Cl, int ldc,
    int K, int m0, int n0, const int* __restrict__ mask)
{
    __shared__ __align__(16) ushort_t As[2][2][BM][PADK];
    __shared__ __align__(16) ushort_t Bs[2][2][BN][PADK];

    const int tid  = threadIdx.x;
    const int w    = tid >> 5;
    const int lane = tid & 31;
    constexpr int WROWS = BM / WM;
    const int wm = (w % WROWS) * WM;
    const int wn = (w / WROWS) * WN;
    constexpr int MT = WM / 16;
    constexpr int NT = WN / 8;
    const int g  = lane >> 2;
    const int t4 = lane & 3;
    // ldmatrix per-lane offsets (row within 16-block, col 0/8)
    const int roff = ((lane >> 3) & 1) * 8 + (lane & 7);
    const int coff = (lane >> 4) * 8;

    float acc[MT][NT][4];
    #pragma unroll
    for (int mt=0;mt<MT;mt++)
        #pragma unroll
        for (int nt=0;nt<NT;nt++)
            #pragma unroll
            for (int i=0;i<4;i++) acc[mt][nt][i]=0.f;

    constexpr int TC = 4*BM + 4*BN;   // 16B chunks per stage

    auto stage = [&](int buf, int k0) {
        #pragma unroll
        for (int i = 0; i < TC/256; i++) {
            int q = tid + i*256;
            if (q < 2*BM) {
                int r = q >> 1, o = (q & 1) * 8;
                cp16(&As[buf][0][r][o], Ah + (size_t)(m0+r)*lda + k0 + o);
            } else if (q < 4*BM) {
                int qq = q - 2*BM; int r = qq >> 1, o = (qq & 1) * 8;
                cp16(&As[buf][1][r][o], Al + (size_t)(m0+r)*lda + k0 + o);
            } else if (q < 4*BM + 2*BN) {
                int qq = q - 4*BM; int r = qq >> 1, o = (qq & 1) * 8;
                cp16(&Bs[buf][0][r][o], Bh + (size_t)(n0+r)*ldb + k0 + o);
            } else {
                int qq = q - 4*BM - 2*BN; int r = qq >> 1, o = (qq & 1) * 8;
                cp16(&Bs[buf][1][r][o], Bl + (size_t)(n0+r)*ldb + k0 + o);
            }
        }
    };

    const int KIT = K / BKK;
    stage(0, 0);
    cp_commit();
    int buf = 0;

    for (int it = 0; it < KIT; it++) {
        if (it + 1 < KIT) {
            stage(buf ^ 1, (it + 1) * BKK);
            cp_commit();
            cp_wait1();
        } else {
            cp_wait0();
        }
        __syncthreads();

        unsigned ah[MT][4], al[MT][4], bh[NT][2], bl[NT][2];
        #pragma unroll
        for (int mt = 0; mt < MT; mt++) {
            ldm4(ah[mt], &As[buf][0][wm + mt*16 + roff][coff]);
            ldm4(al[mt], &As[buf][1][wm + mt*16 + roff][coff]);
        }
        #pragma unroll
        for (int p = 0; p < NT/2; p++) {
            unsigned t[4];
            ldm4(t, &Bs[buf][0][wn + p*16 + roff][coff]);
            bh[2*p][0]=t[0]; bh[2*p][1]=t[2]; bh[2*p+1][0]=t[1]; bh[2*p+1][1]=t[3];
            ldm4(t, &Bs[buf][1][wn + p*16 + roff][coff]);
            bl[2*p][0]=t[0]; bl[2*p][1]=t[2]; bl[2*p+1][0]=t[1]; bl[2*p+1][1]=t[3];
        }
        #pragma unroll
        for (int mt = 0; mt < MT; mt++)
            #pragma unroll
            for (int nt = 0; nt < NT; nt++) {
                mma16816(acc[mt][nt], ah[mt], bh[nt]);
                mma16816(acc[mt][nt], ah[mt], bl[nt]);
                mma16816(acc[mt][nt], al[mt], bh[nt]);
            }
        __syncthreads();
        buf ^= 1;
    }

    // ---- epilogue ----
    #pragma unroll
    for (int mt = 0; mt < MT; mt++) {
        #pragma unroll
        for (int nt = 0; nt < NT; nt++) {
            int row = m0 + wm + mt*16 + g;
            int col = n0 + wn + nt*8 + t4*2;
            if (EPI == 0) {
                *(float2*)&C[(size_t)row    *ldc + col] = make_float2(acc[mt][nt][0], acc[mt][nt][1]);
                *(float2*)&C[(size_t)(row+8)*ldc + col] = make_float2(acc[mt][nt][2], acc[mt][nt][3]);
            } else if (EPI == 1) {
                int2 m0v = *(const int2*)&mask[(size_t)row    *T_SEQ + col];
                int2 m1v = *(const int2*)&mask[(size_t)(row+8)*T_SEQ + col];
                float s0 = acc[mt][nt][0]*0.125f, s1 = acc[mt][nt][1]*0.125f;
                float s2 = acc[mt][nt][2]*0.125f, s3 = acc[mt][nt][3]*0.125f;
                *(float2*)&C[(size_t)row    *ldc + col] =
                    make_float2(m0v.x ? (s0+s0) : (s0-1e9f), m0v.y ? (s1+s1) : (s1-1e9f));
                *(float2*)&C[(size_t)(row+8)*ldc + col] =
                    make_float2(m1v.x ? (s2+s2) : (s2-1e9f), m1v.y ? (s3+s3) : (s3-1e9f));
            } else {
                ushort_t h0,l0,h1,l1;
                split1(acc[mt][nt][0], h0, l0); split1(acc[mt][nt][1], h1, l1);
                *(unsigned*)&Ch[(size_t)row*ldc + col] = ((unsigned)h1<<16)|h0;
                *(unsigned*)&Cl[(size_t)row*ldc + col] = ((unsigned)l1<<16)|l0;
                split1(acc[mt][nt][2], h0, l0); split1(acc[mt][nt][3], h1, l1);
                *(unsigned*)&Ch[(size_t)(row+8)*ldc + col] = ((unsigned)h1<<16)|h0;
                *(unsigned*)&Cl[(size_t)(row+8)*ldc + col] = ((unsigned)l1<<16)|l0;
            }
        }
    }
}

// ---------------- GEMM wrappers ----------------
__global__ void __launch_bounds__(256,2) gemm_tc(
    const ushort_t* Ah, const ushort_t* Al, int lda,
    const ushort_t* Bh, const ushort_t* Bl, int ldb,
    float* C, int ldc, int K)
{
    mma_core<128,128,32,64,0>(Ah,Al,lda,Bh,Bl,ldb,C,nullptr,nullptr,ldc,K,
                              blockIdx.y*128, blockIdx.x*128, nullptr);
}

__global__ void __launch_bounds__(256,2) logits_tc(
    const ushort_t* Qh, const ushort_t* Ql,
    const ushort_t* Kh, const ushort_t* Kl,
    const int* mask, float* probs)
{
    int h = blockIdx.z;
    mma_core<128,128,32,64,1>(
        Qh + h*HD, Ql + h*HD, DMODEL,
        Kh + (h>>2)*HD, Kl + (h>>2)*HD, KVW,
        probs + (size_t)h*T_SEQ*T_SEQ, nullptr, nullptr, T_SEQ,
        HD, blockIdx.y*128, blockIdx.x*128, mask);
}

__global__ void __launch_bounds__(256,2) pv_tc(
    const ushort_t* Ph, const ushort_t* Pl,
    const ushort_t* VTh, const ushort_t* VTl,
    ushort_t* Ah, ushort_t* Al)
{
    int h = blockIdx.z;
    mma_core<128,64,32,32,2>(
        Ph + (size_t)h*T_SEQ*T_SEQ, Pl + (size_t)h*T_SEQ*T_SEQ, T_SEQ,
        VTh + (size_t)((h>>2)*HD)*T_SEQ, VTl + (size_t)((h>>2)*HD)*T_SEQ, T_SEQ,
        nullptr, Ah + h*HD, Al + h*HD, DMODEL,
        T_SEQ, blockIdx.y*128, 0, nullptr);
}

// ---------------- pre/post processing kernels ----------------
// elementwise split: fp32 -> bf16 hi/lo
__global__ void split_arr(const float* __restrict__ in, ushort_t* __restrict__ h,
                          ushort_t* __restrict__ l, int n)
{
    int i = blockIdx.x*blockDim.x + threadIdx.x;
    if (i*4 >= n) return;
    float4 v = *(const float4*)&in[i*4];
    ushort_t hh[4], ll[4];
    split1(v.x,hh[0],ll[0]); split1(v.y,hh[1],ll[1]);
    split1(v.z,hh[2],ll[2]); split1(v.w,hh[3],ll[3]);
    *(ushort2*)&h[i*4]   = make_ushort2(hh[0],hh[1]);
    *(ushort2*)&h[i*4+2] = make_ushort2(hh[2],hh[3]);
    *(ushort2*)&l[i*4]   = make_ushort2(ll[0],ll[1]);
    *(ushort2*)&l[i*4+2] = make_ushort2(ll[2],ll[3]);
}

// transpose + split: W[K][N] fp32 -> WT hi/lo [N][K] bf16
__global__ void splitT(const float* __restrict__ W, int K, int N,
                       ushort_t* __restrict__ Th, ushort_t* __restrict__ Tl)
{
    __shared__ float t[32][33];
    int k0 = blockIdx.y*32, n0 = blockIdx.x*32;
    for (int i = threadIdx.y; i < 32; i += 8)
        t[i][threadIdx.x] = W[(size_t)(k0+i)*N + n0 + threadIdx.x];
    __syncthreads();
    for (int i = threadIdx.y; i < 32; i += 8) {
        float v = t[threadIdx.x][i];
        ushort_t h, l;
        split1(v, h, l);
        Th[(size_t)(n0+i)*K + k0 + threadIdx.x] = h;
        Tl[(size_t)(n0+i)*K + k0 + threadIdx.x] = l;
    }
}

// RoPE + split: fp32 in -> bf16 hi/lo out
__global__ void rope_split(const float* __restrict__ in,
                           ushort_t* __restrict__ oh, ushort_t* __restrict__ ol,
                           int rowW, int nPairs)
{
    int idx = blockIdx.x*blockDim.x + threadIdx.x;
    if (idx >= nPairs) return;
    int pairsPerRow = rowW >> 1;
    int t = idx / pairsPerRow;
    int p = idx % pairsPerRow;
    int c = 2*p;
    int j = (c & 63) >> 1;
    float theta = powf(10000.0f, -(float)(2*j) / 64.0f);
    float f = (float)t * theta;
    float sn, cs;
    sincosf(f, &sn, &cs);
    size_t base = (size_t)t*rowW + c;
    float x1 = in[base], x2 = in[base+1];
    float y1 = x1*cs - x2*sn;
    float y2 = x1*sn + x2*cs;
    ushort_t h1,l1,h2,l2;
    split1(y1,h1,l1); split1(y2,h2,l2);
    *(ushort2*)&oh[base] = make_ushort2(h1,h2);
    *(ushort2*)&ol[base] = make_ushort2(l1,l2);
}

// softmax over rows of 2048; optional fp32 in-place write, optional hi/lo write
__global__ void __launch_bounds__(256) softmax_split(
    float* __restrict__ p, ushort_t* __restrict__ ph, ushort_t* __restrict__ pl,
    int wf32, int whl)
{
    size_t row = blockIdx.x;
    float* ptr = p + row*(size_t)T_SEQ;
    int tid = threadIdx.x;
    int lane = tid & 31, warp = tid >> 5;
    __shared__ float sm[8];
    float v[8];
    float mx = -3.0e38f;
    #pragma unroll
    for (int i=0;i<8;i++){ v[i]=ptr[tid+i*256]; mx=fmaxf(mx,v[i]); }
    #pragma unroll
    for (int o=16;o>0;o>>=1) mx = fmaxf(mx, __shfl_xor_sync(0xffffffffu, mx, o));
    if (lane==0) sm[warp]=mx;
    __syncthreads();
    if (tid==0){ float m=sm[0]; for(int i=1;i<8;i++) m=fmaxf(m,sm[i]); sm[0]=m; }
    __syncthreads();
    mx = sm[0];
    __syncthreads();
    float s=0.f;
    #pragma unroll
    for (int i=0;i<8;i++){ v[i]=expf(v[i]-mx); s+=v[i]; }
    #pragma unroll
    for (int o=16;o>0;o>>=1) s += __shfl_xor_sync(0xffffffffu, s, o);
    if (lane==0) sm[warp]=s;
    __syncthreads();
    if (tid==0){ float t=0; for(int i=1;i<8;i++) t+=sm[i]; sm[0]+=t; }
    __syncthreads();
    float inv = 1.0f/sm[0];
    #pragma unroll
    for (int i=0;i<8;i++){
        float val = v[i]*inv;
        size_t off = row*(size_t)T_SEQ + tid + i*256;
        if (wf32) p[off] = val;
        if (whl) {
            ushort_t h,l;
            split1(val,h,l);
            ph[off]=h; pl[off]=l;
        }
    }
}

// ============================================================================
extern "C" void kernel_launch(void* const* d_in, const int* in_sizes, int n_in,
                              void* d_out, int out_size)
{
    (void)in_sizes; (void)n_in;
    const float* x  = (const float*)d_in[0];
    const float* Wq = (const float*)d_in[1];
    const float* Wk = (const float*)d_in[2];
    const float* Wv = (const float*)d_in[3];
    const float* Wo = (const float*)d_in[4];
    const int* mask = (const int*)d_in[5];
    float* out = (float*)d_out;

    float *gQ, *gK, *gV, *gP;
    ushort_t *xh,*xl,*Wqh,*Wql,*Wkh,*Wkl,*Wvh,*Wvl,*Woh,*Wol;
    ushort_t *Qh,*Ql,*Kh,*Kl,*VTh,*VTl,*Ph,*Pl,*Ahh,*All;
    cudaGetSymbolAddress((void**)&gQ, g_Q);
    cudaGetSymbolAddress((void**)&gK, g_K);
    cudaGetSymbolAddress((void**)&gV, g_V);
    cudaGetSymbolAddress((void**)&gP, g_P);
    cudaGetSymbolAddress((void**)&xh, g_xh);   cudaGetSymbolAddress((void**)&xl, g_xl);
    cudaGetSymbolAddress((void**)&Wqh, g_Wqh); cudaGetSymbolAddress((void**)&Wql, g_Wql);
    cudaGetSymbolAddress((void**)&Wkh, g_Wkh); cudaGetSymbolAddress((void**)&Wkl, g_Wkl);
    cudaGetSymbolAddress((void**)&Wvh, g_Wvh); cudaGetSymbolAddress((void**)&Wvl, g_Wvl);
    cudaGetSymbolAddress((void**)&Woh, g_Woh); cudaGetSymbolAddress((void**)&Wol, g_Wol);
    cudaGetSymbolAddress((void**)&Qh, g_Qh);   cudaGetSymbolAddress((void**)&Ql, g_Ql);
    cudaGetSymbolAddress((void**)&Kh, g_Kh);   cudaGetSymbolAddress((void**)&Kl, g_Kl);
    cudaGetSymbolAddress((void**)&VTh, g_VTh); cudaGetSymbolAddress((void**)&VTl, g_VTl);
    cudaGetSymbolAddress((void**)&Ph, g_Ph);   cudaGetSymbolAddress((void**)&Pl, g_Pl);
    cudaGetSymbolAddress((void**)&Ahh, g_Ah);  cudaGetSymbolAddress((void**)&All, g_Al);

    const long long OUT_N = (long long)T_SEQ * DMODEL;
    const long long ATT_N = (long long)NH * T_SEQ * T_SEQ;
    long long osz = (long long)out_size;
    float* probs; bool need_out; int wf32;
    if (osz >= OUT_N + ATT_N)      { probs = out + OUT_N; need_out = true;  wf32 = 1; }
    else if (osz == ATT_N)         { probs = out;         need_out = false; wf32 = 1; }
    else                           { probs = gP;          need_out = true;  wf32 = 0; }

    // ---- pre-split x and weights ----
    {
        int nx = T_SEQ*DMODEL;
        split_arr<<<nx/4/256, 256>>>(x, xh, xl, nx);
        splitT<<<dim3(DMODEL/32, DMODEL/32), dim3(32,8)>>>(Wq, DMODEL, DMODEL, Wqh, Wql);
        splitT<<<dim3(KVW/32,   DMODEL/32), dim3(32,8)>>>(Wk, DMODEL, KVW, Wkh, Wkl);
        splitT<<<dim3(KVW/32,   DMODEL/32), dim3(32,8)>>>(Wv, DMODEL, KVW, Wvh, Wvl);
        if (need_out)
            splitT<<<dim3(DMODEL/32, DMODEL/32), dim3(32,8)>>>(Wo, DMODEL, DMODEL, Woh, Wol);
    }

    // ---- QKV projections ----
    gemm_tc<<<dim3(DMODEL/128, T_SEQ/128), 256>>>(xh, xl, DMODEL, Wqh, Wql, DMODEL, gQ, DMODEL, DMODEL);
    gemm_tc<<<dim3(KVW/128,   T_SEQ/128), 256>>>(xh, xl, DMODEL, Wkh, Wkl, DMODEL, gK, KVW,   DMODEL);
    gemm_tc<<<dim3(KVW/128,   T_SEQ/128), 256>>>(xh, xl, DMODEL, Wvh, Wvl, DMODEL, gV, KVW,   DMODEL);

    // ---- RoPE + split Q,K ; transpose + split V ----
    {
        int np_q = T_SEQ * (DMODEL/2);
        int np_k = T_SEQ * (KVW/2);
        rope_split<<<(np_q+255)/256, 256>>>(gQ, Qh, Ql, DMODEL, np_q);
        rope_split<<<(np_k+255)/256, 256>>>(gK, Kh, Kl, KVW, np_k);
        if (need_out)
            splitT<<<dim3(KVW/32, T_SEQ/32), dim3(32,8)>>>(gV, T_SEQ, KVW, VTh, VTl);
    }

    // ---- logits + softmax ----
    logits_tc<<<dim3(T_SEQ/128, T_SEQ/128, NH), 256>>>(Qh, Ql, Kh, Kl, mask, probs);
    softmax_split<<<NH*T_SEQ, 256>>>(probs, Ph, Pl, wf32, need_out ? 1 : 0);

    // ---- PV + output projection ----
    if (need_out) {
        pv_tc<<<dim3(1, T_SEQ/128, NH), 256>>>(Ph, Pl, VTh, VTl, Ahh, All);
        gemm_tc<<<dim3(DMODEL/128, T_SEQ/128), 256>>>(Ahh, All, DMODEL, Woh, Wol, DMODEL, out, DMODEL, DMODEL);
    }
}

// round 7
// speedup vs baseline: 2.0850x; 1.1133x over previous
#include <cuda_runtime.h>
#include <cuda_bf16.h>
#include <math.h>

#define T_SEQ 2048
#define DMODEL 2048
#define NH 32
#define NKV 8
#define HD 64
#define KVW (NKV*HD)   // 512
typedef unsigned short ushort_t;

// ---------------- scratch ----------------
__device__ float g_V[(size_t)T_SEQ * KVW];
__device__ float g_P[(size_t)NH * T_SEQ * T_SEQ];          // 512 MB (out-only path)

__device__ __align__(16) ushort_t g_xh[(size_t)T_SEQ*DMODEL],  g_xl[(size_t)T_SEQ*DMODEL];
__device__ __align__(16) ushort_t g_Wqh[(size_t)DMODEL*DMODEL],g_Wql[(size_t)DMODEL*DMODEL];
__device__ __align__(16) ushort_t g_Wkh[(size_t)KVW*DMODEL],   g_Wkl[(size_t)KVW*DMODEL];
__device__ __align__(16) ushort_t g_Wvh[(size_t)KVW*DMODEL],   g_Wvl[(size_t)KVW*DMODEL];
__device__ __align__(16) ushort_t g_Woh[(size_t)DMODEL*DMODEL],g_Wol[(size_t)DMODEL*DMODEL];
__device__ __align__(16) ushort_t g_Qh[(size_t)T_SEQ*DMODEL],  g_Ql[(size_t)T_SEQ*DMODEL];
__device__ __align__(16) ushort_t g_Kh[(size_t)T_SEQ*KVW],     g_Kl[(size_t)T_SEQ*KVW];
__device__ __align__(16) ushort_t g_VTh[(size_t)KVW*T_SEQ],    g_VTl[(size_t)KVW*T_SEQ];
__device__ __align__(16) ushort_t g_Ph[(size_t)NH*T_SEQ*T_SEQ],g_Pl[(size_t)NH*T_SEQ*T_SEQ];
__device__ __align__(16) ushort_t g_Ah[(size_t)T_SEQ*DMODEL],  g_Al[(size_t)T_SEQ*DMODEL];

// ---------------- helpers ----------------
__device__ __forceinline__ void split1(float x, ushort_t &h, ushort_t &l) {
    __nv_bfloat16 hb = __float2bfloat16(x);
    __nv_bfloat16 lb = __float2bfloat16(x - __bfloat162float(hb));
    h = *(ushort_t*)&hb;
    l = *(ushort_t*)&lb;
}

__device__ __forceinline__ void mma16816(float c[4], const unsigned a[4], const unsigned b[2]) {
    asm volatile(
        "mma.sync.aligned.m16n8k16.row.col.f32.bf16.bf16.f32 "
        "{%0,%1,%2,%3},{%4,%5,%6,%7},{%8,%9},{%0,%1,%2,%3};\n"
        : "+f"(c[0]), "+f"(c[1]), "+f"(c[2]), "+f"(c[3])
        : "r"(a[0]), "r"(a[1]), "r"(a[2]), "r"(a[3]), "r"(b[0]), "r"(b[1]));
}

__device__ __forceinline__ void cp16(void* dst, const void* src) {
    unsigned d = (unsigned)__cvta_generic_to_shared(dst);
    asm volatile("cp.async.cg.shared.global [%0], [%1], 16;\n" :: "r"(d), "l"(src));
}
__device__ __forceinline__ void cp_commit() { asm volatile("cp.async.commit_group;\n"); }
__device__ __forceinline__ void cp_wait1()  { asm volatile("cp.async.wait_group 1;\n"); }
__device__ __forceinline__ void cp_wait0()  { asm volatile("cp.async.wait_group 0;\n"); }

__device__ __forceinline__ void ldm4(unsigned r[4], const void* p) {
    unsigned a = (unsigned)__cvta_generic_to_shared(p);
    asm volatile("ldmatrix.sync.aligned.m8n8.x4.shared.b16 {%0,%1,%2,%3},[%4];\n"
        : "=r"(r[0]), "=r"(r[1]), "=r"(r[2]), "=r"(r[3]) : "r"(a));
}

// ============================================================================
// Pipelined bf16-split tensor-core GEMM, BK=32, dynamic smem.
//   A: hi/lo [M][K] (lda), B: hi/lo [N][K] (ldb).
//   EPI 0: fp32 C.    EPI 1: logits (scale + faithful-bug mask).
//   EPI 2: split store to Ch/Cl.    EPI 3: RoPE + split store to Ch/Cl.
// ============================================================================
#define BKK 32
#define PADK 40

template<int BM,int BN,int WM,int WN,int EPI>
__device__ __forceinline__ void mma_core(
    const ushort_t* __restrict__ Ah, const ushort_t* __restrict__ Al, int lda,
    const ushort_t* __restrict__ Bh, const ushort_t* __restrict__ Bl, int ldb,
    float* __restrict__ C, ushort_t* __restrict__ Ch, ushort_t* __restrict__ Cl, int ldc,
    int K, int m0, int n0, const int* __restrict__ mask)
{
    extern __shared__ __align__(16) ushort_t smp[];
    ushort_t* Asm = smp;                       // [2][2][BM][PADK]
    ushort_t* Bsm = smp + 4*BM*PADK;           // [2][2][BN][PADK]

    const int tid  = threadIdx.x;
    const int w    = tid >> 5;
    const int lane = tid & 31;
    constexpr int WROWS = BM / WM;
    const int wm = (w % WROWS) * WM;
    const int wn = (w / WROWS) * WN;
    constexpr int MT = WM / 16;
    constexpr int NT = WN / 8;
    const int g  = lane >> 2;
    const int t4 = lane & 3;
    const int roff = ((lane >> 3) & 1) * 8 + (lane & 7);
    const int coff = (lane >> 4) * 8;

    float acc[MT][NT][4];
    #pragma unroll
    for (int mt=0;mt<MT;mt++)
        #pragma unroll
        for (int nt=0;nt<NT;nt++)
            #pragma unroll
            for (int i=0;i<4;i++) acc[mt][nt][i]=0.f;

    constexpr int ACH = 2*BM*(BKK/8);   // 16B chunks for A (hi+lo)
    constexpr int BCH = 2*BN*(BKK/8);
    constexpr int TC  = ACH + BCH;

    auto stage = [&](int buf, int k0) {
        #pragma unroll
        for (int i = 0; i < TC/256; i++) {
            int q = tid + i*256;
            if (q < ACH) {
                int p = q / (BM*4);
                int rem = q - p*(BM*4);
                int r = rem >> 2, o = (rem & 3) * 8;
                const ushort_t* src = (p ? Al : Ah) + (size_t)(m0+r)*lda + k0 + o;
                cp16(Asm + ((buf*2+p)*BM + r)*PADK + o, src);
            } else {
                int qq = q - ACH;
                int p = qq / (BN*4);
                int rem = qq - p*(BN*4);
                int r = rem >> 2, o = (rem & 3) * 8;
                const ushort_t* src = (p ? Bl : Bh) + (size_t)(n0+r)*ldb + k0 + o;
                cp16(Bsm + ((buf*2+p)*BN + r)*PADK + o, src);
            }
        }
    };

    const int KIT = K / BKK;
    stage(0, 0);
    cp_commit();
    int buf = 0;

    for (int it = 0; it < KIT; it++) {
        if (it + 1 < KIT) {
            stage(buf ^ 1, (it + 1) * BKK);
            cp_commit();
            cp_wait1();
        } else {
            cp_wait0();
        }
        __syncthreads();

        #pragma unroll
        for (int ks = 0; ks < BKK; ks += 16) {
            unsigned ah[MT][4], al[MT][4], bh[NT][2], bl[NT][2];
            #pragma unroll
            for (int mt = 0; mt < MT; mt++) {
                int row = wm + mt*16 + roff;
                ldm4(ah[mt], Asm + ((buf*2+0)*BM + row)*PADK + ks + coff);
                ldm4(al[mt], Asm + ((buf*2+1)*BM + row)*PADK + ks + coff);
            }
            #pragma unroll
            for (int p = 0; p < NT/2; p++) {
                int row = wn + p*16 + roff;
                unsigned t[4];
                ldm4(t, Bsm + ((buf*2+0)*BN + row)*PADK + ks + coff);
                bh[2*p][0]=t[0]; bh[2*p][1]=t[2]; bh[2*p+1][0]=t[1]; bh[2*p+1][1]=t[3];
                ldm4(t, Bsm + ((buf*2+1)*BN + row)*PADK + ks + coff);
                bl[2*p][0]=t[0]; bl[2*p][1]=t[2]; bl[2*p+1][0]=t[1]; bl[2*p+1][1]=t[3];
            }
            #pragma unroll
            for (int mt = 0; mt < MT; mt++)
                #pragma unroll
                for (int nt = 0; nt < NT; nt++) {
                    mma16816(acc[mt][nt], ah[mt], bh[nt]);
                    mma16816(acc[mt][nt], ah[mt], bl[nt]);
                    mma16816(acc[mt][nt], al[mt], bh[nt]);
                }
        }
        __syncthreads();
        buf ^= 1;
    }

    // ---- epilogue ----
    #pragma unroll
    for (int mt = 0; mt < MT; mt++) {
        #pragma unroll
        for (int nt = 0; nt < NT; nt++) {
            int row = m0 + wm + mt*16 + g;
            int col = n0 + wn + nt*8 + t4*2;
            if (EPI == 0) {
                *(float2*)&C[(size_t)row    *ldc + col] = make_float2(acc[mt][nt][0], acc[mt][nt][1]);
                *(float2*)&C[(size_t)(row+8)*ldc + col] = make_float2(acc[mt][nt][2], acc[mt][nt][3]);
            } else if (EPI == 1) {
                int2 m0v = *(const int2*)&mask[(size_t)row    *T_SEQ + col];
                int2 m1v = *(const int2*)&mask[(size_t)(row+8)*T_SEQ + col];
                float s0 = acc[mt][nt][0]*0.125f, s1 = acc[mt][nt][1]*0.125f;
                float s2 = acc[mt][nt][2]*0.125f, s3 = acc[mt][nt][3]*0.125f;
                *(float2*)&C[(size_t)row    *ldc + col] =
                    make_float2(m0v.x ? (s0+s0) : (s0-1e9f), m0v.y ? (s1+s1) : (s1-1e9f));
                *(float2*)&C[(size_t)(row+8)*ldc + col] =
                    make_float2(m1v.x ? (s2+s2) : (s2-1e9f), m1v.y ? (s3+s3) : (s3-1e9f));
            } else if (EPI == 2) {
                ushort_t h0,l0,h1,l1;
                split1(acc[mt][nt][0], h0, l0); split1(acc[mt][nt][1], h1, l1);
                *(unsigned*)&Ch[(size_t)row*ldc + col] = ((unsigned)h1<<16)|h0;
                *(unsigned*)&Cl[(size_t)row*ldc + col] = ((unsigned)l1<<16)|l0;
                split1(acc[mt][nt][2], h0, l0); split1(acc[mt][nt][3], h1, l1);
                *(unsigned*)&Ch[(size_t)(row+8)*ldc + col] = ((unsigned)h1<<16)|h0;
                *(unsigned*)&Cl[(size_t)(row+8)*ldc + col] = ((unsigned)l1<<16)|l0;
            } else {
                // RoPE on pair (col, col+1), then split store
                int j = (col & (HD-1)) >> 1;
                float theta = powf(10000.0f, -(float)(2*j) / 64.0f);
                ushort_t h0,l0,h1,l1;
                float sn, cs;
                sincosf((float)row * theta, &sn, &cs);
                float y1 = acc[mt][nt][0]*cs - acc[mt][nt][1]*sn;
                float y2 = acc[mt][nt][0]*sn + acc[mt][nt][1]*cs;
                split1(y1, h0, l0); split1(y2, h1, l1);
                *(unsigned*)&Ch[(size_t)row*ldc + col] = ((unsigned)h1<<16)|h0;
                *(unsigned*)&Cl[(size_t)row*ldc + col] = ((unsigned)l1<<16)|l0;
                sincosf((float)(row+8) * theta, &sn, &cs);
                y1 = acc[mt][nt][2]*cs - acc[mt][nt][3]*sn;
                y2 = acc[mt][nt][2]*sn + acc[mt][nt][3]*cs;
                split1(y1, h0, l0); split1(y2, h1, l1);
                *(unsigned*)&Ch[(size_t)(row+8)*ldc + col] = ((unsigned)h1<<16)|h0;
                *(unsigned*)&Cl[(size_t)(row+8)*ldc + col] = ((unsigned)l1<<16)|l0;
            }
        }
    }
}

// smem sizes
#define SM_BN128 ((4*128*PADK + 4*128*PADK)*2)   // 81920
#define SM_BN64  ((4*128*PADK + 4*64*PADK)*2)    // 61440

// ---------------- GEMM wrappers ----------------
__global__ void __launch_bounds__(256,2) gemm_tc(
    const ushort_t* Ah, const ushort_t* Al, int lda,
    const ushort_t* Bh, const ushort_t* Bl, int ldb,
    float* C, int ldc, int K)
{
    mma_core<128,128,32,64,0>(Ah,Al,lda,Bh,Bl,ldb,C,nullptr,nullptr,ldc,K,
                              blockIdx.y*128, blockIdx.x*128, nullptr);
}

__global__ void __launch_bounds__(256,2) gemm_rope_tc(
    const ushort_t* Ah, const ushort_t* Al, int lda,
    const ushort_t* Bh, const ushort_t* Bl, int ldb,
    ushort_t* Ch, ushort_t* Cl, int ldc, int K)
{
    mma_core<128,128,32,64,3>(Ah,Al,lda,Bh,Bl,ldb,nullptr,Ch,Cl,ldc,K,
                              blockIdx.y*128, blockIdx.x*128, nullptr);
}

__global__ void __launch_bounds__(256,2) logits_tc(
    const ushort_t* Qh, const ushort_t* Ql,
    const ushort_t* Kh, const ushort_t* Kl,
    const int* mask, float* probs)
{
    int h = blockIdx.z;
    mma_core<128,128,32,64,1>(
        Qh + h*HD, Ql + h*HD, DMODEL,
        Kh + (h>>2)*HD, Kl + (h>>2)*HD, KVW,
        probs + (size_t)h*T_SEQ*T_SEQ, nullptr, nullptr, T_SEQ,
        HD, blockIdx.y*128, blockIdx.x*128, mask);
}

__global__ void __launch_bounds__(256,2) pv_tc(
    const ushort_t* Ph, const ushort_t* Pl,
    const ushort_t* VTh, const ushort_t* VTl,
    ushort_t* Ah, ushort_t* Al)
{
    int h = blockIdx.z;
    mma_core<128,64,32,32,2>(
        Ph + (size_t)h*T_SEQ*T_SEQ, Pl + (size_t)h*T_SEQ*T_SEQ, T_SEQ,
        VTh + (size_t)((h>>2)*HD)*T_SEQ, VTl + (size_t)((h>>2)*HD)*T_SEQ, T_SEQ,
        nullptr, Ah + h*HD, Al + h*HD, DMODEL,
        T_SEQ, blockIdx.y*128, 0, nullptr);
}

// ---------------- pre/post processing ----------------
__global__ void split_arr(const float* __restrict__ in, ushort_t* __restrict__ h,
                          ushort_t* __restrict__ l, int n)
{
    int i = blockIdx.x*blockDim.x + threadIdx.x;
    if (i*4 >= n) return;
    float4 v = *(const float4*)&in[i*4];
    ushort_t hh[4], ll[4];
    split1(v.x,hh[0],ll[0]); split1(v.y,hh[1],ll[1]);
    split1(v.z,hh[2],ll[2]); split1(v.w,hh[3],ll[3]);
    *(ushort2*)&h[i*4]   = make_ushort2(hh[0],hh[1]);
    *(ushort2*)&h[i*4+2] = make_ushort2(hh[2],hh[3]);
    *(ushort2*)&l[i*4]   = make_ushort2(ll[0],ll[1]);
    *(ushort2*)&l[i*4+2] = make_ushort2(ll[2],ll[3]);
}

__global__ void splitT(const float* __restrict__ W, int K, int N,
                       ushort_t* __restrict__ Th, ushort_t* __restrict__ Tl)
{
    __shared__ float t[32][33];
    int k0 = blockIdx.y*32, n0 = blockIdx.x*32;
    for (int i = threadIdx.y; i < 32; i += 8)
        t[i][threadIdx.x] = W[(size_t)(k0+i)*N + n0 + threadIdx.x];
    __syncthreads();
    for (int i = threadIdx.y; i < 32; i += 8) {
        float v = t[threadIdx.x][i];
        ushort_t h, l;
        split1(v, h, l);
        Th[(size_t)(n0+i)*K + k0 + threadIdx.x] = h;
        Tl[(size_t)(n0+i)*K + k0 + threadIdx.x] = l;
    }
}

__global__ void __launch_bounds__(256) softmax_split(
    float* __restrict__ p, ushort_t* __restrict__ ph, ushort_t* __restrict__ pl,
    int wf32, int whl)
{
    size_t row = blockIdx.x;
    float* ptr = p + row*(size_t)T_SEQ;
    int tid = threadIdx.x;
    int lane = tid & 31, warp = tid >> 5;
    __shared__ float sm[8];
    float v[8];
    float mx = -3.0e38f;
    #pragma unroll
    for (int i=0;i<8;i++){ v[i]=ptr[tid+i*256]; mx=fmaxf(mx,v[i]); }
    #pragma unroll
    for (int o=16;o>0;o>>=1) mx = fmaxf(mx, __shfl_xor_sync(0xffffffffu, mx, o));
    if (lane==0) sm[warp]=mx;
    __syncthreads();
    if (tid==0){ float m=sm[0]; for(int i=1;i<8;i++) m=fmaxf(m,sm[i]); sm[0]=m; }
    __syncthreads();
    mx = sm[0];
    __syncthreads();
    float s=0.f;
    #pragma unroll
    for (int i=0;i<8;i++){ v[i]=expf(v[i]-mx); s+=v[i]; }
    #pragma unroll
    for (int o=16;o>0;o>>=1) s += __shfl_xor_sync(0xffffffffu, s, o);
    if (lane==0) sm[warp]=s;
    __syncthreads();
    if (tid==0){ float t=0; for(int i=1;i<8;i++) t+=sm[i]; sm[0]+=t; }
    __syncthreads();
    float inv = 1.0f/sm[0];
    #pragma unroll
    for (int i=0;i<8;i++){
        float val = v[i]*inv;
        size_t off = row*(size_t)T_SEQ + tid + i*256;
        if (wf32) p[off] = val;
        if (whl) {
            ushort_t h,l;
            split1(val,h,l);
            ph[off]=h; pl[off]=l;
        }
    }
}

// ============================================================================
extern "C" void kernel_launch(void* const* d_in, const int* in_sizes, int n_in,
                              void* d_out, int out_size)
{
    (void)in_sizes; (void)n_in;
    const float* x  = (const float*)d_in[0];
    const float* Wq = (const float*)d_in[1];
    const float* Wk = (const float*)d_in[2];
    const float* Wv = (const float*)d_in[3];
    const float* Wo = (const float*)d_in[4];
    const int* mask = (const int*)d_in[5];
    float* out = (float*)d_out;

    float *gV, *gP;
    ushort_t *xh,*xl,*Wqh,*Wql,*Wkh,*Wkl,*Wvh,*Wvl,*Woh,*Wol;
    ushort_t *Qh,*Ql,*Kh,*Kl,*VTh,*VTl,*Ph,*Pl,*Ahh,*All;
    cudaGetSymbolAddress((void**)&gV, g_V);
    cudaGetSymbolAddress((void**)&gP, g_P);
    cudaGetSymbolAddress((void**)&xh, g_xh);   cudaGetSymbolAddress((void**)&xl, g_xl);
    cudaGetSymbolAddress((void**)&Wqh, g_Wqh); cudaGetSymbolAddress((void**)&Wql, g_Wql);
    cudaGetSymbolAddress((void**)&Wkh, g_Wkh); cudaGetSymbolAddress((void**)&Wkl, g_Wkl);
    cudaGetSymbolAddress((void**)&Wvh, g_Wvh); cudaGetSymbolAddress((void**)&Wvl, g_Wvl);
    cudaGetSymbolAddress((void**)&Woh, g_Woh); cudaGetSymbolAddress((void**)&Wol, g_Wol);
    cudaGetSymbolAddress((void**)&Qh, g_Qh);   cudaGetSymbolAddress((void**)&Ql, g_Ql);
    cudaGetSymbolAddress((void**)&Kh, g_Kh);   cudaGetSymbolAddress((void**)&Kl, g_Kl);
    cudaGetSymbolAddress((void**)&VTh, g_VTh); cudaGetSymbolAddress((void**)&VTl, g_VTl);
    cudaGetSymbolAddress((void**)&Ph, g_Ph);   cudaGetSymbolAddress((void**)&Pl, g_Pl);
    cudaGetSymbolAddress((void**)&Ahh, g_Ah);  cudaGetSymbolAddress((void**)&All, g_Al);

    // opt in to >48KB dynamic smem (host-side attribute, idempotent)
    cudaFuncSetAttribute(gemm_tc,      cudaFuncAttributeMaxDynamicSharedMemorySize, SM_BN128);
    cudaFuncSetAttribute(gemm_rope_tc, cudaFuncAttributeMaxDynamicSharedMemorySize, SM_BN128);
    cudaFuncSetAttribute(logits_tc,    cudaFuncAttributeMaxDynamicSharedMemorySize, SM_BN128);
    cudaFuncSetAttribute(pv_tc,        cudaFuncAttributeMaxDynamicSharedMemorySize, SM_BN64);

    const long long OUT_N = (long long)T_SEQ * DMODEL;
    const long long ATT_N = (long long)NH * T_SEQ * T_SEQ;
    long long osz = (long long)out_size;
    float* probs; bool need_out; int wf32;
    if (osz >= OUT_N + ATT_N)      { probs = out + OUT_N; need_out = true;  wf32 = 1; }
    else if (osz == ATT_N)         { probs = out;         need_out = false; wf32 = 1; }
    else                           { probs = gP;          need_out = true;  wf32 = 0; }

    // ---- pre-split x and weights ----
    {
        int nx = T_SEQ*DMODEL;
        split_arr<<<nx/4/256, 256>>>(x, xh, xl, nx);
        splitT<<<dim3(DMODEL/32, DMODEL/32), dim3(32,8)>>>(Wq, DMODEL, DMODEL, Wqh, Wql);
        splitT<<<dim3(KVW/32,   DMODEL/32), dim3(32,8)>>>(Wk, DMODEL, KVW, Wkh, Wkl);
        if (need_out) {
            splitT<<<dim3(KVW/32,   DMODEL/32), dim3(32,8)>>>(Wv, DMODEL, KVW, Wvh, Wvl);
            splitT<<<dim3(DMODEL/32, DMODEL/32), dim3(32,8)>>>(Wo, DMODEL, DMODEL, Woh, Wol);
        }
    }

    // ---- Q/K projections with fused RoPE + split epilogue ----
    gemm_rope_tc<<<dim3(DMODEL/128, T_SEQ/128), 256, SM_BN128>>>(
        xh, xl, DMODEL, Wqh, Wql, DMODEL, Qh, Ql, DMODEL, DMODEL);
    gemm_rope_tc<<<dim3(KVW/128,   T_SEQ/128), 256, SM_BN128>>>(
        xh, xl, DMODEL, Wkh, Wkl, DMODEL, Kh, Kl, KVW, DMODEL);

    // ---- V projection + transpose-split (only if out needed) ----
    if (need_out) {
        gemm_tc<<<dim3(KVW/128, T_SEQ/128), 256, SM_BN128>>>(
            xh, xl, DMODEL, Wvh, Wvl, DMODEL, gV, KVW, DMODEL);
        splitT<<<dim3(KVW/32, T_SEQ/32), dim3(32,8)>>>(gV, T_SEQ, KVW, VTh, VTl);
    }

    // ---- logits + softmax ----
    logits_tc<<<dim3(T_SEQ/128, T_SEQ/128, NH), 256, SM_BN128>>>(Qh, Ql, Kh, Kl, mask, probs);
    softmax_split<<<NH*T_SEQ, 256>>>(probs, Ph, Pl, wf32, need_out ? 1 : 0);

    // ---- PV + output projection ----
    if (need_out) {
        pv_tc<<<dim3(1, T_SEQ/128, NH), 256, SM_BN64>>>(Ph, Pl, VTh, VTl, Ahh, All);
        gemm_tc<<<dim3(DMODEL/128, T_SEQ/128), 256, SM_BN128>>>(
            Ahh, All, DMODEL, Woh, Wol, DMODEL, out, DMODEL, DMODEL);
    }
}

// round 9
// speedup vs baseline: 2.7780x; 1.3324x over previous
#include <cuda_runtime.h>
#include <cuda_fp16.h>
#include <math.h>

#define T_SEQ 2048
#define DMODEL 2048
#define NH 32
#define NKV 8
#define HD 64
#define KVW (NKV*HD)       // 512
#define NQKV (DMODEL+2*KVW) // 3072
typedef unsigned short ushort_t;

// ---------------- scratch ----------------
__device__ float g_P[(size_t)NH * T_SEQ * T_SEQ];            // 512 MB (out-only path)
__device__ __align__(16) ushort_t g_xh[(size_t)T_SEQ*DMODEL],  g_xl[(size_t)T_SEQ*DMODEL];
__device__ __align__(16) ushort_t g_Wcat[(size_t)NQKV*DMODEL];           // fp16, k-major
__device__ __align__(16) ushort_t g_WoT[(size_t)DMODEL*DMODEL];          // fp16, k-major
__device__ __align__(16) ushort_t g_Qh[(size_t)T_SEQ*DMODEL],  g_Ql[(size_t)T_SEQ*DMODEL];
__device__ __align__(16) ushort_t g_Kf[(size_t)T_SEQ*KVW];               // fp16 single
__device__ __align__(16) ushort_t g_VT[(size_t)KVW*T_SEQ];               // fp16 [dim][t]
__device__ __align__(16) ushort_t g_Ph[(size_t)NH*T_SEQ*T_SEQ], g_Pl[(size_t)NH*T_SEQ*T_SEQ];
__device__ __align__(16) ushort_t g_Ah[(size_t)T_SEQ*DMODEL],  g_Al[(size_t)T_SEQ*DMODEL];

// ---------------- helpers ----------------
__device__ __forceinline__ void splitH(float x, ushort_t &h, ushort_t &l) {
    __half hb = __float2half_rn(x);
    __half lb = __float2half_rn(x - __half2float(hb));
    h = *(ushort_t*)&hb;
    l = *(ushort_t*)&lb;
}
__device__ __forceinline__ ushort_t rndH(float x) {
    __half hb = __float2half_rn(x);
    return *(ushort_t*)&hb;
}

__device__ __forceinline__ void mma16816(float c[4], const unsigned a[4], const unsigned b[2]) {
    asm volatile(
        "mma.sync.aligned.m16n8k16.row.col.f32.f16.f16.f32 "
        "{%0,%1,%2,%3},{%4,%5,%6,%7},{%8,%9},{%0,%1,%2,%3};\n"
        : "+f"(c[0]), "+f"(c[1]), "+f"(c[2]), "+f"(c[3])
        : "r"(a[0]), "r"(a[1]), "r"(a[2]), "r"(a[3]), "r"(b[0]), "r"(b[1]));
}

__device__ __forceinline__ void cp16(void* dst, const void* src) {
    unsigned d = (unsigned)__cvta_generic_to_shared(dst);
    asm volatile("cp.async.cg.shared.global [%0], [%1], 16;\n" :: "r"(d), "l"(src));
}
__device__ __forceinline__ void cp_commit() { asm volatile("cp.async.commit_group;\n"); }
__device__ __forceinline__ void cp_wait1()  { asm volatile("cp.async.wait_group 1;\n"); }
__device__ __forceinline__ void cp_wait0()  { asm volatile("cp.async.wait_group 0;\n"); }

__device__ __forceinline__ void ldm4(unsigned r[4], const void* p) {
    unsigned a = (unsigned)__cvta_generic_to_shared(p);
    asm volatile("ldmatrix.sync.aligned.m8n8.x4.shared.b16 {%0,%1,%2,%3},[%4];\n"
        : "=r"(r[0]), "=r"(r[1]), "=r"(r[2]), "=r"(r[3]) : "r"(a));
}

// ============================================================================
// 2-term fp16-split GEMM:  C = (Ah+Al) @ Bh^T,  A hi/lo fp16, B single fp16.
//   EPI 0: fp32 C.   EPI 1: logits (scale + faithful-bug mask).
//   EPI 2: fp16 split store (Ch,Cl).
//   EPI 4: fused QKV epilogue (Q: rope+split; K: rope+round; V: transpose).
// ============================================================================
#define BKK 32
#define PADK 40

template<int BM,int BN,int WM,int WN,int EPI>
__device__ __forceinline__ void mma_core(
    const ushort_t* __restrict__ Ah, const ushort_t* __restrict__ Al, int lda,
    const ushort_t* __restrict__ Bh, int ldb,
    float* __restrict__ C, ushort_t* __restrict__ Ch, ushort_t* __restrict__ Cl, int ldc,
    int K, int m0, int n0, const int* __restrict__ mask,
    ushort_t* __restrict__ Kd, ushort_t* __restrict__ VTd)
{
    extern __shared__ __align__(16) ushort_t smp[];
    ushort_t* Asm = smp;                        // [2][2][BM][PADK]
    ushort_t* Bsm = smp + 4*BM*PADK;            // [2][BN][PADK]

    const int tid  = threadIdx.x;
    const int w    = tid >> 5;
    const int lane = tid & 31;
    constexpr int WROWS = BM / WM;
    const int wm = (w % WROWS) * WM;
    const int wn = (w / WROWS) * WN;
    constexpr int MT = WM / 16;
    constexpr int NT = WN / 8;
    const int g  = lane >> 2;
    const int t4 = lane & 3;
    const int roff = ((lane >> 3) & 1) * 8 + (lane & 7);
    const int coff = (lane >> 4) * 8;

    float acc[MT][NT][4];
    #pragma unroll
    for (int mt=0;mt<MT;mt++)
        #pragma unroll
        for (int nt=0;nt<NT;nt++)
            #pragma unroll
            for (int i=0;i<4;i++) acc[mt][nt][i]=0.f;

    constexpr int ACH = 2*BM*(BKK/8);
    constexpr int BCH = BN*(BKK/8);
    constexpr int TC  = ACH + BCH;

    auto stage = [&](int buf, int k0) {
        #pragma unroll
        for (int i = 0; i < TC/256; i++) {
            int q = tid + i*256;
            if (q < ACH) {
                int p = q / (BM*4);
                int rem = q - p*(BM*4);
                int r = rem >> 2, o = (rem & 3) * 8;
                const ushort_t* src = (p ? Al : Ah) + (size_t)(m0+r)*lda + k0 + o;
                cp16(Asm + ((buf*2+p)*BM + r)*PADK + o, src);
            } else {
                int qq = q - ACH;
                int r = qq >> 2, o = (qq & 3) * 8;
                cp16(Bsm + (buf*BN + r)*PADK + o, Bh + (size_t)(n0+r)*ldb + k0 + o);
            }
        }
    };

    const int KIT = K / BKK;
    stage(0, 0);
    cp_commit();
    int buf = 0;

    for (int it = 0; it < KIT; it++) {
        if (it + 1 < KIT) {
            stage(buf ^ 1, (it + 1) * BKK);
            cp_commit();
            cp_wait1();
        } else {
            cp_wait0();
        }
        __syncthreads();

        #pragma unroll
        for (int ks = 0; ks < BKK; ks += 16) {
            unsigned ah[MT][4], al[MT][4], bh[NT][2];
            #pragma unroll
            for (int mt = 0; mt < MT; mt++) {
                int row = wm + mt*16 + roff;
                ldm4(ah[mt], Asm + ((buf*2+0)*BM + row)*PADK + ks + coff);
                ldm4(al[mt], Asm + ((buf*2+1)*BM + row)*PADK + ks + coff);
            }
            #pragma unroll
            for (int p = 0; p < NT/2; p++) {
                unsigned t[4];
                ldm4(t, Bsm + (buf*BN + wn + p*16 + roff)*PADK + ks + coff);
                bh[2*p][0]=t[0]; bh[2*p][1]=t[2]; bh[2*p+1][0]=t[1]; bh[2*p+1][1]=t[3];
            }
            #pragma unroll
            for (int mt = 0; mt < MT; mt++)
                #pragma unroll
                for (int nt = 0; nt < NT; nt++) {
                    mma16816(acc[mt][nt], ah[mt], bh[nt]);
                    mma16816(acc[mt][nt], al[mt], bh[nt]);
                }
        }
        __syncthreads();
        buf ^= 1;
    }

    // ---- epilogue ----
    #pragma unroll
    for (int mt = 0; mt < MT; mt++) {
        #pragma unroll
        for (int nt = 0; nt < NT; nt++) {
            int row = m0 + wm + mt*16 + g;
            int col = n0 + wn + nt*8 + t4*2;
            float a0 = acc[mt][nt][0], a1 = acc[mt][nt][1];
            float a2 = acc[mt][nt][2], a3 = acc[mt][nt][3];
            if (EPI == 0) {
                *(float2*)&C[(size_t)row    *ldc + col] = make_float2(a0, a1);
                *(float2*)&C[(size_t)(row+8)*ldc + col] = make_float2(a2, a3);
            } else if (EPI == 1) {
                int2 m0v = *(const int2*)&mask[(size_t)row    *T_SEQ + col];
                int2 m1v = *(const int2*)&mask[(size_t)(row+8)*T_SEQ + col];
                float s0 = a0*0.125f, s1 = a1*0.125f, s2 = a2*0.125f, s3 = a3*0.125f;
                *(float2*)&C[(size_t)row    *ldc + col] =
                    make_float2(m0v.x ? (s0+s0) : (s0-1e9f), m0v.y ? (s1+s1) : (s1-1e9f));
                *(float2*)&C[(size_t)(row+8)*ldc + col] =
                    make_float2(m1v.x ? (s2+s2) : (s2-1e9f), m1v.y ? (s3+s3) : (s3-1e9f));
            } else if (EPI == 2) {
                ushort_t h0,l0,h1,l1;
                splitH(a0, h0, l0); splitH(a1, h1, l1);
                *(unsigned*)&Ch[(size_t)row*ldc + col] = ((unsigned)h1<<16)|h0;
                *(unsigned*)&Cl[(size_t)row*ldc + col] = ((unsigned)l1<<16)|l0;
                splitH(a2, h0, l0); splitH(a3, h1, l1);
                *(unsigned*)&Ch[(size_t)(row+8)*ldc + col] = ((unsigned)h1<<16)|h0;
                *(unsigned*)&Cl[(size_t)(row+8)*ldc + col] = ((unsigned)l1<<16)|l0;
            } else {
                // fused QKV epilogue
                if (col < DMODEL) {
                    // Q: rope + split
                    int j = (col & (HD-1)) >> 1;
                    float theta = powf(10000.0f, -(float)(2*j) / 64.0f);
                    float sn, cs;
                    ushort_t h0,l0,h1,l1;
                    sincosf((float)row * theta, &sn, &cs);
                    float y1 = a0*cs - a1*sn, y2 = a0*sn + a1*cs;
                    splitH(y1, h0, l0); splitH(y2, h1, l1);
                    *(unsigned*)&Ch[(size_t)row*DMODEL + col] = ((unsigned)h1<<16)|h0;
                    *(unsigned*)&Cl[(size_t)row*DMODEL + col] = ((unsigned)l1<<16)|l0;
                    sincosf((float)(row+8) * theta, &sn, &cs);
                    y1 = a2*cs - a3*sn; y2 = a2*sn + a3*cs;
                    splitH(y1, h0, l0); splitH(y2, h1, l1);
                    *(unsigned*)&Ch[(size_t)(row+8)*DMODEL + col] = ((unsigned)h1<<16)|h0;
                    *(unsigned*)&Cl[(size_t)(row+8)*DMODEL + col] = ((unsigned)l1<<16)|l0;
                } else if (col < DMODEL + KVW) {
                    // K: rope + fp16 round
                    int c2 = col - DMODEL;
                    int j = (c2 & (HD-1)) >> 1;
                    float theta = powf(10000.0f, -(float)(2*j) / 64.0f);
                    float sn, cs;
                    sincosf((float)row * theta, &sn, &cs);
                    float y1 = a0*cs - a1*sn, y2 = a0*sn + a1*cs;
                    *(unsigned*)&Kd[(size_t)row*KVW + c2] = ((unsigned)rndH(y2)<<16)|rndH(y1);
                    sincosf((float)(row+8) * theta, &sn, &cs);
                    y1 = a2*cs - a3*sn; y2 = a2*sn + a3*cs;
                    *(unsigned*)&Kd[(size_t)(row+8)*KVW + c2] = ((unsigned)rndH(y2)<<16)|rndH(y1);
                } else {
                    // V: transpose into VT[dim][t], fp16
                    int c2 = col - (DMODEL + KVW);
                    VTd[(size_t)c2    *T_SEQ + row]   = rndH(a0);
                    VTd[(size_t)(c2+1)*T_SEQ + row]   = rndH(a1);
                    VTd[(size_t)c2    *T_SEQ + row+8] = rndH(a2);
                    VTd[(size_t)(c2+1)*T_SEQ + row+8] = rndH(a3);
                }
            }
        }
    }
}

#define SM_BN128 ((4*128*PADK + 2*128*PADK)*2)   // 61440
#define SM_BN64  ((4*128*PADK + 2*64*PADK)*2)    // 51200

// ---------------- GEMM wrappers ----------------
__global__ void __launch_bounds__(256,2) qkv_tc(
    const ushort_t* xh, const ushort_t* xl, const ushort_t* Wcat,
    ushort_t* Qh, ushort_t* Ql, ushort_t* Kd, ushort_t* VTd)
{
    mma_core<128,128,32,64,4>(xh, xl, DMODEL, Wcat, DMODEL,
                              nullptr, Qh, Ql, DMODEL, DMODEL,
                              blockIdx.y*128, blockIdx.x*128, nullptr, Kd, VTd);
}

__global__ void __launch_bounds__(256,2) gemm_tc(
    const ushort_t* Ah, const ushort_t* Al, int lda,
    const ushort_t* Bh, int ldb, float* C, int ldc, int K)
{
    mma_core<128,128,32,64,0>(Ah,Al,lda,Bh,ldb,C,nullptr,nullptr,ldc,K,
                              blockIdx.y*128, blockIdx.x*128, nullptr, nullptr, nullptr);
}

__global__ void __launch_bounds__(256,2) logits_tc(
    const ushort_t* Qh, const ushort_t* Ql, const ushort_t* Kf,
    const int* mask, float* probs)
{
    int h = blockIdx.z;
    mma_core<128,128,32,64,1>(
        Qh + h*HD, Ql + h*HD, DMODEL,
        Kf + (h>>2)*HD, KVW,
        probs + (size_t)h*T_SEQ*T_SEQ, nullptr, nullptr, T_SEQ,
        HD, blockIdx.y*128, blockIdx.x*128, mask, nullptr, nullptr);
}

__global__ void __launch_bounds__(256,2) pv_tc(
    const ushort_t* Ph, const ushort_t* Pl, const ushort_t* VT,
    ushort_t* Ah, ushort_t* Al)
{
    int h = blockIdx.z;
    mma_core<128,64,32,32,2>(
        Ph + (size_t)h*T_SEQ*T_SEQ, Pl + (size_t)h*T_SEQ*T_SEQ, T_SEQ,
        VT + (size_t)((h>>2)*HD)*T_SEQ, T_SEQ,
        nullptr, Ah + h*HD, Al + h*HD, DMODEL,
        T_SEQ, blockIdx.y*128, 0, nullptr, nullptr, nullptr);
}

// ---------------- pre/post processing ----------------
__global__ void split_x(const float* __restrict__ in, ushort_t* __restrict__ h,
                        ushort_t* __restrict__ l, int n)
{
    int i = blockIdx.x*blockDim.x + threadIdx.x;
    if (i*4 >= n) return;
    float4 v = *(const float4*)&in[i*4];
    ushort_t hh[4], ll[4];
    splitH(v.x,hh[0],ll[0]); splitH(v.y,hh[1],ll[1]);
    splitH(v.z,hh[2],ll[2]); splitH(v.w,hh[3],ll[3]);
    *(ushort2*)&h[i*4]   = make_ushort2(hh[0],hh[1]);
    *(ushort2*)&h[i*4+2] = make_ushort2(hh[2],hh[3]);
    *(ushort2*)&l[i*4]   = make_ushort2(ll[0],ll[1]);
    *(ushort2*)&l[i*4+2] = make_ushort2(ll[2],ll[3]);
}

// W [K][N] fp32 -> T_[(rowOff+n)*2048 + k] fp16
__global__ void splitWT(const float* __restrict__ W, int K, int N,
                        ushort_t* __restrict__ T_, int rowOff)
{
    __shared__ float t[32][33];
    int k0 = blockIdx.y*32, n0 = blockIdx.x*32;
    for (int i = threadIdx.y; i < 32; i += 8)
        t[i][threadIdx.x] = W[(size_t)(k0+i)*N + n0 + threadIdx.x];
    __syncthreads();
    for (int i = threadIdx.y; i < 32; i += 8)
        T_[(size_t)(rowOff+n0+i)*DMODEL + k0 + threadIdx.x] = rndH(t[threadIdx.x][i]);
}

__global__ void __launch_bounds__(256) softmax_split(
    float* __restrict__ p, ushort_t* __restrict__ ph, ushort_t* __restrict__ pl,
    int wf32, int whl)
{
    size_t row = blockIdx.x;
    float* ptr = p + row*(size_t)T_SEQ;
    int tid = threadIdx.x;
    int lane = tid & 31, warp = tid >> 5;
    __shared__ float sm[8];
    float v[8];
    float mx = -3.0e38f;
    #pragma unroll
    for (int i=0;i<8;i++){ v[i]=ptr[tid+i*256]; mx=fmaxf(mx,v[i]); }
    #pragma unroll
    for (int o=16;o>0;o>>=1) mx = fmaxf(mx, __shfl_xor_sync(0xffffffffu, mx, o));
    if (lane==0) sm[warp]=mx;
    __syncthreads();
    if (tid==0){ float m=sm[0]; for(int i=1;i<8;i++) m=fmaxf(m,sm[i]); sm[0]=m; }
    __syncthreads();
    mx = sm[0];
    __syncthreads();
    float s=0.f;
    #pragma unroll
    for (int i=0;i<8;i++){ v[i]=expf(v[i]-mx); s+=v[i]; }
    #pragma unroll
    for (int o=16;o>0;o>>=1) s += __shfl_xor_sync(0xffffffffu, s, o);
    if (lane==0) sm[warp]=s;
    __syncthreads();
    if (tid==0){ float t=0; for(int i=1;i<8;i++) t+=sm[i]; sm[0]+=t; }
    __syncthreads();
    float inv = 1.0f/sm[0];
    #pragma unroll
    for (int i=0;i<8;i++){
        float val = v[i]*inv;
        size_t off = row*(size_t)T_SEQ + tid + i*256;
        if (wf32) p[off] = val;
        if (whl) {
            ushort_t h,l;
            splitH(val,h,l);
            ph[off]=h; pl[off]=l;
        }
    }
}

// ============================================================================
extern "C" void kernel_launch(void* const* d_in, const int* in_sizes, int n_in,
                              void* d_out, int out_size)
{
    (void)in_sizes; (void)n_in;
    const float* x  = (const float*)d_in[0];
    const float* Wq = (const float*)d_in[1];
    const float* Wk = (const float*)d_in[2];
    const float* Wv = (const float*)d_in[3];
    const float* Wo = (const float*)d_in[4];
    const int* mask = (const int*)d_in[5];
    float* out = (float*)d_out;

    float *gP;
    ushort_t *xh,*xl,*Wcat,*WoT,*Qh,*Ql,*Kf,*VT,*Ph,*Pl,*Ahh,*All;
    cudaGetSymbolAddress((void**)&gP,  g_P);
    cudaGetSymbolAddress((void**)&xh,  g_xh);   cudaGetSymbolAddress((void**)&xl,  g_xl);
    cudaGetSymbolAddress((void**)&Wcat,g_Wcat); cudaGetSymbolAddress((void**)&WoT, g_WoT);
    cudaGetSymbolAddress((void**)&Qh,  g_Qh);   cudaGetSymbolAddress((void**)&Ql,  g_Ql);
    cudaGetSymbolAddress((void**)&Kf,  g_Kf);   cudaGetSymbolAddress((void**)&VT,  g_VT);
    cudaGetSymbolAddress((void**)&Ph,  g_Ph);   cudaGetSymbolAddress((void**)&Pl,  g_Pl);
    cudaGetSymbolAddress((void**)&Ahh, g_Ah);   cudaGetSymbolAddress((void**)&All, g_Al);

    cudaFuncSetAttribute(qkv_tc,    cudaFuncAttributeMaxDynamicSharedMemorySize, SM_BN128);
    cudaFuncSetAttribute(gemm_tc,   cudaFuncAttributeMaxDynamicSharedMemorySize, SM_BN128);
    cudaFuncSetAttribute(logits_tc, cudaFuncAttributeMaxDynamicSharedMemorySize, SM_BN128);
    cudaFuncSetAttribute(pv_tc,     cudaFuncAttributeMaxDynamicSharedMemorySize, SM_BN64);

    const long long OUT_N = (long long)T_SEQ * DMODEL;
    const long long ATT_N = (long long)NH * T_SEQ * T_SEQ;
    long long osz = (long long)out_size;
    float* probs; bool need_out; int wf32;
    if (osz >= OUT_N + ATT_N)      { probs = out + OUT_N; need_out = true;  wf32 = 1; }
    else if (osz == ATT_N)         { probs = out;         need_out = false; wf32 = 1; }
    else                           { probs = gP;          need_out = true;  wf32 = 0; }

    // ---- pre-split x; transpose+round weights into concat fp16 ----
    {
        int nx = T_SEQ*DMODEL;
        split_x<<<nx/4/256, 256>>>(x, xh, xl, nx);
        splitWT<<<dim3(DMODEL/32, DMODEL/32), dim3(32,8)>>>(Wq, DMODEL, DMODEL, Wcat, 0);
        splitWT<<<dim3(KVW/32,    DMODEL/32), dim3(32,8)>>>(Wk, DMODEL, KVW, Wcat, DMODEL);
        splitWT<<<dim3(KVW/32,    DMODEL/32), dim3(32,8)>>>(Wv, DMODEL, KVW, Wcat, DMODEL+KVW);
        if (need_out)
            splitWT<<<dim3(DMODEL/32, DMODEL/32), dim3(32,8)>>>(Wo, DMODEL, DMODEL, WoT, 0);
    }

    // ---- fused QKV projection (rope+split Q, rope K, transpose V in epilogue) ----
    qkv_tc<<<dim3(NQKV/128, T_SEQ/128), 256, SM_BN128>>>(xh, xl, Wcat, Qh, Ql, Kf, VT);

    // ---- logits + softmax ----
    logits_tc<<<dim3(T_SEQ/128, T_SEQ/128, NH), 256, SM_BN128>>>(Qh, Ql, Kf, mask, probs);
    softmax_split<<<NH*T_SEQ, 256>>>(probs, Ph, Pl, wf32, need_out ? 1 : 0);

    // ---- PV + output projection ----
    if (need_out) {
        pv_tc<<<dim3(1, T_SEQ/128, NH), 256, SM_BN64>>>(Ph, Pl, VT, Ahh, All);
        gemm_tc<<<dim3(DMODEL/128, T_SEQ/128), 256, SM_BN128>>>(
            Ahh, All, DMODEL, WoT, DMODEL, out, DMODEL, DMODEL);
    }
}

// round 11
// speedup vs baseline: 2.9394x; 1.0581x over previous
#include <cuda_runtime.h>
#include <cuda_fp16.h>
#include <math.h>

#define T_SEQ 2048
#define DMODEL 2048
#define NH 32
#define NKV 8
#define HD 64
#define KVW (NKV*HD)       // 512
#define NQKV (DMODEL+2*KVW) // 3072
typedef unsigned short ushort_t;

// ---------------- scratch ----------------
__device__ float g_P[(size_t)NH * T_SEQ * T_SEQ];            // 512 MB (out-only path)
__device__ __align__(16) ushort_t g_xh[(size_t)T_SEQ*DMODEL],  g_xl[(size_t)T_SEQ*DMODEL];
__device__ __align__(16) ushort_t g_Wcat[(size_t)NQKV*DMODEL];           // fp16, k-major
__device__ __align__(16) ushort_t g_WoT[(size_t)DMODEL*DMODEL];          // fp16, k-major
__device__ __align__(16) ushort_t g_Qh[(size_t)T_SEQ*DMODEL],  g_Ql[(size_t)T_SEQ*DMODEL];
__device__ __align__(16) ushort_t g_Kf[(size_t)T_SEQ*KVW];               // fp16 single
__device__ __align__(16) ushort_t g_VT[(size_t)KVW*T_SEQ];               // fp16 [dim][t]
__device__ __align__(16) ushort_t g_Ah[(size_t)T_SEQ*DMODEL],  g_Al[(size_t)T_SEQ*DMODEL];

// ---------------- helpers ----------------
__device__ __forceinline__ void splitH(float x, ushort_t &h, ushort_t &l) {
    __half hb = __float2half_rn(x);
    __half lb = __float2half_rn(x - __half2float(hb));
    h = *(ushort_t*)&hb;
    l = *(ushort_t*)&lb;
}
__device__ __forceinline__ ushort_t rndH(float x) {
    __half hb = __float2half_rn(x);
    return *(ushort_t*)&hb;
}

__device__ __forceinline__ void mma16816(float c[4], const unsigned a[4], const unsigned b[2]) {
    asm volatile(
        "mma.sync.aligned.m16n8k16.row.col.f32.f16.f16.f32 "
        "{%0,%1,%2,%3},{%4,%5,%6,%7},{%8,%9},{%0,%1,%2,%3};\n"
        : "+f"(c[0]), "+f"(c[1]), "+f"(c[2]), "+f"(c[3])
        : "r"(a[0]), "r"(a[1]), "r"(a[2]), "r"(a[3]), "r"(b[0]), "r"(b[1]));
}

__device__ __forceinline__ void cp16(void* dst, const void* src) {
    unsigned d = (unsigned)__cvta_generic_to_shared(dst);
    asm volatile("cp.async.cg.shared.global [%0], [%1], 16;\n" :: "r"(d), "l"(src));
}
__device__ __forceinline__ void cp_commit() { asm volatile("cp.async.commit_group;\n"); }
__device__ __forceinline__ void cp_wait1()  { asm volatile("cp.async.wait_group 1;\n"); }
__device__ __forceinline__ void cp_wait0()  { asm volatile("cp.async.wait_group 0;\n"); }

__device__ __forceinline__ void ldm4(unsigned r[4], const void* p) {
    unsigned a = (unsigned)__cvta_generic_to_shared(p);
    asm volatile("ldmatrix.sync.aligned.m8n8.x4.shared.b16 {%0,%1,%2,%3},[%4];\n"
        : "=r"(r[0]), "=r"(r[1]), "=r"(r[2]), "=r"(r[3]) : "r"(a));
}

// ============================================================================
// 2-term fp16-split GEMM:  C = (Ah+Al) @ Bh^T.
//   EPI 0: fp32 C.   EPI 1: logits (scale + faithful-bug mask).
//   EPI 4: fused QKV epilogue (Q: rope+split; K: rope+round; V: transpose).
// ============================================================================
#define BKK 32
#define PADK 40

template<int BM,int BN,int WM,int WN,int EPI>
__device__ __forceinline__ void mma_core(
    const ushort_t* __restrict__ Ah, const ushort_t* __restrict__ Al, int lda,
    const ushort_t* __restrict__ Bh, int ldb,
    float* __restrict__ C, ushort_t* __restrict__ Ch, ushort_t* __restrict__ Cl, int ldc,
    int K, int m0, int n0, const int* __restrict__ mask,
    ushort_t* __restrict__ Kd, ushort_t* __restrict__ VTd)
{
    extern __shared__ __align__(16) ushort_t smp[];
    ushort_t* Asm = smp;                        // [2][2][BM][PADK]
    ushort_t* Bsm = smp + 4*BM*PADK;            // [2][BN][PADK]

    const int tid  = threadIdx.x;
    const int w    = tid >> 5;
    const int lane = tid & 31;
    constexpr int WROWS = BM / WM;
    const int wm = (w % WROWS) * WM;
    const int wn = (w / WROWS) * WN;
    constexpr int MT = WM / 16;
    constexpr int NT = WN / 8;
    const int g  = lane >> 2;
    const int t4 = lane & 3;
    const int roff = ((lane >> 3) & 1) * 8 + (lane & 7);
    const int coff = (lane >> 4) * 8;

    float acc[MT][NT][4];
    #pragma unroll
    for (int mt=0;mt<MT;mt++)
        #pragma unroll
        for (int nt=0;nt<NT;nt++)
            #pragma unroll
            for (int i=0;i<4;i++) acc[mt][nt][i]=0.f;

    constexpr int ACH = 2*BM*(BKK/8);
    constexpr int BCH = BN*(BKK/8);
    constexpr int TC  = ACH + BCH;

    auto stage = [&](int buf, int k0) {
        #pragma unroll
        for (int i = 0; i < TC/256; i++) {
            int q = tid + i*256;
            if (q < ACH) {
                int p = q / (BM*4);
                int rem = q - p*(BM*4);
                int r = rem >> 2, o = (rem & 3) * 8;
                const ushort_t* src = (p ? Al : Ah) + (size_t)(m0+r)*lda + k0 + o;
                cp16(Asm + ((buf*2+p)*BM + r)*PADK + o, src);
            } else {
                int qq = q - ACH;
                int r = qq >> 2, o = (qq & 3) * 8;
                cp16(Bsm + (buf*BN + r)*PADK + o, Bh + (size_t)(n0+r)*ldb + k0 + o);
            }
        }
    };

    const int KIT = K / BKK;
    stage(0, 0);
    cp_commit();
    int buf = 0;

    for (int it = 0; it < KIT; it++) {
        if (it + 1 < KIT) {
            stage(buf ^ 1, (it + 1) * BKK);
            cp_commit();
            cp_wait1();
        } else {
            cp_wait0();
        }
        __syncthreads();

        #pragma unroll
        for (int ks = 0; ks < BKK; ks += 16) {
            unsigned ah[MT][4], al[MT][4], bh[NT][2];
            #pragma unroll
            for (int mt = 0; mt < MT; mt++) {
                int row = wm + mt*16 + roff;
                ldm4(ah[mt], Asm + ((buf*2+0)*BM + row)*PADK + ks + coff);
                ldm4(al[mt], Asm + ((buf*2+1)*BM + row)*PADK + ks + coff);
            }
            #pragma unroll
            for (int p = 0; p < NT/2; p++) {
                unsigned t[4];
                ldm4(t, Bsm + (buf*BN + wn + p*16 + roff)*PADK + ks + coff);
                bh[2*p][0]=t[0]; bh[2*p][1]=t[2]; bh[2*p+1][0]=t[1]; bh[2*p+1][1]=t[3];
            }
            #pragma unroll
            for (int mt = 0; mt < MT; mt++)
                #pragma unroll
                for (int nt = 0; nt < NT; nt++) {
                    mma16816(acc[mt][nt], ah[mt], bh[nt]);
                    mma16816(acc[mt][nt], al[mt], bh[nt]);
                }
        }
        __syncthreads();
        buf ^= 1;
    }

    // ---- epilogue ----
    #pragma unroll
    for (int mt = 0; mt < MT; mt++) {
        #pragma unroll
        for (int nt = 0; nt < NT; nt++) {
            int row = m0 + wm + mt*16 + g;
            int col = n0 + wn + nt*8 + t4*2;
            float a0 = acc[mt][nt][0], a1 = acc[mt][nt][1];
            float a2 = acc[mt][nt][2], a3 = acc[mt][nt][3];
            if (EPI == 0) {
                *(float2*)&C[(size_t)row    *ldc + col] = make_float2(a0, a1);
                *(float2*)&C[(size_t)(row+8)*ldc + col] = make_float2(a2, a3);
            } else if (EPI == 1) {
                int2 m0v = *(const int2*)&mask[(size_t)row    *T_SEQ + col];
                int2 m1v = *(const int2*)&mask[(size_t)(row+8)*T_SEQ + col];
                float s0 = a0*0.125f, s1 = a1*0.125f, s2 = a2*0.125f, s3 = a3*0.125f;
                *(float2*)&C[(size_t)row    *ldc + col] =
                    make_float2(m0v.x ? (s0+s0) : (s0-1e9f), m0v.y ? (s1+s1) : (s1-1e9f));
                *(float2*)&C[(size_t)(row+8)*ldc + col] =
                    make_float2(m1v.x ? (s2+s2) : (s2-1e9f), m1v.y ? (s3+s3) : (s3-1e9f));
            } else {
                // fused QKV epilogue
                if (col < DMODEL) {
                    int j = (col & (HD-1)) >> 1;
                    float theta = powf(10000.0f, -(float)(2*j) / 64.0f);
                    float sn, cs;
                    ushort_t h0,l0,h1,l1;
                    sincosf((float)row * theta, &sn, &cs);
                    float y1 = a0*cs - a1*sn, y2 = a0*sn + a1*cs;
                    splitH(y1, h0, l0); splitH(y2, h1, l1);
                    *(unsigned*)&Ch[(size_t)row*DMODEL + col] = ((unsigned)h1<<16)|h0;
                    *(unsigned*)&Cl[(size_t)row*DMODEL + col] = ((unsigned)l1<<16)|l0;
                    sincosf((float)(row+8) * theta, &sn, &cs);
                    y1 = a2*cs - a3*sn; y2 = a2*sn + a3*cs;
                    splitH(y1, h0, l0); splitH(y2, h1, l1);
                    *(unsigned*)&Ch[(size_t)(row+8)*DMODEL + col] = ((unsigned)h1<<16)|h0;
                    *(unsigned*)&Cl[(size_t)(row+8)*DMODEL + col] = ((unsigned)l1<<16)|l0;
                } else if (col < DMODEL + KVW) {
                    int c2 = col - DMODEL;
                    int j = (c2 & (HD-1)) >> 1;
                    float theta = powf(10000.0f, -(float)(2*j) / 64.0f);
                    float sn, cs;
                    sincosf((float)row * theta, &sn, &cs);
                    float y1 = a0*cs - a1*sn, y2 = a0*sn + a1*cs;
                    *(unsigned*)&Kd[(size_t)row*KVW + c2] = ((unsigned)rndH(y2)<<16)|rndH(y1);
                    sincosf((float)(row+8) * theta, &sn, &cs);
                    y1 = a2*cs - a3*sn; y2 = a2*sn + a3*cs;
                    *(unsigned*)&Kd[(size_t)(row+8)*KVW + c2] = ((unsigned)rndH(y2)<<16)|rndH(y1);
                } else {
                    int c2 = col - (DMODEL + KVW);
                    VTd[(size_t)c2    *T_SEQ + row]   = rndH(a0);
                    VTd[(size_t)(c2+1)*T_SEQ + row]   = rndH(a1);
                    VTd[(size_t)c2    *T_SEQ + row+8] = rndH(a2);
                    VTd[(size_t)(c2+1)*T_SEQ + row+8] = rndH(a3);
                }
            }
        }
    }
}

#define SM_BN128 ((4*128*PADK + 2*128*PADK)*2)   // 61440

// ---------------- GEMM wrappers ----------------
__global__ void __launch_bounds__(256,2) qkv_tc(
    const ushort_t* xh, const ushort_t* xl, const ushort_t* Wcat,
    ushort_t* Qh, ushort_t* Ql, ushort_t* Kd, ushort_t* VTd)
{
    mma_core<128,128,32,64,4>(xh, xl, DMODEL, Wcat, DMODEL,
                              nullptr, Qh, Ql, DMODEL, DMODEL,
                              blockIdx.y*128, blockIdx.x*128, nullptr, Kd, VTd);
}

__global__ void __launch_bounds__(256,2) gemm_tc(
    const ushort_t* Ah, const ushort_t* Al, int lda,
    const ushort_t* Bh, int ldb, float* C, int ldc, int K)
{
    mma_core<128,128,32,64,0>(Ah,Al,lda,Bh,ldb,C,nullptr,nullptr,ldc,K,
                              blockIdx.y*128, blockIdx.x*128, nullptr, nullptr, nullptr);
}

__global__ void __launch_bounds__(256,2) logits_tc(
    const ushort_t* Qh, const ushort_t* Ql, const ushort_t* Kf,
    const int* mask, float* probs)
{
    int h = blockIdx.z;
    mma_core<128,128,32,64,1>(
        Qh + h*HD, Ql + h*HD, DMODEL,
        Kf + (h>>2)*HD, KVW,
        probs + (size_t)h*T_SEQ*T_SEQ, nullptr, nullptr, T_SEQ,
        HD, blockIdx.y*128, blockIdx.x*128, mask, nullptr, nullptr);
}

// ============================================================================
// PV kernel: A = fp32 probs (staged + converted to hi/lo fp16 in smem),
//            B = fp16 V^T. Split-fp16 output to Ah/Al.
//   BM=128, BN=64, WM=32, WN=32, 8 warps.
// ============================================================================
#define PV_AF_PAD 36
#define SM_PV (4*128*PADK*2 + 2*64*PADK*2 + 2*128*PV_AF_PAD*4)  // 40960+10240+36864 = 88064

__global__ void __launch_bounds__(256,2) pv_tc(
    const float* __restrict__ P, const ushort_t* __restrict__ VT,
    ushort_t* __restrict__ Ah, ushort_t* __restrict__ Al)
{
    const int h = blockIdx.z;
    const float* Pp = P + (size_t)h*T_SEQ*T_SEQ;
    const ushort_t* Vp = VT + (size_t)((h>>2)*HD)*T_SEQ;
    ushort_t* Chp = Ah + h*HD;
    ushort_t* Clp = Al + h*HD;
    const int m0 = blockIdx.y*128;

    extern __shared__ __align__(16) char smb[];
    ushort_t* Asm = (ushort_t*)smb;                      // [2][2][128][PADK]
    ushort_t* Bsm = (ushort_t*)(smb + 4*128*PADK*2);     // [2][64][PADK]
    float*    Afm = (float*)(smb + 4*128*PADK*2 + 2*64*PADK*2);  // [2][128][36]

    const int tid  = threadIdx.x;
    const int w    = tid >> 5;
    const int lane = tid & 31;
    const int wm = (w % 4) * 32;
    const int wn = (w / 4) * 32;
    const int g  = lane >> 2;
    const int t4 = lane & 3;
    const int roff = ((lane >> 3) & 1) * 8 + (lane & 7);
    const int coff = (lane >> 4) * 8;

    float acc[2][4][4];
    #pragma unroll
    for (int mt=0;mt<2;mt++)
        #pragma unroll
        for (int nt=0;nt<4;nt++)
            #pragma unroll
            for (int i=0;i<4;i++) acc[mt][nt][i]=0.f;

    // 1024 A chunks (fp32 128x32) + 256 B chunks = 1280 -> 5/thread
    auto stage = [&](int buf, int k0) {
        #pragma unroll
        for (int i = 0; i < 5; i++) {
            int q = tid + i*256;
            if (q < 1024) {
                int r = q >> 3, o = (q & 7) * 4;
                cp16(Afm + (buf*128 + r)*PV_AF_PAD + o, Pp + (size_t)(m0+r)*T_SEQ + k0 + o);
            } else {
                int qq = q - 1024;
                int r = qq >> 2, o = (qq & 3) * 8;
                cp16(Bsm + (buf*64 + r)*PADK + o, Vp + (size_t)r*T_SEQ + k0 + o);
            }
        }
    };

    const int KIT = T_SEQ / BKK;  // 64
    stage(0, 0);
    cp_commit();
    int buf = 0;

    const int cr = tid >> 1;
    const int cc = (tid & 1) * 16;

    for (int it = 0; it < KIT; it++) {
        if (it + 1 < KIT) {
            stage(buf ^ 1, (it + 1) * BKK);
            cp_commit();
            cp_wait1();
        } else {
            cp_wait0();
        }
        __syncthreads();

        // convert fp32 -> hi/lo fp16 (each element exactly once)
        {
            const float* src = Afm + (buf*128 + cr)*PV_AF_PAD + cc;
            ushort_t* dh = Asm + ((buf*2+0)*128 + cr)*PADK + cc;
            ushort_t* dl = Asm + ((buf*2+1)*128 + cr)*PADK + cc;
            #pragma unroll
            for (int j = 0; j < 16; j += 4) {
                float4 v = *(const float4*)(src + j);
                ushort_t h0,l0,h1,l1,h2,l2,h3,l3;
                splitH(v.x,h0,l0); splitH(v.y,h1,l1);
                splitH(v.z,h2,l2); splitH(v.w,h3,l3);
                *(unsigned*)(dh + j)     = ((unsigned)h1<<16)|h0;
                *(unsigned*)(dh + j + 2) = ((unsigned)h3<<16)|h2;
                *(unsigned*)(dl + j)     = ((unsigned)l1<<16)|l0;
                *(unsigned*)(dl + j + 2) = ((unsigned)l3<<16)|l2;
            }
        }
        __syncthreads();

        #pragma unroll
        for (int ks = 0; ks < BKK; ks += 16) {
            unsigned ah[2][4], al[2][4], bh[4][2];
            #pragma unroll
            for (int mt = 0; mt < 2; mt++) {
                int row = wm + mt*16 + roff;
                ldm4(ah[mt], Asm + ((buf*2+0)*128 + row)*PADK + ks + coff);
                ldm4(al[mt], Asm + ((buf*2+1)*128 + row)*PADK + ks + coff);
            }
            #pragma unroll
            for (int p = 0; p < 2; p++) {
                unsigned t[4];
                ldm4(t, Bsm + (buf*64 + wn + p*16 + roff)*PADK + ks + coff);
                bh[2*p][0]=t[0]; bh[2*p][1]=t[2]; bh[2*p+1][0]=t[1]; bh[2*p+1][1]=t[3];
            }
            #pragma unroll
            for (int mt = 0; mt < 2; mt++)
                #pragma unroll
                for (int nt = 0; nt < 4; nt++) {
                    mma16816(acc[mt][nt], ah[mt], bh[nt]);
                    mma16816(acc[mt][nt], al[mt], bh[nt]);
                }
        }
        __syncthreads();
        buf ^= 1;
    }

    #pragma unroll
    for (int mt = 0; mt < 2; mt++) {
        #pragma unroll
        for (int nt = 0; nt < 4; nt++) {
            int row = m0 + wm + mt*16 + g;
            int col = wn + nt*8 + t4*2;
            ushort_t h0,l0,h1,l1;
            splitH(acc[mt][nt][0], h0, l0); splitH(acc[mt][nt][1], h1, l1);
            *(unsigned*)&Chp[(size_t)row*DMODEL + col] = ((unsigned)h1<<16)|h0;
            *(unsigned*)&Clp[(size_t)row*DMODEL + col] = ((unsigned)l1<<16)|l0;
            splitH(acc[mt][nt][2], h0, l0); splitH(acc[mt][nt][3], h1, l1);
            *(unsigned*)&Chp[(size_t)(row+8)*DMODEL + col] = ((unsigned)h1<<16)|h0;
            *(unsigned*)&Clp[(size_t)(row+8)*DMODEL + col] = ((unsigned)l1<<16)|l0;
        }
    }
}

// ---------------- pre/post processing ----------------
__global__ void split_x(const float* __restrict__ in, ushort_t* __restrict__ h,
                        ushort_t* __restrict__ l, int n)
{
    int i = blockIdx.x*blockDim.x + threadIdx.x;
    if (i*4 >= n) return;
    float4 v = *(const float4*)&in[i*4];
    ushort_t hh[4], ll[4];
    splitH(v.x,hh[0],ll[0]); splitH(v.y,hh[1],ll[1]);
    splitH(v.z,hh[2],ll[2]); splitH(v.w,hh[3],ll[3]);
    *(ushort2*)&h[i*4]   = make_ushort2(hh[0],hh[1]);
    *(ushort2*)&h[i*4+2] = make_ushort2(hh[2],hh[3]);
    *(ushort2*)&l[i*4]   = make_ushort2(ll[0],ll[1]);
    *(ushort2*)&l[i*4+2] = make_ushort2(ll[2],ll[3]);
}

__global__ void splitWT(const float* __restrict__ W, int K, int N,
                        ushort_t* __restrict__ T_, int rowOff)
{
    __shared__ float t[32][33];
    int k0 = blockIdx.y*32, n0 = blockIdx.x*32;
    for (int i = threadIdx.y; i < 32; i += 8)
        t[i][threadIdx.x] = W[(size_t)(k0+i)*N + n0 + threadIdx.x];
    __syncthreads();
    for (int i = threadIdx.y; i < 32; i += 8)
        T_[(size_t)(rowOff+n0+i)*DMODEL + k0 + threadIdx.x] = rndH(t[threadIdx.x][i]);
}

// fp32 in-place row softmax, vectorized
__global__ void __launch_bounds__(256) softmax_kernel(float* __restrict__ p)
{
    size_t row = blockIdx.x;
    float* ptr = p + row*(size_t)T_SEQ;
    int tid = threadIdx.x;
    int lane = tid & 31, warp = tid >> 5;
    __shared__ float sm[8];
    float4 va = *(float4*)&ptr[tid*4];
    float4 vb = *(float4*)&ptr[tid*4 + 1024];
    float mx = fmaxf(fmaxf(fmaxf(va.x,va.y),fmaxf(va.z,va.w)),
                     fmaxf(fmaxf(vb.x,vb.y),fmaxf(vb.z,vb.w)));
    #pragma unroll
    for (int o=16;o>0;o>>=1) mx = fmaxf(mx, __shfl_xor_sync(0xffffffffu, mx, o));
    if (lane==0) sm[warp]=mx;
    __syncthreads();
    if (tid==0){ float m=sm[0]; for(int i=1;i<8;i++) m=fmaxf(m,sm[i]); sm[0]=m; }
    __syncthreads();
    mx = sm[0];
    __syncthreads();
    va.x=expf(va.x-mx); va.y=expf(va.y-mx); va.z=expf(va.z-mx); va.w=expf(va.w-mx);
    vb.x=expf(vb.x-mx); vb.y=expf(vb.y-mx); vb.z=expf(vb.z-mx); vb.w=expf(vb.w-mx);
    float s = (va.x+va.y)+(va.z+va.w)+(vb.x+vb.y)+(vb.z+vb.w);
    #pragma unroll
    for (int o=16;o>0;o>>=1) s += __shfl_xor_sync(0xffffffffu, s, o);
    if (lane==0) sm[warp]=s;
    __syncthreads();
    if (tid==0){ float t=0; for(int i=1;i<8;i++) t+=sm[i]; sm[0]+=t; }
    __syncthreads();
    float inv = 1.0f/sm[0];
    va.x*=inv; va.y*=inv; va.z*=inv; va.w*=inv;
    vb.x*=inv; vb.y*=inv; vb.z*=inv; vb.w*=inv;
    *(float4*)&ptr[tid*4]        = va;
    *(float4*)&ptr[tid*4 + 1024] = vb;
}

// ============================================================================
extern "C" void kernel_launch(void* const* d_in, const int* in_sizes, int n_in,
                              void* d_out, int out_size)
{
    (void)in_sizes; (void)n_in;
    const float* x  = (const float*)d_in[0];
    const float* Wq = (const float*)d_in[1];
    const float* Wk = (const float*)d_in[2];
    const float* Wv = (const float*)d_in[3];
    const float* Wo = (const float*)d_in[4];
    const int* mask = (const int*)d_in[5];
    float* out = (float*)d_out;

    float *gP;
    ushort_t *xh,*xl,*Wcat,*WoT,*Qh,*Ql,*Kf,*VT,*Ahh,*All;
    cudaGetSymbolAddress((void**)&gP,  g_P);
    cudaGetSymbolAddress((void**)&xh,  g_xh);   cudaGetSymbolAddress((void**)&xl,  g_xl);
    cudaGetSymbolAddress((void**)&Wcat,g_Wcat); cudaGetSymbolAddress((void**)&WoT, g_WoT);
    cudaGetSymbolAddress((void**)&Qh,  g_Qh);   cudaGetSymbolAddress((void**)&Ql,  g_Ql);
    cudaGetSymbolAddress((void**)&Kf,  g_Kf);   cudaGetSymbolAddress((void**)&VT,  g_VT);
    cudaGetSymbolAddress((void**)&Ahh, g_Ah);   cudaGetSymbolAddress((void**)&All, g_Al);

    cudaFuncSetAttribute(qkv_tc,    cudaFuncAttributeMaxDynamicSharedMemorySize, SM_BN128);
    cudaFuncSetAttribute(gemm_tc,   cudaFuncAttributeMaxDynamicSharedMemorySize, SM_BN128);
    cudaFuncSetAttribute(logits_tc, cudaFuncAttributeMaxDynamicSharedMemorySize, SM_BN128);
    cudaFuncSetAttribute(pv_tc,     cudaFuncAttributeMaxDynamicSharedMemorySize, SM_PV);

    const long long OUT_N = (long long)T_SEQ * DMODEL;
    const long long ATT_N = (long long)NH * T_SEQ * T_SEQ;
    long long osz = (long long)out_size;
    float* probs; bool need_out;
    if (osz >= OUT_N + ATT_N)      { probs = out + OUT_N; need_out = true;  }
    else if (osz == ATT_N)         { probs = out;         need_out = false; }
    else                           { probs = gP;          need_out = true;  }

    // ---- pre-split x; transpose+round weights into concat fp16 ----
    {
        int nx = T_SEQ*DMODEL;
        split_x<<<nx/4/256, 256>>>(x, xh, xl, nx);
        splitWT<<<dim3(DMODEL/32, DMODEL/32), dim3(32,8)>>>(Wq, DMODEL, DMODEL, Wcat, 0);
        splitWT<<<dim3(KVW/32,    DMODEL/32), dim3(32,8)>>>(Wk, DMODEL, KVW, Wcat, DMODEL);
        splitWT<<<dim3(KVW/32,    DMODEL/32), dim3(32,8)>>>(Wv, DMODEL, KVW, Wcat, DMODEL+KVW);
        if (need_out)
            splitWT<<<dim3(DMODEL/32, DMODEL/32), dim3(32,8)>>>(Wo, DMODEL, DMODEL, WoT, 0);
    }

    // ---- fused QKV projection (rope+split Q, rope K, transpose V in epilogue) ----
    qkv_tc<<<dim3(NQKV/128, T_SEQ/128), 256, SM_BN128>>>(xh, xl, Wcat, Qh, Ql, Kf, VT);

    // ---- logits + softmax (fp32 probs only; no split copies) ----
    logits_tc<<<dim3(T_SEQ/128, T_SEQ/128, NH), 256, SM_BN128>>>(Qh, Ql, Kf, mask, probs);
    softmax_kernel<<<NH*T_SEQ, 256>>>(probs);

    // ---- PV (reads fp32 probs, converts in-kernel) + output projection ----
    if (need_out) {
        pv_tc<<<dim3(1, T_SEQ/128, NH), 256, SM_PV>>>(probs, VT, Ahh, All);
        gemm_tc<<<dim3(DMODEL/128, T_SEQ/128), 256, SM_BN128>>>(
            Ahh, All, DMODEL, WoT, DMODEL, out, DMODEL, DMODEL);
    }
}

// round 13
// speedup vs baseline: 2.9400x; 1.0002x over previous
#include <cuda_runtime.h>
#include <cuda_fp16.h>
#include <math.h>

#define T_SEQ 2048
#define DMODEL 2048
#define NH 32
#define NKV 8
#define HD 64
#define KVW (NKV*HD)       // 512
#define NQKV (DMODEL+2*KVW) // 3072
typedef unsigned short ushort_t;

// ---------------- scratch ----------------
__device__ float g_P[(size_t)NH * T_SEQ * T_SEQ];            // 512 MB (attn-materialized paths)
__device__ __align__(16) ushort_t g_xh[(size_t)T_SEQ*DMODEL],  g_xl[(size_t)T_SEQ*DMODEL];
__device__ __align__(16) ushort_t g_Wcat[(size_t)NQKV*DMODEL];
__device__ __align__(16) ushort_t g_WoT[(size_t)DMODEL*DMODEL];
__device__ __align__(16) ushort_t g_Qh[(size_t)T_SEQ*DMODEL],  g_Ql[(size_t)T_SEQ*DMODEL];
__device__ __align__(16) ushort_t g_Kf[(size_t)T_SEQ*KVW];
__device__ __align__(16) ushort_t g_VT[(size_t)KVW*T_SEQ];
__device__ __align__(16) ushort_t g_Ah[(size_t)T_SEQ*DMODEL],  g_Al[(size_t)T_SEQ*DMODEL];

// ---------------- helpers ----------------
__device__ __forceinline__ void splitH(float x, ushort_t &h, ushort_t &l) {
    __half hb = __float2half_rn(x);
    __half lb = __float2half_rn(x - __half2float(hb));
    h = *(ushort_t*)&hb;
    l = *(ushort_t*)&lb;
}
__device__ __forceinline__ ushort_t rndH(float x) {
    __half hb = __float2half_rn(x);
    return *(ushort_t*)&hb;
}
__device__ __forceinline__ unsigned packH2(float a, float b) {
    return ((unsigned)rndH(b) << 16) | rndH(a);
}
__device__ __forceinline__ void splitPack(float a, float b, unsigned &hi, unsigned &lo) {
    ushort_t ha,la,hb2,lb2;
    splitH(a, ha, la); splitH(b, hb2, lb2);
    hi = ((unsigned)hb2<<16)|ha;
    lo = ((unsigned)lb2<<16)|la;
}

__device__ __forceinline__ void mma16816(float c[4], const unsigned a[4], const unsigned b[2]) {
    asm volatile(
        "mma.sync.aligned.m16n8k16.row.col.f32.f16.f16.f32 "
        "{%0,%1,%2,%3},{%4,%5,%6,%7},{%8,%9},{%0,%1,%2,%3};\n"
        : "+f"(c[0]), "+f"(c[1]), "+f"(c[2]), "+f"(c[3])
        : "r"(a[0]), "r"(a[1]), "r"(a[2]), "r"(a[3]), "r"(b[0]), "r"(b[1]));
}

__device__ __forceinline__ void cp16(void* dst, const void* src) {
    unsigned d = (unsigned)__cvta_generic_to_shared(dst);
    asm volatile("cp.async.cg.shared.global [%0], [%1], 16;\n" :: "r"(d), "l"(src));
}
__device__ __forceinline__ void cp_commit() { asm volatile("cp.async.commit_group;\n"); }
__device__ __forceinline__ void cp_wait1()  { asm volatile("cp.async.wait_group 1;\n"); }
__device__ __forceinline__ void cp_wait0()  { asm volatile("cp.async.wait_group 0;\n"); }

__device__ __forceinline__ void ldm4(unsigned r[4], const void* p) {
    unsigned a = (unsigned)__cvta_generic_to_shared(p);
    asm volatile("ldmatrix.sync.aligned.m8n8.x4.shared.b16 {%0,%1,%2,%3},[%4];\n"
        : "=r"(r[0]), "=r"(r[1]), "=r"(r[2]), "=r"(r[3]) : "r"(a));
}

// ============================================================================
// 2-term fp16-split GEMM (materialized paths + projections)
// ============================================================================
#define BKK 32
#define PADK 40

template<int BM,int BN,int WM,int WN,int EPI>
__device__ __forceinline__ void mma_core(
    const ushort_t* __restrict__ Ah, const ushort_t* __restrict__ Al, int lda,
    const ushort_t* __restrict__ Bh, int ldb,
    float* __restrict__ C, ushort_t* __restrict__ Ch, ushort_t* __restrict__ Cl, int ldc,
    int K, int m0, int n0, const int* __restrict__ mask,
    ushort_t* __restrict__ Kd, ushort_t* __restrict__ VTd)
{
    extern __shared__ __align__(16) ushort_t smp[];
    ushort_t* Asm = smp;
    ushort_t* Bsm = smp + 4*BM*PADK;

    const int tid  = threadIdx.x;
    const int w    = tid >> 5;
    const int lane = tid & 31;
    constexpr int WROWS = BM / WM;
    const int wm = (w % WROWS) * WM;
    const int wn = (w / WROWS) * WN;
    constexpr int MT = WM / 16;
    constexpr int NT = WN / 8;
    const int g  = lane >> 2;
    const int t4 = lane & 3;
    const int roff = ((lane >> 3) & 1) * 8 + (lane & 7);
    const int coff = (lane >> 4) * 8;

    float acc[MT][NT][4];
    #pragma unroll
    for (int mt=0;mt<MT;mt++)
        #pragma unroll
        for (int nt=0;nt<NT;nt++)
            #pragma unroll
            for (int i=0;i<4;i++) acc[mt][nt][i]=0.f;

    constexpr int ACH = 2*BM*(BKK/8);
    constexpr int BCH = BN*(BKK/8);
    constexpr int TC  = ACH + BCH;

    auto stage = [&](int buf, int k0) {
        #pragma unroll
        for (int i = 0; i < TC/256; i++) {
            int q = tid + i*256;
            if (q < ACH) {
                int p = q / (BM*4);
                int rem = q - p*(BM*4);
                int r = rem >> 2, o = (rem & 3) * 8;
                const ushort_t* src = (p ? Al : Ah) + (size_t)(m0+r)*lda + k0 + o;
                cp16(Asm + ((buf*2+p)*BM + r)*PADK + o, src);
            } else {
                int qq = q - ACH;
                int r = qq >> 2, o = (qq & 3) * 8;
                cp16(Bsm + (buf*BN + r)*PADK + o, Bh + (size_t)(n0+r)*ldb + k0 + o);
            }
        }
    };

    const int KIT = K / BKK;
    stage(0, 0);
    cp_commit();
    int buf = 0;

    for (int it = 0; it < KIT; it++) {
        if (it + 1 < KIT) {
            stage(buf ^ 1, (it + 1) * BKK);
            cp_commit();
            cp_wait1();
        } else {
            cp_wait0();
        }
        __syncthreads();

        #pragma unroll
        for (int ks = 0; ks < BKK; ks += 16) {
            unsigned ah[MT][4], al[MT][4], bh[NT][2];
            #pragma unroll
            for (int mt = 0; mt < MT; mt++) {
                int row = wm + mt*16 + roff;
                ldm4(ah[mt], Asm + ((buf*2+0)*BM + row)*PADK + ks + coff);
                ldm4(al[mt], Asm + ((buf*2+1)*BM + row)*PADK + ks + coff);
            }
            #pragma unroll
            for (int p = 0; p < NT/2; p++) {
                unsigned t[4];
                ldm4(t, Bsm + (buf*BN + wn + p*16 + roff)*PADK + ks + coff);
                bh[2*p][0]=t[0]; bh[2*p][1]=t[2]; bh[2*p+1][0]=t[1]; bh[2*p+1][1]=t[3];
            }
            #pragma unroll
            for (int mt = 0; mt < MT; mt++)
                #pragma unroll
                for (int nt = 0; nt < NT; nt++) {
                    mma16816(acc[mt][nt], ah[mt], bh[nt]);
                    mma16816(acc[mt][nt], al[mt], bh[nt]);
                }
        }
        __syncthreads();
        buf ^= 1;
    }

    #pragma unroll
    for (int mt = 0; mt < MT; mt++) {
        #pragma unroll
        for (int nt = 0; nt < NT; nt++) {
            int row = m0 + wm + mt*16 + g;
            int col = n0 + wn + nt*8 + t4*2;
            float a0 = acc[mt][nt][0], a1 = acc[mt][nt][1];
            float a2 = acc[mt][nt][2], a3 = acc[mt][nt][3];
            if (EPI == 0) {
                *(float2*)&C[(size_t)row    *ldc + col] = make_float2(a0, a1);
                *(float2*)&C[(size_t)(row+8)*ldc + col] = make_float2(a2, a3);
            } else if (EPI == 1) {
                int2 m0v = *(const int2*)&mask[(size_t)row    *T_SEQ + col];
                int2 m1v = *(const int2*)&mask[(size_t)(row+8)*T_SEQ + col];
                float s0 = a0*0.125f, s1 = a1*0.125f, s2 = a2*0.125f, s3 = a3*0.125f;
                *(float2*)&C[(size_t)row    *ldc + col] =
                    make_float2(m0v.x ? (s0+s0) : (s0-1e9f), m0v.y ? (s1+s1) : (s1-1e9f));
                *(float2*)&C[(size_t)(row+8)*ldc + col] =
                    make_float2(m1v.x ? (s2+s2) : (s2-1e9f), m1v.y ? (s3+s3) : (s3-1e9f));
            } else {
                if (col < DMODEL) {
                    int j = (col & (HD-1)) >> 1;
                    float theta = powf(10000.0f, -(float)(2*j) / 64.0f);
                    float sn, cs;
                    unsigned hi, lo;
                    sincosf((float)row * theta, &sn, &cs);
                    splitPack(a0*cs - a1*sn, a0*sn + a1*cs, hi, lo);
                    *(unsigned*)&Ch[(size_t)row*DMODEL + col] = hi;
                    *(unsigned*)&Cl[(size_t)row*DMODEL + col] = lo;
                    sincosf((float)(row+8) * theta, &sn, &cs);
                    splitPack(a2*cs - a3*sn, a2*sn + a3*cs, hi, lo);
                    *(unsigned*)&Ch[(size_t)(row+8)*DMODEL + col] = hi;
                    *(unsigned*)&Cl[(size_t)(row+8)*DMODEL + col] = lo;
                } else if (col < DMODEL + KVW) {
                    int c2 = col - DMODEL;
                    int j = (c2 & (HD-1)) >> 1;
                    float theta = powf(10000.0f, -(float)(2*j) / 64.0f);
                    float sn, cs;
                    sincosf((float)row * theta, &sn, &cs);
                    *(unsigned*)&Kd[(size_t)row*KVW + c2] = packH2(a0*cs - a1*sn, a0*sn + a1*cs);
                    sincosf((float)(row+8) * theta, &sn, &cs);
                    *(unsigned*)&Kd[(size_t)(row+8)*KVW + c2] = packH2(a2*cs - a3*sn, a2*sn + a3*cs);
                } else {
                    int c2 = col - (DMODEL + KVW);
                    VTd[(size_t)c2    *T_SEQ + row]   = rndH(a0);
                    VTd[(size_t)(c2+1)*T_SEQ + row]   = rndH(a1);
                    VTd[(size_t)c2    *T_SEQ + row+8] = rndH(a2);
                    VTd[(size_t)(c2+1)*T_SEQ + row+8] = rndH(a3);
                }
            }
        }
    }
}

#define SM_BN128 ((4*128*PADK + 2*128*PADK)*2)   // 61440

__global__ void __launch_bounds__(256,2) qkv_tc(
    const ushort_t* xh, const ushort_t* xl, const ushort_t* Wcat,
    ushort_t* Qh, ushort_t* Ql, ushort_t* Kd, ushort_t* VTd)
{
    mma_core<128,128,32,64,4>(xh, xl, DMODEL, Wcat, DMODEL,
                              nullptr, Qh, Ql, DMODEL, DMODEL,
                              blockIdx.y*128, blockIdx.x*128, nullptr, Kd, VTd);
}

__global__ void __launch_bounds__(256,2) gemm_tc(
    const ushort_t* Ah, const ushort_t* Al, int lda,
    const ushort_t* Bh, int ldb, float* C, int ldc, int K)
{
    mma_core<128,128,32,64,0>(Ah,Al,lda,Bh,ldb,C,nullptr,nullptr,ldc,K,
                              blockIdx.y*128, blockIdx.x*128, nullptr, nullptr, nullptr);
}

__global__ void __launch_bounds__(256,2) logits_tc(
    const ushort_t* Qh, const ushort_t* Ql, const ushort_t* Kf,
    const int* mask, float* probs)
{
    int h = blockIdx.z;
    mma_core<128,128,32,64,1>(
        Qh + h*HD, Ql + h*HD, DMODEL,
        Kf + (h>>2)*HD, KVW,
        probs + (size_t)h*T_SEQ*T_SEQ, nullptr, nullptr, T_SEQ,
        HD, blockIdx.y*128, blockIdx.x*128, mask, nullptr, nullptr);
}

// ============================================================================
// PV kernel (materialized branches): fp32 probs -> split in smem -> mma
// ============================================================================
#define PV_AF_PAD 36
#define SM_PV (4*128*PADK*2 + 2*64*PADK*2 + 2*128*PV_AF_PAD*4)

__global__ void __launch_bounds__(256,2) pv_tc(
    const float* __restrict__ P, const ushort_t* __restrict__ VT,
    ushort_t* __restrict__ Ah, ushort_t* __restrict__ Al)
{
    const int h = blockIdx.z;
    const float* Pp = P + (size_t)h*T_SEQ*T_SEQ;
    const ushort_t* Vp = VT + (size_t)((h>>2)*HD)*T_SEQ;
    ushort_t* Chp = Ah + h*HD;
    ushort_t* Clp = Al + h*HD;
    const int m0 = blockIdx.y*128;

    extern __shared__ __align__(16) char smb[];
    ushort_t* Asm = (ushort_t*)smb;
    ushort_t* Bsm = (ushort_t*)(smb + 4*128*PADK*2);
    float*    Afm = (float*)(smb + 4*128*PADK*2 + 2*64*PADK*2);

    const int tid  = threadIdx.x;
    const int w    = tid >> 5;
    const int lane = tid & 31;
    const int wm = (w % 4) * 32;
    const int wn = (w / 4) * 32;
    const int g  = lane >> 2;
    const int t4 = lane & 3;
    const int roff = ((lane >> 3) & 1) * 8 + (lane & 7);
    const int coff = (lane >> 4) * 8;

    float acc[2][4][4];
    #pragma unroll
    for (int mt=0;mt<2;mt++)
        #pragma unroll
        for (int nt=0;nt<4;nt++)
            #pragma unroll
            for (int i=0;i<4;i++) acc[mt][nt][i]=0.f;

    auto stage = [&](int buf, int k0) {
        #pragma unroll
        for (int i = 0; i < 5; i++) {
            int q = tid + i*256;
            if (q < 1024) {
                int r = q >> 3, o = (q & 7) * 4;
                cp16(Afm + (buf*128 + r)*PV_AF_PAD + o, Pp + (size_t)(m0+r)*T_SEQ + k0 + o);
            } else {
                int qq = q - 1024;
                int r = qq >> 2, o = (qq & 3) * 8;
                cp16(Bsm + (buf*64 + r)*PADK + o, Vp + (size_t)r*T_SEQ + k0 + o);
            }
        }
    };

    const int KIT = T_SEQ / BKK;
    stage(0, 0);
    cp_commit();
    int buf = 0;
    const int cr = tid >> 1;
    const int cc = (tid & 1) * 16;

    for (int it = 0; it < KIT; it++) {
        if (it + 1 < KIT) { stage(buf ^ 1, (it + 1) * BKK); cp_commit(); cp_wait1(); }
        else { cp_wait0(); }
        __syncthreads();
        {
            const float* src = Afm + (buf*128 + cr)*PV_AF_PAD + cc;
            ushort_t* dh = Asm + ((buf*2+0)*128 + cr)*PADK + cc;
            ushort_t* dl = Asm + ((buf*2+1)*128 + cr)*PADK + cc;
            #pragma unroll
            for (int j = 0; j < 16; j += 4) {
                float4 v = *(const float4*)(src + j);
                unsigned hi0, lo0, hi1, lo1;
                splitPack(v.x, v.y, hi0, lo0);
                splitPack(v.z, v.w, hi1, lo1);
                *(unsigned*)(dh + j)     = hi0;
                *(unsigned*)(dh + j + 2) = hi1;
                *(unsigned*)(dl + j)     = lo0;
                *(unsigned*)(dl + j + 2) = lo1;
            }
        }
        __syncthreads();

        #pragma unroll
        for (int ks = 0; ks < BKK; ks += 16) {
            unsigned ah[2][4], al[2][4], bh[4][2];
            #pragma unroll
            for (int mt = 0; mt < 2; mt++) {
                int row = wm + mt*16 + roff;
                ldm4(ah[mt], Asm + ((buf*2+0)*128 + row)*PADK + ks + coff);
                ldm4(al[mt], Asm + ((buf*2+1)*128 + row)*PADK + ks + coff);
            }
            #pragma unroll
            for (int p = 0; p < 2; p++) {
                unsigned t[4];
                ldm4(t, Bsm + (buf*64 + wn + p*16 + roff)*PADK + ks + coff);
                bh[2*p][0]=t[0]; bh[2*p][1]=t[2]; bh[2*p+1][0]=t[1]; bh[2*p+1][1]=t[3];
            }
            #pragma unroll
            for (int mt = 0; mt < 2; mt++)
                #pragma unroll
                for (int nt = 0; nt < 4; nt++) {
                    mma16816(acc[mt][nt], ah[mt], bh[nt]);
                    mma16816(acc[mt][nt], al[mt], bh[nt]);
                }
        }
        __syncthreads();
        buf ^= 1;
    }

    #pragma unroll
    for (int mt = 0; mt < 2; mt++) {
        #pragma unroll
        for (int nt = 0; nt < 4; nt++) {
            int row = m0 + wm + mt*16 + g;
            int col = wn + nt*8 + t4*2;
            unsigned hi, lo;
            splitPack(acc[mt][nt][0], acc[mt][nt][1], hi, lo);
            *(unsigned*)&Chp[(size_t)row*DMODEL + col] = hi;
            *(unsigned*)&Clp[(size_t)row*DMODEL + col] = lo;
            splitPack(acc[mt][nt][2], acc[mt][nt][3], hi, lo);
            *(unsigned*)&Chp[(size_t)(row+8)*DMODEL + col] = hi;
            *(unsigned*)&Clp[(size_t)(row+8)*DMODEL + col] = lo;
        }
    }
}

// ============================================================================
// FLASH attention kernel (out-only path). CTA = (q-tile 128, head).
// Streams 64-key K/V tiles; P stays in registers (FA2 fragment reuse).
// ============================================================================
#define FPAD 72
#define SM_FLASH ((2*128*FPAD + 2*64*FPAD + 2*64*FPAD)*2)  // 73728

__global__ void __launch_bounds__(256,2) flash_tc(
    const ushort_t* __restrict__ Qh, const ushort_t* __restrict__ Ql,
    const ushort_t* __restrict__ Kf, const ushort_t* __restrict__ VT,
    const int* __restrict__ mask,
    ushort_t* __restrict__ Ahh, ushort_t* __restrict__ All)
{
    const int h  = blockIdx.y, kv = h >> 2;
    const int q0 = blockIdx.x * 128;

    extern __shared__ __align__(16) ushort_t fsm[];
    ushort_t* Qs = fsm;                          // [2][128][FPAD]  hi/lo
    ushort_t* Ks = fsm + 2*128*FPAD;             // [2][64][FPAD]   dbuf
    ushort_t* Vs = Ks  + 2*64*FPAD;              // [2][64][FPAD]   dbuf

    const int tid  = threadIdx.x;
    const int w    = tid >> 5;
    const int lane = tid & 31;
    const int g  = lane >> 2;
    const int t4 = lane & 3;
    const int roff = ((lane >> 3) & 1) * 8 + (lane & 7);
    const int coff = (lane >> 4) * 8;
    const int wq = w * 16;                        // warp q rows [wq, wq+16)

    // stage Q (hi/lo) once: 2048 chunks
    #pragma unroll
    for (int i = 0; i < 8; i++) {
        int q = tid + i*256;
        int p = q >> 10, rem = q & 1023;
        int r = rem >> 3, o = (rem & 7) * 8;
        cp16(Qs + (p*128 + r)*FPAD + o, (p ? Ql : Qh) + (size_t)(q0+r)*DMODEL + h*HD + o);
    }
    auto stageKV = [&](int buf, int kt) {
        #pragma unroll
        for (int i = 0; i < 4; i++) {
            int q = tid + i*256;
            int p = q >> 9, rem = q & 511;
            int r = rem >> 3, o = (rem & 7) * 8;
            if (p == 0)
                cp16(Ks + (buf*64 + r)*FPAD + o, Kf + (size_t)(kt*64+r)*KVW + kv*HD + o);
            else
                cp16(Vs + (buf*64 + r)*FPAD + o, VT + (size_t)(kv*HD + r)*T_SEQ + kt*64 + o);
        }
    };
    stageKV(0, 0);
    cp_commit();
    int buf = 0;

    float oacc[8][4];
    #pragma unroll
    for (int nt=0;nt<8;nt++)
        #pragma unroll
        for (int i=0;i<4;i++) oacc[nt][i]=0.f;
    float mrow[2] = {-3.0e38f, -3.0e38f};
    float lrow[2] = {0.f, 0.f};

    const int NKT = T_SEQ / 64;  // 32
    for (int kt = 0; kt < NKT; kt++) {
        if (kt + 1 < NKT) { stageKV(buf ^ 1, kt + 1); cp_commit(); cp_wait1(); }
        else { cp_wait0(); }
        __syncthreads();

        // ---- S = (Qh+Ql) @ K^T ----
        float sacc[8][4];
        #pragma unroll
        for (int nt=0;nt<8;nt++)
            #pragma unroll
            for (int i=0;i<4;i++) sacc[nt][i]=0.f;
        #pragma unroll
        for (int kb = 0; kb < 4; kb++) {
            unsigned qh4[4], ql4[4], bh[8][2];
            ldm4(qh4, Qs + (0*128 + wq + roff)*FPAD + kb*16 + coff);
            ldm4(ql4, Qs + (1*128 + wq + roff)*FPAD + kb*16 + coff);
            #pragma unroll
            for (int p = 0; p < 4; p++) {
                unsigned t[4];
                ldm4(t, Ks + (buf*64 + p*16 + roff)*FPAD + kb*16 + coff);
                bh[2*p][0]=t[0]; bh[2*p][1]=t[2]; bh[2*p+1][0]=t[1]; bh[2*p+1][1]=t[3];
            }
            #pragma unroll
            for (int nt = 0; nt < 8; nt++) {
                mma16816(sacc[nt], qh4, bh[nt]);
                mma16816(sacc[nt], ql4, bh[nt]);
            }
        }

        // ---- scale + faithful-bug mask; row max ----
        const int gq = q0 + wq + g;
        float rmax0 = -3.0e38f, rmax1 = -3.0e38f;
        #pragma unroll
        for (int nt = 0; nt < 8; nt++) {
            int col = kt*64 + nt*8 + t4*2;
            int2 mv0 = *(const int2*)&mask[(size_t)gq    *T_SEQ + col];
            int2 mv1 = *(const int2*)&mask[(size_t)(gq+8)*T_SEQ + col];
            float s0 = sacc[nt][0]*0.125f, s1 = sacc[nt][1]*0.125f;
            float s2 = sacc[nt][2]*0.125f, s3 = sacc[nt][3]*0.125f;
            s0 = mv0.x ? (s0+s0) : (s0-1e9f);
            s1 = mv0.y ? (s1+s1) : (s1-1e9f);
            s2 = mv1.x ? (s2+s2) : (s2-1e9f);
            s3 = mv1.y ? (s3+s3) : (s3-1e9f);
            sacc[nt][0]=s0; sacc[nt][1]=s1; sacc[nt][2]=s2; sacc[nt][3]=s3;
            rmax0 = fmaxf(rmax0, fmaxf(s0, s1));
            rmax1 = fmaxf(rmax1, fmaxf(s2, s3));
        }
        #pragma unroll
        for (int o = 1; o <= 2; o <<= 1) {
            rmax0 = fmaxf(rmax0, __shfl_xor_sync(0xffffffffu, rmax0, o));
            rmax1 = fmaxf(rmax1, __shfl_xor_sync(0xffffffffu, rmax1, o));
        }
        float mnew0 = fmaxf(mrow[0], rmax0);
        float mnew1 = fmaxf(mrow[1], rmax1);
        float alpha0 = expf(mrow[0] - mnew0);
        float alpha1 = expf(mrow[1] - mnew1);
        mrow[0] = mnew0; mrow[1] = mnew1;

        // ---- exp, row sum ----
        float rsum0 = 0.f, rsum1 = 0.f;
        #pragma unroll
        for (int nt = 0; nt < 8; nt++) {
            float p0 = expf(sacc[nt][0] - mnew0);
            float p1 = expf(sacc[nt][1] - mnew0);
            float p2 = expf(sacc[nt][2] - mnew1);
            float p3 = expf(sacc[nt][3] - mnew1);
            sacc[nt][0]=p0; sacc[nt][1]=p1; sacc[nt][2]=p2; sacc[nt][3]=p3;
            rsum0 += p0 + p1; rsum1 += p2 + p3;
        }
        #pragma unroll
        for (int o = 1; o <= 2; o <<= 1) {
            rsum0 += __shfl_xor_sync(0xffffffffu, rsum0, o);
            rsum1 += __shfl_xor_sync(0xffffffffu, rsum1, o);
        }
        lrow[0] = lrow[0]*alpha0 + rsum0;
        lrow[1] = lrow[1]*alpha1 + rsum1;

        // ---- rescale O ----
        #pragma unroll
        for (int nt = 0; nt < 8; nt++) {
            oacc[nt][0] *= alpha0; oacc[nt][1] *= alpha0;
            oacc[nt][2] *= alpha1; oacc[nt][3] *= alpha1;
        }

        // ---- PV: P fragments from S registers (FA2 trick), 2-term split ----
        #pragma unroll
        for (int kb2 = 0; kb2 < 4; kb2++) {
            unsigned aph[4], apl[4];
            splitPack(sacc[2*kb2  ][0], sacc[2*kb2  ][1], aph[0], apl[0]);
            splitPack(sacc[2*kb2  ][2], sacc[2*kb2  ][3], aph[1], apl[1]);
            splitPack(sacc[2*kb2+1][0], sacc[2*kb2+1][1], aph[2], apl[2]);
            splitPack(sacc[2*kb2+1][2], sacc[2*kb2+1][3], aph[3], apl[3]);
            unsigned bv[8][2];
            #pragma unroll
            for (int p = 0; p < 4; p++) {
                unsigned t[4];
                ldm4(t, Vs + (buf*64 + p*16 + roff)*FPAD + kb2*16 + coff);
                bv[2*p][0]=t[0]; bv[2*p][1]=t[2]; bv[2*p+1][0]=t[1]; bv[2*p+1][1]=t[3];
            }
            #pragma unroll
            for (int nt = 0; nt < 8; nt++) {
                mma16816(oacc[nt], aph, bv[nt]);
                mma16816(oacc[nt], apl, bv[nt]);
            }
        }
        __syncthreads();
        buf ^= 1;
    }

    // ---- normalize + split store ----
    float inv0 = 1.0f / lrow[0];
    float inv1 = 1.0f / lrow[1];
    const int gq = q0 + wq + g;
    #pragma unroll
    for (int nt = 0; nt < 8; nt++) {
        int col = h*HD + nt*8 + t4*2;
        unsigned hi, lo;
        splitPack(oacc[nt][0]*inv0, oacc[nt][1]*inv0, hi, lo);
        *(unsigned*)&Ahh[(size_t)gq*DMODEL + col] = hi;
        *(unsigned*)&All[(size_t)gq*DMODEL + col] = lo;
        splitPack(oacc[nt][2]*inv1, oacc[nt][3]*inv1, hi, lo);
        *(unsigned*)&Ahh[(size_t)(gq+8)*DMODEL + col] = hi;
        *(unsigned*)&All[(size_t)(gq+8)*DMODEL + col] = lo;
    }
}

// ---------------- pre/post processing ----------------
__global__ void split_x(const float* __restrict__ in, ushort_t* __restrict__ h,
                        ushort_t* __restrict__ l, int n)
{
    int i = blockIdx.x*blockDim.x + threadIdx.x;
    if (i*4 >= n) return;
    float4 v = *(const float4*)&in[i*4];
    unsigned hi0, lo0, hi1, lo1;
    splitPack(v.x, v.y, hi0, lo0);
    splitPack(v.z, v.w, hi1, lo1);
    *(unsigned*)&h[i*4]   = hi0; *(unsigned*)&h[i*4+2] = hi1;
    *(unsigned*)&l[i*4]   = lo0; *(unsigned*)&l[i*4+2] = lo1;
}

__global__ void splitWT(const float* __restrict__ W, int K, int N,
                        ushort_t* __restrict__ T_, int rowOff)
{
    __shared__ float t[32][33];
    int k0 = blockIdx.y*32, n0 = blockIdx.x*32;
    for (int i = threadIdx.y; i < 32; i += 8)
        t[i][threadIdx.x] = W[(size_t)(k0+i)*N + n0 + threadIdx.x];
    __syncthreads();
    for (int i = threadIdx.y; i < 32; i += 8)
        T_[(size_t)(rowOff+n0+i)*DMODEL + k0 + threadIdx.x] = rndH(t[threadIdx.x][i]);
}

__global__ void __launch_bounds__(256) softmax_kernel(float* __restrict__ p)
{
    size_t row = blockIdx.x;
    float* ptr = p + row*(size_t)T_SEQ;
    int tid = threadIdx.x;
    int lane = tid & 31, warp = tid >> 5;
    __shared__ float sm[8];
    float4 va = *(float4*)&ptr[tid*4];
    float4 vb = *(float4*)&ptr[tid*4 + 1024];
    float mx = fmaxf(fmaxf(fmaxf(va.x,va.y),fmaxf(va.z,va.w)),
                     fmaxf(fmaxf(vb.x,vb.y),fmaxf(vb.z,vb.w)));
    #pragma unroll
    for (int o=16;o>0;o>>=1) mx = fmaxf(mx, __shfl_xor_sync(0xffffffffu, mx, o));
    if (lane==0) sm[warp]=mx;
    __syncthreads();
    if (tid==0){ float m=sm[0]; for(int i=1;i<8;i++) m=fmaxf(m,sm[i]); sm[0]=m; }
    __syncthreads();
    mx = sm[0];
    __syncthreads();
    va.x=expf(va.x-mx); va.y=expf(va.y-mx); va.z=expf(va.z-mx); va.w=expf(va.w-mx);
    vb.x=expf(vb.x-mx); vb.y=expf(vb.y-mx); vb.z=expf(vb.z-mx); vb.w=expf(vb.w-mx);
    float s = (va.x+va.y)+(va.z+va.w)+(vb.x+vb.y)+(vb.z+vb.w);
    #pragma unroll
    for (int o=16;o>0;o>>=1) s += __shfl_xor_sync(0xffffffffu, s, o);
    if (lane==0) sm[warp]=s;
    __syncthreads();
    if (tid==0){ float t=0; for(int i=1;i<8;i++) t+=sm[i]; sm[0]+=t; }
    __syncthreads();
    float inv = 1.0f/sm[0];
    va.x*=inv; va.y*=inv; va.z*=inv; va.w*=inv;
    vb.x*=inv; vb.y*=inv; vb.z*=inv; vb.w*=inv;
    *(float4*)&ptr[tid*4]        = va;
    *(float4*)&ptr[tid*4 + 1024] = vb;
}

// ============================================================================
extern "C" void kernel_launch(void* const* d_in, const int* in_sizes, int n_in,
                              void* d_out, int out_size)
{
    (void)in_sizes; (void)n_in;
    const float* x  = (const float*)d_in[0];
    const float* Wq = (const float*)d_in[1];
    const float* Wk = (const float*)d_in[2];
    const float* Wv = (const float*)d_in[3];
    const float* Wo = (const float*)d_in[4];
    const int* mask = (const int*)d_in[5];
    float* out = (float*)d_out;

    float *gP;
    ushort_t *xh,*xl,*Wcat,*WoT,*Qh,*Ql,*Kf,*VT,*Ahh,*All;
    cudaGetSymbolAddress((void**)&gP,  g_P);
    cudaGetSymbolAddress((void**)&xh,  g_xh);   cudaGetSymbolAddress((void**)&xl,  g_xl);
    cudaGetSymbolAddress((void**)&Wcat,g_Wcat); cudaGetSymbolAddress((void**)&WoT, g_WoT);
    cudaGetSymbolAddress((void**)&Qh,  g_Qh);   cudaGetSymbolAddress((void**)&Ql,  g_Ql);
    cudaGetSymbolAddress((void**)&Kf,  g_Kf);   cudaGetSymbolAddress((void**)&VT,  g_VT);
    cudaGetSymbolAddress((void**)&Ahh, g_Ah);   cudaGetSymbolAddress((void**)&All, g_Al);

    cudaFuncSetAttribute(qkv_tc,    cudaFuncAttributeMaxDynamicSharedMemorySize, SM_BN128);
    cudaFuncSetAttribute(gemm_tc,   cudaFuncAttributeMaxDynamicSharedMemorySize, SM_BN128);
    cudaFuncSetAttribute(logits_tc, cudaFuncAttributeMaxDynamicSharedMemorySize, SM_BN128);
    cudaFuncSetAttribute(pv_tc,     cudaFuncAttributeMaxDynamicSharedMemorySize, SM_PV);
    cudaFuncSetAttribute(flash_tc,  cudaFuncAttributeMaxDynamicSharedMemorySize, SM_FLASH);

    const long long OUT_N = (long long)T_SEQ * DMODEL;
    const long long ATT_N = (long long)NH * T_SEQ * T_SEQ;
    long long osz = (long long)out_size;

    // ---- pre-split x; transpose+round weights into concat fp16 ----
    bool need_out = !(osz == ATT_N);
    {
        int nx = T_SEQ*DMODEL;
        split_x<<<nx/4/256, 256>>>(x, xh, xl, nx);
        splitWT<<<dim3(DMODEL/32, DMODEL/32), dim3(32,8)>>>(Wq, DMODEL, DMODEL, Wcat, 0);
        splitWT<<<dim3(KVW/32,    DMODEL/32), dim3(32,8)>>>(Wk, DMODEL, KVW, Wcat, DMODEL);
        splitWT<<<dim3(KVW/32,    DMODEL/32), dim3(32,8)>>>(Wv, DMODEL, KVW, Wcat, DMODEL+KVW);
        if (need_out)
            splitWT<<<dim3(DMODEL/32, DMODEL/32), dim3(32,8)>>>(Wo, DMODEL, DMODEL, WoT, 0);
    }

    // ---- fused QKV projection ----
    qkv_tc<<<dim3(NQKV/128, T_SEQ/128), 256, SM_BN128>>>(xh, xl, Wcat, Qh, Ql, Kf, VT);

    if (osz < ATT_N) {
        // out-only: FLASH path (no probs materialization)
        flash_tc<<<dim3(T_SEQ/128, NH), 256, SM_FLASH>>>(Qh, Ql, Kf, VT, mask, Ahh, All);
        gemm_tc<<<dim3(DMODEL/128, T_SEQ/128), 256, SM_BN128>>>(
            Ahh, All, DMODEL, WoT, DMODEL, out, DMODEL, DMODEL);
    } else {
        // attn must be materialized
        float* probs = (osz >= OUT_N + ATT_N) ? (out + OUT_N) : out;
        logits_tc<<<dim3(T_SEQ/128, T_SEQ/128, NH), 256, SM_BN128>>>(Qh, Ql, Kf, mask, probs);
        softmax_kernel<<<NH*T_SEQ, 256>>>(probs);
        if (osz >= OUT_N + ATT_N) {
            pv_tc<<<dim3(1, T_SEQ/128, NH), 256, SM_PV>>>(probs, VT, Ahh, All);
            gemm_tc<<<dim3(DMODEL/128, T_SEQ/128), 256, SM_BN128>>>(
                Ahh, All, DMODEL, WoT, DMODEL, out, DMODEL, DMODEL);
        }
    }
}

// round 16
// speedup vs baseline: 3.1529x; 1.0724x over previous
#include <cuda_runtime.h>
#include <cuda_fp16.h>
#include <math.h>

#define T_SEQ 2048
#define DMODEL 2048
#define NH 32
#define NKV 8
#define HD 64
#define KVW (NKV*HD)       // 512
#define NQKV (DMODEL+2*KVW) // 3072
typedef unsigned short ushort_t;

// ---------------- scratch ----------------
__device__ float g_P[(size_t)NH * T_SEQ * T_SEQ];            // probs (out-only fallback)
__device__ float g_stats[(size_t)NH * T_SEQ * 2];            // per-row {max, sum}
__device__ __align__(16) ushort_t g_xh[(size_t)T_SEQ*DMODEL],  g_xl[(size_t)T_SEQ*DMODEL];
__device__ __align__(16) ushort_t g_Wcat[(size_t)NQKV*DMODEL];
__device__ __align__(16) ushort_t g_WoT[(size_t)DMODEL*DMODEL];
__device__ __align__(16) ushort_t g_Qh[(size_t)T_SEQ*DMODEL],  g_Ql[(size_t)T_SEQ*DMODEL];
__device__ __align__(16) ushort_t g_Kf[(size_t)T_SEQ*KVW];
__device__ __align__(16) ushort_t g_VT[(size_t)KVW*T_SEQ];
__device__ __align__(16) ushort_t g_Ah[(size_t)T_SEQ*DMODEL],  g_Al[(size_t)T_SEQ*DMODEL];

// ---------------- helpers ----------------
__device__ __forceinline__ void splitH(float x, ushort_t &h, ushort_t &l) {
    __half hb = __float2half_rn(x);
    __half lb = __float2half_rn(x - __half2float(hb));
    h = *(ushort_t*)&hb;
    l = *(ushort_t*)&lb;
}
__device__ __forceinline__ ushort_t rndH(float x) {
    __half hb = __float2half_rn(x);
    return *(ushort_t*)&hb;
}
__device__ __forceinline__ unsigned packH2(float a, float b) {
    return ((unsigned)rndH(b) << 16) | rndH(a);
}
__device__ __forceinline__ void splitPack(float a, float b, unsigned &hi, unsigned &lo) {
    ushort_t ha,la,hb2,lb2;
    splitH(a, ha, la); splitH(b, hb2, lb2);
    hi = ((unsigned)hb2<<16)|ha;
    lo = ((unsigned)lb2<<16)|la;
}

__device__ __forceinline__ void mma16816(float c[4], const unsigned a[4], const unsigned b[2]) {
    asm volatile(
        "mma.sync.aligned.m16n8k16.row.col.f32.f16.f16.f32 "
        "{%0,%1,%2,%3},{%4,%5,%6,%7},{%8,%9},{%0,%1,%2,%3};\n"
        : "+f"(c[0]), "+f"(c[1]), "+f"(c[2]), "+f"(c[3])
        : "r"(a[0]), "r"(a[1]), "r"(a[2]), "r"(a[3]), "r"(b[0]), "r"(b[1]));
}

__device__ __forceinline__ void cp16(void* dst, const void* src) {
    unsigned d = (unsigned)__cvta_generic_to_shared(dst);
    asm volatile("cp.async.cg.shared.global [%0], [%1], 16;\n" :: "r"(d), "l"(src));
}
__device__ __forceinline__ void cp_commit() { asm volatile("cp.async.commit_group;\n"); }
__device__ __forceinline__ void cp_wait1()  { asm volatile("cp.async.wait_group 1;\n"); }
__device__ __forceinline__ void cp_wait0()  { asm volatile("cp.async.wait_group 0;\n"); }

__device__ __forceinline__ void ldm4(unsigned r[4], const void* p) {
    unsigned a = (unsigned)__cvta_generic_to_shared(p);
    asm volatile("ldmatrix.sync.aligned.m8n8.x4.shared.b16 {%0,%1,%2,%3},[%4];\n"
        : "=r"(r[0]), "=r"(r[1]), "=r"(r[2]), "=r"(r[3]) : "r"(a));
}

// ============================================================================
// 2-term fp16-split GEMM (projections). EPI 0: fp32 C. EPI 4: fused QKV.
// ============================================================================
#define BKK 32
#define PADK 40

template<int BM,int BN,int WM,int WN,int EPI>
__device__ __forceinline__ void mma_core(
    const ushort_t* __restrict__ Ah, const ushort_t* __restrict__ Al, int lda,
    const ushort_t* __restrict__ Bh, int ldb,
    float* __restrict__ C, ushort_t* __restrict__ Ch, ushort_t* __restrict__ Cl, int ldc,
    int K, int m0, int n0,
    ushort_t* __restrict__ Kd, ushort_t* __restrict__ VTd)
{
    extern __shared__ __align__(16) ushort_t smp[];
    ushort_t* Asm = smp;
    ushort_t* Bsm = smp + 4*BM*PADK;

    const int tid  = threadIdx.x;
    const int w    = tid >> 5;
    const int lane = tid & 31;
    constexpr int WROWS = BM / WM;
    const int wm = (w % WROWS) * WM;
    const int wn = (w / WROWS) * WN;
    constexpr int MT = WM / 16;
    constexpr int NT = WN / 8;
    const int g  = lane >> 2;
    const int t4 = lane & 3;
    const int roff = ((lane >> 3) & 1) * 8 + (lane & 7);
    const int coff = (lane >> 4) * 8;

    float acc[MT][NT][4];
    #pragma unroll
    for (int mt=0;mt<MT;mt++)
        #pragma unroll
        for (int nt=0;nt<NT;nt++)
            #pragma unroll
            for (int i=0;i<4;i++) acc[mt][nt][i]=0.f;

    constexpr int ACH = 2*BM*(BKK/8);
    constexpr int BCH = BN*(BKK/8);
    constexpr int TC  = ACH + BCH;

    auto stage = [&](int buf, int k0) {
        #pragma unroll
        for (int i = 0; i < TC/256; i++) {
            int q = tid + i*256;
            if (q < ACH) {
                int p = q / (BM*4);
                int rem = q - p*(BM*4);
                int r = rem >> 2, o = (rem & 3) * 8;
                const ushort_t* src = (p ? Al : Ah) + (size_t)(m0+r)*lda + k0 + o;
                cp16(Asm + ((buf*2+p)*BM + r)*PADK + o, src);
            } else {
                int qq = q - ACH;
                int r = qq >> 2, o = (qq & 3) * 8;
                cp16(Bsm + (buf*BN + r)*PADK + o, Bh + (size_t)(n0+r)*ldb + k0 + o);
            }
        }
    };

    const int KIT = K / BKK;
    stage(0, 0);
    cp_commit();
    int buf = 0;

    for (int it = 0; it < KIT; it++) {
        if (it + 1 < KIT) { stage(buf ^ 1, (it + 1) * BKK); cp_commit(); cp_wait1(); }
        else { cp_wait0(); }
        __syncthreads();

        #pragma unroll
        for (int ks = 0; ks < BKK; ks += 16) {
            unsigned ah[MT][4], al[MT][4], bh[NT][2];
            #pragma unroll
            for (int mt = 0; mt < MT; mt++) {
                int row = wm + mt*16 + roff;
                ldm4(ah[mt], Asm + ((buf*2+0)*BM + row)*PADK + ks + coff);
                ldm4(al[mt], Asm + ((buf*2+1)*BM + row)*PADK + ks + coff);
            }
            #pragma unroll
            for (int p = 0; p < NT/2; p++) {
                unsigned t[4];
                ldm4(t, Bsm + (buf*BN + wn + p*16 + roff)*PADK + ks + coff);
                bh[2*p][0]=t[0]; bh[2*p][1]=t[2]; bh[2*p+1][0]=t[1]; bh[2*p+1][1]=t[3];
            }
            #pragma unroll
            for (int mt = 0; mt < MT; mt++)
                #pragma unroll
                for (int nt = 0; nt < NT; nt++) {
                    mma16816(acc[mt][nt], ah[mt], bh[nt]);
                    mma16816(acc[mt][nt], al[mt], bh[nt]);
                }
        }
        __syncthreads();
        buf ^= 1;
    }

    #pragma unroll
    for (int mt = 0; mt < MT; mt++) {
        #pragma unroll
        for (int nt = 0; nt < NT; nt++) {
            int row = m0 + wm + mt*16 + g;
            int col = n0 + wn + nt*8 + t4*2;
            float a0 = acc[mt][nt][0], a1 = acc[mt][nt][1];
            float a2 = acc[mt][nt][2], a3 = acc[mt][nt][3];
            if (EPI == 0) {
                *(float2*)&C[(size_t)row    *ldc + col] = make_float2(a0, a1);
                *(float2*)&C[(size_t)(row+8)*ldc + col] = make_float2(a2, a3);
            } else {
                if (col < DMODEL) {
                    int j = (col & (HD-1)) >> 1;
                    float theta = powf(10000.0f, -(float)(2*j) / 64.0f);
                    float sn, cs;
                    unsigned hi, lo;
                    sincosf((float)row * theta, &sn, &cs);
                    splitPack(a0*cs - a1*sn, a0*sn + a1*cs, hi, lo);
                    *(unsigned*)&Ch[(size_t)row*DMODEL + col] = hi;
                    *(unsigned*)&Cl[(size_t)row*DMODEL + col] = lo;
                    sincosf((float)(row+8) * theta, &sn, &cs);
                    splitPack(a2*cs - a3*sn, a2*sn + a3*cs, hi, lo);
                    *(unsigned*)&Ch[(size_t)(row+8)*DMODEL + col] = hi;
                    *(unsigned*)&Cl[(size_t)(row+8)*DMODEL + col] = lo;
                } else if (col < DMODEL + KVW) {
                    int c2 = col - DMODEL;
                    int j = (c2 & (HD-1)) >> 1;
                    float theta = powf(10000.0f, -(float)(2*j) / 64.0f);
                    float sn, cs;
                    sincosf((float)row * theta, &sn, &cs);
                    *(unsigned*)&Kd[(size_t)row*KVW + c2] = packH2(a0*cs - a1*sn, a0*sn + a1*cs);
                    sincosf((float)(row+8) * theta, &sn, &cs);
                    *(unsigned*)&Kd[(size_t)(row+8)*KVW + c2] = packH2(a2*cs - a3*sn, a2*sn + a3*cs);
                } else {
                    int c2 = col - (DMODEL + KVW);
                    VTd[(size_t)c2    *T_SEQ + row]   = rndH(a0);
                    VTd[(size_t)(c2+1)*T_SEQ + row]   = rndH(a1);
                    VTd[(size_t)c2    *T_SEQ + row+8] = rndH(a2);
                    VTd[(size_t)(c2+1)*T_SEQ + row+8] = rndH(a3);
                }
            }
        }
    }
}

#define SM_BN128 ((4*128*PADK + 2*128*PADK)*2)   // 61440

__global__ void __launch_bounds__(256,2) qkv_tc(
    const ushort_t* xh, const ushort_t* xl, const ushort_t* Wcat,
    ushort_t* Qh, ushort_t* Ql, ushort_t* Kd, ushort_t* VTd)
{
    mma_core<128,128,32,64,4>(xh, xl, DMODEL, Wcat, DMODEL,
                              nullptr, Qh, Ql, DMODEL, DMODEL,
                              blockIdx.y*128, blockIdx.x*128, Kd, VTd);
}

__global__ void __launch_bounds__(256,2) gemm_tc(
    const ushort_t* Ah, const ushort_t* Al, int lda,
    const ushort_t* Bh, int ldb, float* C, int ldc, int K)
{
    mma_core<128,128,32,64,0>(Ah,Al,lda,Bh,ldb,C,nullptr,nullptr,ldc,K,
                              blockIdx.y*128, blockIdx.x*128, nullptr, nullptr);
}

// ============================================================================
// S-tile machinery: CTA = (q-tile 128, head); warp owns 16 q-rows; 64-wide k tiles.
// ============================================================================
#define FPAD 72
#define SM_STATS ((2*128*FPAD + 2*64*FPAD)*2)               // 55296
#define SM_PVW   ((2*128*FPAD + 2*64*FPAD + 2*64*FPAD)*2)   // 73728

__device__ __forceinline__ void s_tile(
    float sacc[8][4], const ushort_t* Qs, const ushort_t* Ks, int buf,
    const int* __restrict__ mask, int gq, int kt,
    int wq, int roff, int coff, int t4)
{
    #pragma unroll
    for (int nt=0;nt<8;nt++)
        #pragma unroll
        for (int i=0;i<4;i++) sacc[nt][i]=0.f;
    #pragma unroll
    for (int kb = 0; kb < 4; kb++) {
        unsigned qh4[4], ql4[4], bh[8][2];
        ldm4(qh4, Qs + (0*128 + wq + roff)*FPAD + kb*16 + coff);
        ldm4(ql4, Qs + (1*128 + wq + roff)*FPAD + kb*16 + coff);
        #pragma unroll
        for (int p = 0; p < 4; p++) {
            unsigned t[4];
            ldm4(t, Ks + (buf*64 + p*16 + roff)*FPAD + kb*16 + coff);
            bh[2*p][0]=t[0]; bh[2*p][1]=t[2]; bh[2*p+1][0]=t[1]; bh[2*p+1][1]=t[3];
        }
        #pragma unroll
        for (int nt = 0; nt < 8; nt++) {
            mma16816(sacc[nt], qh4, bh[nt]);
            mma16816(sacc[nt], ql4, bh[nt]);
        }
    }
    #pragma unroll
    for (int nt = 0; nt < 8; nt++) {
        int col = kt*64 + nt*8 + t4*2;
        int2 mv0 = *(const int2*)&mask[(size_t)gq    *T_SEQ + col];
        int2 mv1 = *(const int2*)&mask[(size_t)(gq+8)*T_SEQ + col];
        float s0 = sacc[nt][0]*0.125f, s1 = sacc[nt][1]*0.125f;
        float s2 = sacc[nt][2]*0.125f, s3 = sacc[nt][3]*0.125f;
        sacc[nt][0] = mv0.x ? (s0+s0) : (s0-1e9f);
        sacc[nt][1] = mv0.y ? (s1+s1) : (s1-1e9f);
        sacc[nt][2] = mv1.x ? (s2+s2) : (s2-1e9f);
        sacc[nt][3] = mv1.y ? (s3+s3) : (s3-1e9f);
    }
}

// ---- stats pass: online row max/sum ----
__global__ void __launch_bounds__(256,2) stats_tc(
    const ushort_t* __restrict__ Qh, const ushort_t* __restrict__ Ql,
    const ushort_t* __restrict__ Kf, const int* __restrict__ mask,
    float* __restrict__ stats)
{
    const int h  = blockIdx.y, kv = h >> 2;
    const int q0 = blockIdx.x * 128;
    extern __shared__ __align__(16) ushort_t fsm[];
    ushort_t* Qs = fsm;
    ushort_t* Ks = fsm + 2*128*FPAD;

    const int tid = threadIdx.x, w = tid >> 5, lane = tid & 31;
    const int g = lane >> 2, t4 = lane & 3;
    const int roff = ((lane >> 3) & 1) * 8 + (lane & 7);
    const int coff = (lane >> 4) * 8;
    const int wq = w * 16;

    #pragma unroll
    for (int i = 0; i < 8; i++) {
        int q = tid + i*256;
        int p = q >> 10, rem = q & 1023;
        int r = rem >> 3, o = (rem & 7) * 8;
        cp16(Qs + (p*128 + r)*FPAD + o, (p ? Ql : Qh) + (size_t)(q0+r)*DMODEL + h*HD + o);
    }
    auto stageK = [&](int buf, int kt) {
        #pragma unroll
        for (int i = 0; i < 2; i++) {
            int q = tid + i*256;
            int r = q >> 3, o = (q & 7) * 8;
            cp16(Ks + (buf*64 + r)*FPAD + o, Kf + (size_t)(kt*64+r)*KVW + kv*HD + o);
        }
    };
    stageK(0, 0);
    cp_commit();
    int buf = 0;

    float mrow0 = -3.0e38f, mrow1 = -3.0e38f, lrow0 = 0.f, lrow1 = 0.f;
    const int gq = q0 + wq + g;
    const int NKT = T_SEQ / 64;
    for (int kt = 0; kt < NKT; kt++) {
        if (kt + 1 < NKT) { stageK(buf ^ 1, kt + 1); cp_commit(); cp_wait1(); }
        else { cp_wait0(); }
        __syncthreads();

        float sacc[8][4];
        s_tile(sacc, Qs, Ks, buf, mask, gq, kt, wq, roff, coff, t4);

        float rmax0 = -3.0e38f, rmax1 = -3.0e38f;
        #pragma unroll
        for (int nt = 0; nt < 8; nt++) {
            rmax0 = fmaxf(rmax0, fmaxf(sacc[nt][0], sacc[nt][1]));
            rmax1 = fmaxf(rmax1, fmaxf(sacc[nt][2], sacc[nt][3]));
        }
        #pragma unroll
        for (int o = 1; o <= 2; o <<= 1) {
            rmax0 = fmaxf(rmax0, __shfl_xor_sync(0xffffffffu, rmax0, o));
            rmax1 = fmaxf(rmax1, __shfl_xor_sync(0xffffffffu, rmax1, o));
        }
        float mnew0 = fmaxf(mrow0, rmax0);
        float mnew1 = fmaxf(mrow1, rmax1);
        float alpha0 = expf(mrow0 - mnew0);
        float alpha1 = expf(mrow1 - mnew1);
        float rsum0 = 0.f, rsum1 = 0.f;
        #pragma unroll
        for (int nt = 0; nt < 8; nt++) {
            rsum0 += expf(sacc[nt][0] - mnew0) + expf(sacc[nt][1] - mnew0);
            rsum1 += expf(sacc[nt][2] - mnew1) + expf(sacc[nt][3] - mnew1);
        }
        #pragma unroll
        for (int o = 1; o <= 2; o <<= 1) {
            rsum0 += __shfl_xor_sync(0xffffffffu, rsum0, o);
            rsum1 += __shfl_xor_sync(0xffffffffu, rsum1, o);
        }
        lrow0 = lrow0*alpha0 + rsum0;
        lrow1 = lrow1*alpha1 + rsum1;
        mrow0 = mnew0; mrow1 = mnew1;
        __syncthreads();
        buf ^= 1;
    }
    if (t4 == 0) {
        *(float2*)&stats[((size_t)h*T_SEQ + gq  )*2] = make_float2(mrow0, lrow0);
        *(float2*)&stats[((size_t)h*T_SEQ + gq+8)*2] = make_float2(mrow1, lrow1);
    }
}

// ---- pvwrite: recompute S, p = exp(s-m)/l, write probs, O += P@V ----
__global__ void __launch_bounds__(256,2) pvwrite_tc(
    const ushort_t* __restrict__ Qh, const ushort_t* __restrict__ Ql,
    const ushort_t* __restrict__ Kf, const ushort_t* __restrict__ VT,
    const int* __restrict__ mask, const float* __restrict__ stats,
    float* __restrict__ probs,
    ushort_t* __restrict__ Ahh, ushort_t* __restrict__ All, int do_out)
{
    const int h  = blockIdx.y, kv = h >> 2;
    const int q0 = blockIdx.x * 128;
    extern __shared__ __align__(16) ushort_t fsm[];
    ushort_t* Qs = fsm;
    ushort_t* Ks = fsm + 2*128*FPAD;
    ushort_t* Vs = Ks  + 2*64*FPAD;

    const int tid = threadIdx.x, w = tid >> 5, lane = tid & 31;
    const int g = lane >> 2, t4 = lane & 3;
    const int roff = ((lane >> 3) & 1) * 8 + (lane & 7);
    const int coff = (lane >> 4) * 8;
    const int wq = w * 16;

    #pragma unroll
    for (int i = 0; i < 8; i++) {
        int q = tid + i*256;
        int p = q >> 10, rem = q & 1023;
        int r = rem >> 3, o = (rem & 7) * 8;
        cp16(Qs + (p*128 + r)*FPAD + o, (p ? Ql : Qh) + (size_t)(q0+r)*DMODEL + h*HD + o);
    }
    auto stageKV = [&](int buf, int kt) {
        #pragma unroll
        for (int i = 0; i < 4; i++) {
            int q = tid + i*256;
            int p = q >> 9, rem = q & 511;
            int r = rem >> 3, o = (rem & 7) * 8;
            if (p == 0)
                cp16(Ks + (buf*64 + r)*FPAD + o, Kf + (size_t)(kt*64+r)*KVW + kv*HD + o);
            else
                cp16(Vs + (buf*64 + r)*FPAD + o, VT + (size_t)(kv*HD + r)*T_SEQ + kt*64 + o);
        }
    };
    stageKV(0, 0);
    cp_commit();
    int buf = 0;

    const int gq = q0 + wq + g;
    float2 st0 = *(const float2*)&stats[((size_t)h*T_SEQ + gq  )*2];
    float2 st1 = *(const float2*)&stats[((size_t)h*T_SEQ + gq+8)*2];
    const float m0 = st0.x, inv0 = 1.0f/st0.y;
    const float m1 = st1.x, inv1 = 1.0f/st1.y;
    float* pr0 = probs + ((size_t)h*T_SEQ + gq  )*T_SEQ;
    float* pr1 = probs + ((size_t)h*T_SEQ + gq+8)*T_SEQ;

    float oacc[8][4];
    #pragma unroll
    for (int nt=0;nt<8;nt++)
        #pragma unroll
        for (int i=0;i<4;i++) oacc[nt][i]=0.f;

    const int NKT = T_SEQ / 64;
    for (int kt = 0; kt < NKT; kt++) {
        if (kt + 1 < NKT) { stageKV(buf ^ 1, kt + 1); cp_commit(); cp_wait1(); }
        else { cp_wait0(); }
        __syncthreads();

        float sacc[8][4];
        s_tile(sacc, Qs, Ks, buf, mask, gq, kt, wq, roff, coff, t4);

        #pragma unroll
        for (int nt = 0; nt < 8; nt++) {
            int col = kt*64 + nt*8 + t4*2;
            float p0 = expf(sacc[nt][0] - m0) * inv0;
            float p1 = expf(sacc[nt][1] - m0) * inv0;
            float p2 = expf(sacc[nt][2] - m1) * inv1;
            float p3 = expf(sacc[nt][3] - m1) * inv1;
            sacc[nt][0]=p0; sacc[nt][1]=p1; sacc[nt][2]=p2; sacc[nt][3]=p3;
            *(float2*)&pr0[col] = make_float2(p0, p1);
            *(float2*)&pr1[col] = make_float2(p2, p3);
        }

        if (do_out) {
            #pragma unroll
            for (int kb2 = 0; kb2 < 4; kb2++) {
                unsigned aph[4], apl[4];
                splitPack(sacc[2*kb2  ][0], sacc[2*kb2  ][1], aph[0], apl[0]);
                splitPack(sacc[2*kb2  ][2], sacc[2*kb2  ][3], aph[1], apl[1]);
                splitPack(sacc[2*kb2+1][0], sacc[2*kb2+1][1], aph[2], apl[2]);
                splitPack(sacc[2*kb2+1][2], sacc[2*kb2+1][3], aph[3], apl[3]);
                unsigned bv[8][2];
                #pragma unroll
                for (int p = 0; p < 4; p++) {
                    unsigned t[4];
                    ldm4(t, Vs + (buf*64 + p*16 + roff)*FPAD + kb2*16 + coff);
                    bv[2*p][0]=t[0]; bv[2*p][1]=t[2]; bv[2*p+1][0]=t[1]; bv[2*p+1][1]=t[3];
                }
                #pragma unroll
                for (int nt = 0; nt < 8; nt++) {
                    mma16816(oacc[nt], aph, bv[nt]);
                    mma16816(oacc[nt], apl, bv[nt]);
                }
            }
        }
        __syncthreads();
        buf ^= 1;
    }

    if (do_out) {
        #pragma unroll
        for (int nt = 0; nt < 8; nt++) {
            int col = h*HD + nt*8 + t4*2;
            unsigned hi, lo;
            splitPack(oacc[nt][0], oacc[nt][1], hi, lo);
            *(unsigned*)&Ahh[(size_t)gq*DMODEL + col] = hi;
            *(unsigned*)&All[(size_t)gq*DMODEL + col] = lo;
            splitPack(oacc[nt][2], oacc[nt][3], hi, lo);
            *(unsigned*)&Ahh[(size_t)(gq+8)*DMODEL + col] = hi;
            *(unsigned*)&All[(size_t)(gq+8)*DMODEL + col] = lo;
        }
    }
}

// ---------------- pre-processing ----------------
__global__ void split_x(const float* __restrict__ in, ushort_t* __restrict__ h,
                        ushort_t* __restrict__ l, int n)
{
    int i = blockIdx.x*blockDim.x + threadIdx.x;
    if (i*4 >= n) return;
    float4 v = *(const float4*)&in[i*4];
    unsigned hi0, lo0, hi1, lo1;
    splitPack(v.x, v.y, hi0, lo0);
    splitPack(v.z, v.w, hi1, lo1);
    *(unsigned*)&h[i*4]   = hi0; *(unsigned*)&h[i*4+2] = hi1;
    *(unsigned*)&l[i*4]   = lo0; *(unsigned*)&l[i*4+2] = lo1;
}

__global__ void splitWT(const float* __restrict__ W, int K, int N,
                        ushort_t* __restrict__ T_, int rowOff)
{
    __shared__ float t[32][33];
    int k0 = blockIdx.y*32, n0 = blockIdx.x*32;
    for (int i = threadIdx.y; i < 32; i += 8)
        t[i][threadIdx.x] = W[(size_t)(k0+i)*N + n0 + threadIdx.x];
    __syncthreads();
    for (int i = threadIdx.y; i < 32; i += 8)
        T_[(size_t)(rowOff+n0+i)*DMODEL + k0 + threadIdx.x] = rndH(t[threadIdx.x][i]);
}

// ============================================================================
extern "C" void kernel_launch(void* const* d_in, const int* in_sizes, int n_in,
                              void* d_out, int out_size)
{
    (void)in_sizes; (void)n_in;
    const float* x  = (const float*)d_in[0];
    const float* Wq = (const float*)d_in[1];
    const float* Wk = (const float*)d_in[2];
    const float* Wv = (const float*)d_in[3];
    const float* Wo = (const float*)d_in[4];
    const int* mask = (const int*)d_in[5];
    float* out = (float*)d_out;

    float *gP, *gStats;
    ushort_t *xh,*xl,*Wcat,*WoT,*Qh,*Ql,*Kf,*VT,*Ahh,*All;
    cudaGetSymbolAddress((void**)&gP,  g_P);
    cudaGetSymbolAddress((void**)&gStats, g_stats);
    cudaGetSymbolAddress((void**)&xh,  g_xh);   cudaGetSymbolAddress((void**)&xl,  g_xl);
    cudaGetSymbolAddress((void**)&Wcat,g_Wcat); cudaGetSymbolAddress((void**)&WoT, g_WoT);
    cudaGetSymbolAddress((void**)&Qh,  g_Qh);   cudaGetSymbolAddress((void**)&Ql,  g_Ql);
    cudaGetSymbolAddress((void**)&Kf,  g_Kf);   cudaGetSymbolAddress((void**)&VT,  g_VT);
    cudaGetSymbolAddress((void**)&Ahh, g_Ah);   cudaGetSymbolAddress((void**)&All, g_Al);

    cudaFuncSetAttribute(qkv_tc,     cudaFuncAttributeMaxDynamicSharedMemorySize, SM_BN128);
    cudaFuncSetAttribute(gemm_tc,    cudaFuncAttributeMaxDynamicSharedMemorySize, SM_BN128);
    cudaFuncSetAttribute(stats_tc,   cudaFuncAttributeMaxDynamicSharedMemorySize, SM_STATS);
    cudaFuncSetAttribute(pvwrite_tc, cudaFuncAttributeMaxDynamicSharedMemorySize, SM_PVW);

    const long long OUT_N = (long long)T_SEQ * DMODEL;
    const long long ATT_N = (long long)NH * T_SEQ * T_SEQ;
    long long osz = (long long)out_size;
    bool need_out = !(osz == ATT_N);
    float* probs = (osz >= OUT_N + ATT_N) ? (out + OUT_N) : (osz == ATT_N ? out : gP);

    // ---- pre-split x; transpose+round weights into concat fp16 ----
    {
        int nx = T_SEQ*DMODEL;
        split_x<<<nx/4/256, 256>>>(x, xh, xl, nx);
        splitWT<<<dim3(DMODEL/32, DMODEL/32), dim3(32,8)>>>(Wq, DMODEL, DMODEL, Wcat, 0);
        splitWT<<<dim3(KVW/32,    DMODEL/32), dim3(32,8)>>>(Wk, DMODEL, KVW, Wcat, DMODEL);
        splitWT<<<dim3(KVW/32,    DMODEL/32), dim3(32,8)>>>(Wv, DMODEL, KVW, Wcat, DMODEL+KVW);
        if (need_out)
            splitWT<<<dim3(DMODEL/32, DMODEL/32), dim3(32,8)>>>(Wo, DMODEL, DMODEL, WoT, 0);
    }

    // ---- fused QKV projection ----
    qkv_tc<<<dim3(NQKV/128, T_SEQ/128), 256, SM_BN128>>>(xh, xl, Wcat, Qh, Ql, Kf, VT);

    // ---- stats pass (no probs traffic) ----
    stats_tc<<<dim3(T_SEQ/128, NH), 256, SM_STATS>>>(Qh, Ql, Kf, mask, gStats);

    // ---- recompute + exp + single probs write + fused PV ----
    pvwrite_tc<<<dim3(T_SEQ/128, NH), 256, SM_PVW>>>(
        Qh, Ql, Kf, VT, mask, gStats, probs, Ahh, All, need_out ? 1 : 0);

    // ---- output projection ----
    if (need_out) {
        gemm_tc<<<dim3(DMODEL/128, T_SEQ/128), 256, SM_BN128>>>(
            Ahh, All, DMODEL, WoT, DMODEL, out, DMODEL, DMODEL);
    }
}

// round 17
// speedup vs baseline: 3.3481x; 1.0619x over previous
#include <cuda_runtime.h>
#include <cuda_fp16.h>
#include <math.h>

#define T_SEQ 2048
#define DMODEL 2048
#define NH 32
#define NKV 8
#define HD 64
#define KVW (NKV*HD)       // 512
#define NQKV (DMODEL+2*KVW) // 3072
typedef unsigned short ushort_t;

// ---------------- scratch ----------------
__device__ float g_P[(size_t)NH * T_SEQ * T_SEQ];            // probs (out-only fallback)
__device__ __align__(16) ushort_t g_xh[(size_t)T_SEQ*DMODEL],  g_xl[(size_t)T_SEQ*DMODEL];
__device__ __align__(16) ushort_t g_Wcat[(size_t)NQKV*DMODEL];
__device__ __align__(16) ushort_t g_WoT[(size_t)DMODEL*DMODEL];
__device__ __align__(16) ushort_t g_Qh[(size_t)T_SEQ*DMODEL],  g_Ql[(size_t)T_SEQ*DMODEL];
__device__ __align__(16) ushort_t g_Kf[(size_t)T_SEQ*KVW];
__device__ __align__(16) ushort_t g_VT[(size_t)KVW*T_SEQ];
__device__ __align__(16) ushort_t g_Ah[(size_t)T_SEQ*DMODEL],  g_Al[(size_t)T_SEQ*DMODEL];

// ---------------- helpers ----------------
__device__ __forceinline__ void splitH(float x, ushort_t &h, ushort_t &l) {
    __half hb = __float2half_rn(x);
    __half lb = __float2half_rn(x - __half2float(hb));
    h = *(ushort_t*)&hb;
    l = *(ushort_t*)&lb;
}
__device__ __forceinline__ ushort_t rndH(float x) {
    __half hb = __float2half_rn(x);
    return *(ushort_t*)&hb;
}
__device__ __forceinline__ unsigned packH2(float a, float b) {
    return ((unsigned)rndH(b) << 16) | rndH(a);
}
__device__ __forceinline__ void splitPack(float a, float b, unsigned &hi, unsigned &lo) {
    ushort_t ha,la,hb2,lb2;
    splitH(a, ha, la); splitH(b, hb2, lb2);
    hi = ((unsigned)hb2<<16)|ha;
    lo = ((unsigned)lb2<<16)|la;
}

__device__ __forceinline__ void mma16816(float c[4], const unsigned a[4], const unsigned b[2]) {
    asm volatile(
        "mma.sync.aligned.m16n8k16.row.col.f32.f16.f16.f32 "
        "{%0,%1,%2,%3},{%4,%5,%6,%7},{%8,%9},{%0,%1,%2,%3};\n"
        : "+f"(c[0]), "+f"(c[1]), "+f"(c[2]), "+f"(c[3])
        : "r"(a[0]), "r"(a[1]), "r"(a[2]), "r"(a[3]), "r"(b[0]), "r"(b[1]));
}

__device__ __forceinline__ void cp16(void* dst, const void* src) {
    unsigned d = (unsigned)__cvta_generic_to_shared(dst);
    asm volatile("cp.async.cg.shared.global [%0], [%1], 16;\n" :: "r"(d), "l"(src));
}
__device__ __forceinline__ void cp_commit() { asm volatile("cp.async.commit_group;\n"); }
__device__ __forceinline__ void cp_wait1()  { asm volatile("cp.async.wait_group 1;\n"); }
__device__ __forceinline__ void cp_wait0()  { asm volatile("cp.async.wait_group 0;\n"); }

__device__ __forceinline__ void ldm4(unsigned r[4], const void* p) {
    unsigned a = (unsigned)__cvta_generic_to_shared(p);
    asm volatile("ldmatrix.sync.aligned.m8n8.x4.shared.b16 {%0,%1,%2,%3},[%4];\n"
        : "=r"(r[0]), "=r"(r[1]), "=r"(r[2]), "=r"(r[3]) : "r"(a));
}

// ============================================================================
// 2-term fp16-split GEMM (projections). EPI 0: fp32 C. EPI 4: fused QKV.
// ============================================================================
#define BKK 32
#define PADK 40

template<int BM,int BN,int WM,int WN,int EPI>
__device__ __forceinline__ void mma_core(
    const ushort_t* __restrict__ Ah, const ushort_t* __restrict__ Al, int lda,
    const ushort_t* __restrict__ Bh, int ldb,
    float* __restrict__ C, ushort_t* __restrict__ Ch, ushort_t* __restrict__ Cl, int ldc,
    int K, int m0, int n0,
    ushort_t* __restrict__ Kd, ushort_t* __restrict__ VTd)
{
    extern __shared__ __align__(16) ushort_t smp[];
    ushort_t* Asm = smp;
    ushort_t* Bsm = smp + 4*BM*PADK;

    const int tid  = threadIdx.x;
    const int w    = tid >> 5;
    const int lane = tid & 31;
    constexpr int WROWS = BM / WM;
    const int wm = (w % WROWS) * WM;
    const int wn = (w / WROWS) * WN;
    constexpr int MT = WM / 16;
    constexpr int NT = WN / 8;
    const int g  = lane >> 2;
    const int t4 = lane & 3;
    const int roff = ((lane >> 3) & 1) * 8 + (lane & 7);
    const int coff = (lane >> 4) * 8;

    float acc[MT][NT][4];
    #pragma unroll
    for (int mt=0;mt<MT;mt++)
        #pragma unroll
        for (int nt=0;nt<NT;nt++)
            #pragma unroll
            for (int i=0;i<4;i++) acc[mt][nt][i]=0.f;

    constexpr int ACH = 2*BM*(BKK/8);
    constexpr int BCH = BN*(BKK/8);
    constexpr int TC  = ACH + BCH;

    auto stage = [&](int buf, int k0) {
        #pragma unroll
        for (int i = 0; i < TC/256; i++) {
            int q = tid + i*256;
            if (q < ACH) {
                int p = q / (BM*4);
                int rem = q - p*(BM*4);
                int r = rem >> 2, o = (rem & 3) * 8;
                const ushort_t* src = (p ? Al : Ah) + (size_t)(m0+r)*lda + k0 + o;
                cp16(Asm + ((buf*2+p)*BM + r)*PADK + o, src);
            } else {
                int qq = q - ACH;
                int r = qq >> 2, o = (qq & 3) * 8;
                cp16(Bsm + (buf*BN + r)*PADK + o, Bh + (size_t)(n0+r)*ldb + k0 + o);
            }
        }
    };

    const int KIT = K / BKK;
    stage(0, 0);
    cp_commit();
    int buf = 0;

    for (int it = 0; it < KIT; it++) {
        if (it + 1 < KIT) { stage(buf ^ 1, (it + 1) * BKK); cp_commit(); cp_wait1(); }
        else { cp_wait0(); }
        __syncthreads();

        #pragma unroll
        for (int ks = 0; ks < BKK; ks += 16) {
            unsigned ah[MT][4], al[MT][4], bh[NT][2];
            #pragma unroll
            for (int mt = 0; mt < MT; mt++) {
                int row = wm + mt*16 + roff;
                ldm4(ah[mt], Asm + ((buf*2+0)*BM + row)*PADK + ks + coff);
                ldm4(al[mt], Asm + ((buf*2+1)*BM + row)*PADK + ks + coff);
            }
            #pragma unroll
            for (int p = 0; p < NT/2; p++) {
                unsigned t[4];
                ldm4(t, Bsm + (buf*BN + wn + p*16 + roff)*PADK + ks + coff);
                bh[2*p][0]=t[0]; bh[2*p][1]=t[2]; bh[2*p+1][0]=t[1]; bh[2*p+1][1]=t[3];
            }
            #pragma unroll
            for (int mt = 0; mt < MT; mt++)
                #pragma unroll
                for (int nt = 0; nt < NT; nt++) {
                    mma16816(acc[mt][nt], ah[mt], bh[nt]);
                    mma16816(acc[mt][nt], al[mt], bh[nt]);
                }
        }
        __syncthreads();
        buf ^= 1;
    }

    #pragma unroll
    for (int mt = 0; mt < MT; mt++) {
        #pragma unroll
        for (int nt = 0; nt < NT; nt++) {
            int row = m0 + wm + mt*16 + g;
            int col = n0 + wn + nt*8 + t4*2;
            float a0 = acc[mt][nt][0], a1 = acc[mt][nt][1];
            float a2 = acc[mt][nt][2], a3 = acc[mt][nt][3];
            if (EPI == 0) {
                *(float2*)&C[(size_t)row    *ldc + col] = make_float2(a0, a1);
                *(float2*)&C[(size_t)(row+8)*ldc + col] = make_float2(a2, a3);
            } else {
                if (col < DMODEL) {
                    int j = (col & (HD-1)) >> 1;
                    float theta = powf(10000.0f, -(float)(2*j) / 64.0f);
                    float sn, cs;
                    unsigned hi, lo;
                    sincosf((float)row * theta, &sn, &cs);
                    splitPack(a0*cs - a1*sn, a0*sn + a1*cs, hi, lo);
                    *(unsigned*)&Ch[(size_t)row*DMODEL + col] = hi;
                    *(unsigned*)&Cl[(size_t)row*DMODEL + col] = lo;
                    sincosf((float)(row+8) * theta, &sn, &cs);
                    splitPack(a2*cs - a3*sn, a2*sn + a3*cs, hi, lo);
                    *(unsigned*)&Ch[(size_t)(row+8)*DMODEL + col] = hi;
                    *(unsigned*)&Cl[(size_t)(row+8)*DMODEL + col] = lo;
                } else if (col < DMODEL + KVW) {
                    int c2 = col - DMODEL;
                    int j = (c2 & (HD-1)) >> 1;
                    float theta = powf(10000.0f, -(float)(2*j) / 64.0f);
                    float sn, cs;
                    sincosf((float)row * theta, &sn, &cs);
                    *(unsigned*)&Kd[(size_t)row*KVW + c2] = packH2(a0*cs - a1*sn, a0*sn + a1*cs);
                    sincosf((float)(row+8) * theta, &sn, &cs);
                    *(unsigned*)&Kd[(size_t)(row+8)*KVW + c2] = packH2(a2*cs - a3*sn, a2*sn + a3*cs);
                } else {
                    int c2 = col - (DMODEL + KVW);
                    VTd[(size_t)c2    *T_SEQ + row]   = rndH(a0);
                    VTd[(size_t)(c2+1)*T_SEQ + row]   = rndH(a1);
                    VTd[(size_t)c2    *T_SEQ + row+8] = rndH(a2);
                    VTd[(size_t)(c2+1)*T_SEQ + row+8] = rndH(a3);
                }
            }
        }
    }
}

#define SM_BN128 ((4*128*PADK + 2*128*PADK)*2)   // 61440

__global__ void __launch_bounds__(256,2) qkv_tc(
    const ushort_t* xh, const ushort_t* xl, const ushort_t* Wcat,
    ushort_t* Qh, ushort_t* Ql, ushort_t* Kd, ushort_t* VTd)
{
    mma_core<128,128,32,64,4>(xh, xl, DMODEL, Wcat, DMODEL,
                              nullptr, Qh, Ql, DMODEL, DMODEL,
                              blockIdx.y*128, blockIdx.x*128, Kd, VTd);
}

__global__ void __launch_bounds__(256,2) gemm_tc(
    const ushort_t* Ah, const ushort_t* Al, int lda,
    const ushort_t* Bh, int ldb, float* C, int ldc, int K)
{
    mma_core<128,128,32,64,0>(Ah,Al,lda,Bh,ldb,C,nullptr,nullptr,ldc,K,
                              blockIdx.y*128, blockIdx.x*128, nullptr, nullptr);
}

// ============================================================================
// Fused attention kernel: CTA = (q-tile 128, head).
//   Loop A: S tiles -> l = sum(exp(S)) in registers (no max; masked exp -> 0).
//   Loop B: recompute S -> p = exp(S)/l -> write probs to d_out -> O += P@V.
// ============================================================================
#define FPAD 72
#define SM_ATT ((2*128*FPAD + 2*64*FPAD + 2*64*FPAD)*2)   // 73728

__device__ __forceinline__ void s_tile(
    float sacc[8][4], const ushort_t* Qs, const ushort_t* Ks, int buf,
    const int* __restrict__ mask, int gq, int kt,
    int wq, int roff, int coff, int t4)
{
    #pragma unroll
    for (int nt=0;nt<8;nt++)
        #pragma unroll
        for (int i=0;i<4;i++) sacc[nt][i]=0.f;
    #pragma unroll
    for (int kb = 0; kb < 4; kb++) {
        unsigned qh4[4], ql4[4], bh[8][2];
        ldm4(qh4, Qs + (0*128 + wq + roff)*FPAD + kb*16 + coff);
        ldm4(ql4, Qs + (1*128 + wq + roff)*FPAD + kb*16 + coff);
        #pragma unroll
        for (int p = 0; p < 4; p++) {
            unsigned t[4];
            ldm4(t, Ks + (buf*64 + p*16 + roff)*FPAD + kb*16 + coff);
            bh[2*p][0]=t[0]; bh[2*p][1]=t[2]; bh[2*p+1][0]=t[1]; bh[2*p+1][1]=t[3];
        }
        #pragma unroll
        for (int nt = 0; nt < 8; nt++) {
            mma16816(sacc[nt], qh4, bh[nt]);
            mma16816(sacc[nt], ql4, bh[nt]);
        }
    }
    #pragma unroll
    for (int nt = 0; nt < 8; nt++) {
        int col = kt*64 + nt*8 + t4*2;
        int2 mv0 = *(const int2*)&mask[(size_t)gq    *T_SEQ + col];
        int2 mv1 = *(const int2*)&mask[(size_t)(gq+8)*T_SEQ + col];
        float s0 = sacc[nt][0]*0.125f, s1 = sacc[nt][1]*0.125f;
        float s2 = sacc[nt][2]*0.125f, s3 = sacc[nt][3]*0.125f;
        sacc[nt][0] = mv0.x ? (s0+s0) : (s0-1e9f);
        sacc[nt][1] = mv0.y ? (s1+s1) : (s1-1e9f);
        sacc[nt][2] = mv1.x ? (s2+s2) : (s2-1e9f);
        sacc[nt][3] = mv1.y ? (s3+s3) : (s3-1e9f);
    }
}

__global__ void __launch_bounds__(256,2) attn_tc(
    const ushort_t* __restrict__ Qh, const ushort_t* __restrict__ Ql,
    const ushort_t* __restrict__ Kf, const ushort_t* __restrict__ VT,
    const int* __restrict__ mask,
    float* __restrict__ probs,
    ushort_t* __restrict__ Ahh, ushort_t* __restrict__ All, int do_out)
{
    const int h  = blockIdx.y, kv = h >> 2;
    const int q0 = blockIdx.x * 128;
    extern __shared__ __align__(16) ushort_t fsm[];
    ushort_t* Qs = fsm;
    ushort_t* Ks = fsm + 2*128*FPAD;
    ushort_t* Vs = Ks  + 2*64*FPAD;

    const int tid = threadIdx.x, w = tid >> 5, lane = tid & 31;
    const int g = lane >> 2, t4 = lane & 3;
    const int roff = ((lane >> 3) & 1) * 8 + (lane & 7);
    const int coff = (lane >> 4) * 8;
    const int wq = w * 16;
    const int gq = q0 + wq + g;

    // ---- stage Q (hi/lo) once ----
    #pragma unroll
    for (int i = 0; i < 8; i++) {
        int q = tid + i*256;
        int p = q >> 10, rem = q & 1023;
        int r = rem >> 3, o = (rem & 7) * 8;
        cp16(Qs + (p*128 + r)*FPAD + o, (p ? Ql : Qh) + (size_t)(q0+r)*DMODEL + h*HD + o);
    }
    auto stageK = [&](int buf, int kt) {
        #pragma unroll
        for (int i = 0; i < 2; i++) {
            int q = tid + i*256;
            int r = q >> 3, o = (q & 7) * 8;
            cp16(Ks + (buf*64 + r)*FPAD + o, Kf + (size_t)(kt*64+r)*KVW + kv*HD + o);
        }
    };
    auto stageKV = [&](int buf, int kt) {
        #pragma unroll
        for (int i = 0; i < 4; i++) {
            int q = tid + i*256;
            int p = q >> 9, rem = q & 511;
            int r = rem >> 3, o = (rem & 7) * 8;
            if (p == 0)
                cp16(Ks + (buf*64 + r)*FPAD + o, Kf + (size_t)(kt*64+r)*KVW + kv*HD + o);
            else
                cp16(Vs + (buf*64 + r)*FPAD + o, VT + (size_t)(kv*HD + r)*T_SEQ + kt*64 + o);
        }
    };

    const int NKT = T_SEQ / 64;

    // ================= Loop A: row sums (no max subtraction) =================
    stageK(0, 0);
    cp_commit();
    int buf = 0;
    float lrow0 = 0.f, lrow1 = 0.f;
    for (int kt = 0; kt < NKT; kt++) {
        if (kt + 1 < NKT) { stageK(buf ^ 1, kt + 1); cp_commit(); cp_wait1(); }
        else { cp_wait0(); }
        __syncthreads();

        float sacc[8][4];
        s_tile(sacc, Qs, Ks, buf, mask, gq, kt, wq, roff, coff, t4);

        float rsum0 = 0.f, rsum1 = 0.f;
        #pragma unroll
        for (int nt = 0; nt < 8; nt++) {
            rsum0 += __expf(sacc[nt][0]) + __expf(sacc[nt][1]);
            rsum1 += __expf(sacc[nt][2]) + __expf(sacc[nt][3]);
        }
        lrow0 += rsum0;
        lrow1 += rsum1;
        __syncthreads();
        buf ^= 1;
    }
    #pragma unroll
    for (int o = 1; o <= 2; o <<= 1) {
        lrow0 += __shfl_xor_sync(0xffffffffu, lrow0, o);
        lrow1 += __shfl_xor_sync(0xffffffffu, lrow1, o);
    }
    const float inv0 = 1.0f / lrow0;
    const float inv1 = 1.0f / lrow1;

    // ================= Loop B: probs write + PV =================
    __syncthreads();                 // loop A fully done before restaging buf 0
    stageKV(0, 0);
    cp_commit();
    buf = 0;

    float* pr0 = probs + ((size_t)h*T_SEQ + gq  )*T_SEQ;
    float* pr1 = probs + ((size_t)h*T_SEQ + gq+8)*T_SEQ;

    float oacc[8][4];
    #pragma unroll
    for (int nt=0;nt<8;nt++)
        #pragma unroll
        for (int i=0;i<4;i++) oacc[nt][i]=0.f;

    for (int kt = 0; kt < NKT; kt++) {
        if (kt + 1 < NKT) { stageKV(buf ^ 1, kt + 1); cp_commit(); cp_wait1(); }
        else { cp_wait0(); }
        __syncthreads();

        float sacc[8][4];
        s_tile(sacc, Qs, Ks, buf, mask, gq, kt, wq, roff, coff, t4);

        #pragma unroll
        for (int nt = 0; nt < 8; nt++) {
            int col = kt*64 + nt*8 + t4*2;
            float p0 = __expf(sacc[nt][0]) * inv0;
            float p1 = __expf(sacc[nt][1]) * inv0;
            float p2 = __expf(sacc[nt][2]) * inv1;
            float p3 = __expf(sacc[nt][3]) * inv1;
            sacc[nt][0]=p0; sacc[nt][1]=p1; sacc[nt][2]=p2; sacc[nt][3]=p3;
            *(float2*)&pr0[col] = make_float2(p0, p1);
            *(float2*)&pr1[col] = make_float2(p2, p3);
        }

        if (do_out) {
            #pragma unroll
            for (int kb2 = 0; kb2 < 4; kb2++) {
                unsigned aph[4], apl[4];
                splitPack(sacc[2*kb2  ][0], sacc[2*kb2  ][1], aph[0], apl[0]);
                splitPack(sacc[2*kb2  ][2], sacc[2*kb2  ][3], aph[1], apl[1]);
                splitPack(sacc[2*kb2+1][0], sacc[2*kb2+1][1], aph[2], apl[2]);
                splitPack(sacc[2*kb2+1][2], sacc[2*kb2+1][3], aph[3], apl[3]);
                unsigned bv[8][2];
                #pragma unroll
                for (int p = 0; p < 4; p++) {
                    unsigned t[4];
                    ldm4(t, Vs + (buf*64 + p*16 + roff)*FPAD + kb2*16 + coff);
                    bv[2*p][0]=t[0]; bv[2*p][1]=t[2]; bv[2*p+1][0]=t[1]; bv[2*p+1][1]=t[3];
                }
                #pragma unroll
                for (int nt = 0; nt < 8; nt++) {
                    mma16816(oacc[nt], aph, bv[nt]);
                    mma16816(oacc[nt], apl, bv[nt]);
                }
            }
        }
        __syncthreads();
        buf ^= 1;
    }

    if (do_out) {
        #pragma unroll
        for (int nt = 0; nt < 8; nt++) {
            int col = h*HD + nt*8 + t4*2;
            unsigned hi, lo;
            splitPack(oacc[nt][0], oacc[nt][1], hi, lo);
            *(unsigned*)&Ahh[(size_t)gq*DMODEL + col] = hi;
            *(unsigned*)&All[(size_t)gq*DMODEL + col] = lo;
            splitPack(oacc[nt][2], oacc[nt][3], hi, lo);
            *(unsigned*)&Ahh[(size_t)(gq+8)*DMODEL + col] = hi;
            *(unsigned*)&All[(size_t)(gq+8)*DMODEL + col] = lo;
        }
    }
}

// ---------------- pre-processing ----------------
__global__ void split_x(const float* __restrict__ in, ushort_t* __restrict__ h,
                        ushort_t* __restrict__ l, int n)
{
    int i = blockIdx.x*blockDim.x + threadIdx.x;
    if (i*4 >= n) return;
    float4 v = *(const float4*)&in[i*4];
    unsigned hi0, lo0, hi1, lo1;
    splitPack(v.x, v.y, hi0, lo0);
    splitPack(v.z, v.w, hi1, lo1);
    *(unsigned*)&h[i*4]   = hi0; *(unsigned*)&h[i*4+2] = hi1;
    *(unsigned*)&l[i*4]   = lo0; *(unsigned*)&l[i*4+2] = lo1;
}

__global__ void splitWT(const float* __restrict__ W, int K, int N,
                        ushort_t* __restrict__ T_, int rowOff)
{
    __shared__ float t[32][33];
    int k0 = blockIdx.y*32, n0 = blockIdx.x*32;
    for (int i = threadIdx.y; i < 32; i += 8)
        t[i][threadIdx.x] = W[(size_t)(k0+i)*N + n0 + threadIdx.x];
    __syncthreads();
    for (int i = threadIdx.y; i < 32; i += 8)
        T_[(size_t)(rowOff+n0+i)*DMODEL + k0 + threadIdx.x] = rndH(t[threadIdx.x][i]);
}

// ============================================================================
extern "C" void kernel_launch(void* const* d_in, const int* in_sizes, int n_in,
                              void* d_out, int out_size)
{
    (void)in_sizes; (void)n_in;
    const float* x  = (const float*)d_in[0];
    const float* Wq = (const float*)d_in[1];
    const float* Wk = (const float*)d_in[2];
    const float* Wv = (const float*)d_in[3];
    const float* Wo = (const float*)d_in[4];
    const int* mask = (const int*)d_in[5];
    float* out = (float*)d_out;

    float *gP;
    ushort_t *xh,*xl,*Wcat,*WoT,*Qh,*Ql,*Kf,*VT,*Ahh,*All;
    cudaGetSymbolAddress((void**)&gP,  g_P);
    cudaGetSymbolAddress((void**)&xh,  g_xh);   cudaGetSymbolAddress((void**)&xl,  g_xl);
    cudaGetSymbolAddress((void**)&Wcat,g_Wcat); cudaGetSymbolAddress((void**)&WoT, g_WoT);
    cudaGetSymbolAddress((void**)&Qh,  g_Qh);   cudaGetSymbolAddress((void**)&Ql,  g_Ql);
    cudaGetSymbolAddress((void**)&Kf,  g_Kf);   cudaGetSymbolAddress((void**)&VT,  g_VT);
    cudaGetSymbolAddress((void**)&Ahh, g_Ah);   cudaGetSymbolAddress((void**)&All, g_Al);

    cudaFuncSetAttribute(qkv_tc,  cudaFuncAttributeMaxDynamicSharedMemorySize, SM_BN128);
    cudaFuncSetAttribute(gemm_tc, cudaFuncAttributeMaxDynamicSharedMemorySize, SM_BN128);
    cudaFuncSetAttribute(attn_tc, cudaFuncAttributeMaxDynamicSharedMemorySize, SM_ATT);

    const long long OUT_N = (long long)T_SEQ * DMODEL;
    const long long ATT_N = (long long)NH * T_SEQ * T_SEQ;
    long long osz = (long long)out_size;
    bool need_out = !(osz == ATT_N);
    float* probs = (osz >= OUT_N + ATT_N) ? (out + OUT_N) : (osz == ATT_N ? out : gP);

    // ---- pre-split x; transpose+round weights into concat fp16 ----
    {
        int nx = T_SEQ*DMODEL;
        split_x<<<nx/4/256, 256>>>(x, xh, xl, nx);
        splitWT<<<dim3(DMODEL/32, DMODEL/32), dim3(32,8)>>>(Wq, DMODEL, DMODEL, Wcat, 0);
        splitWT<<<dim3(KVW/32,    DMODEL/32), dim3(32,8)>>>(Wk, DMODEL, KVW, Wcat, DMODEL);
        splitWT<<<dim3(KVW/32,    DMODEL/32), dim3(32,8)>>>(Wv, DMODEL, KVW, Wcat, DMODEL+KVW);
        if (need_out)
            splitWT<<<dim3(DMODEL/32, DMODEL/32), dim3(32,8)>>>(Wo, DMODEL, DMODEL, WoT, 0);
    }

    // ---- fused QKV projection ----
    qkv_tc<<<dim3(NQKV/128, T_SEQ/128), 256, SM_BN128>>>(xh, xl, Wcat, Qh, Ql, Kf, VT);

    // ---- fused attention: sums pass + probs write + PV, one kernel ----
    attn_tc<<<dim3(T_SEQ/128, NH), 256, SM_ATT>>>(
        Qh, Ql, Kf, VT, mask, probs, Ahh, All, need_out ? 1 : 0);

    // ---- output projection ----
    if (need_out) {
        gemm_tc<<<dim3(DMODEL/128, T_SEQ/128), 256, SM_BN128>>>(
            Ahh, All, DMODEL, WoT, DMODEL, out, DMODEL, DMODEL);
    }
}